// round 7
// baseline (speedup 1.0000x reference)
#include <cuda_runtime.h>
#include <cuda_bf16.h>
#include <cstdint>

#define BB 8
#define CC 512
#define C8 64
#define S  128
#define SS (S*S)
#define NPIX (SS)
#define NEG_INF_F (-1000000000.0f)

// ---------------- scratch buffers (device globals; no allocation) ----------------
__device__ float  g_q    [BB * C8 * SS];
__device__ float  g_k    [BB * C8 * SS];
__device__ float  g_qT   [BB * C8 * SS];
__device__ float  g_kT   [BB * C8 * SS];
__device__ float  g_v    [BB * CC * SS];
__device__ float  g_vT   [BB * CC * SS];
__device__ float  g_att  [BB * SS * 2 * S];
__device__ float  g_ocolT[BB * CC * SS];
__device__ float2 g_stat_col[BB * SS];
__device__ float2 g_stat_row[BB * SS];
__device__ float  g_scale_col[BB * SS];
__device__ float  g_scale_row[BB * SS];

// ---------------- mma helpers ---------------------------------------------------
__device__ __forceinline__ uint32_t f2tf32(float f) {
    uint32_t u;
    asm("cvt.rn.tf32.f32 %0, %1;" : "=r"(u) : "f"(f));
    return u;
}
__device__ __forceinline__ uint4 tf32x4(float4 v) {
    return make_uint4(f2tf32(v.x), f2tf32(v.y), f2tf32(v.z), f2tf32(v.w));
}
__device__ __forceinline__ void mma_tf32(float c[4], const uint32_t a[4], const uint32_t b[2]) {
    asm volatile(
        "mma.sync.aligned.m16n8k8.row.col.f32.tf32.tf32.f32 "
        "{%0,%1,%2,%3}, {%4,%5,%6,%7}, {%8,%9}, {%0,%1,%2,%3};"
        : "+f"(c[0]), "+f"(c[1]), "+f"(c[2]), "+f"(c[3])
        : "r"(a[0]), "r"(a[1]), "r"(a[2]), "r"(a[3]), "r"(b[0]), "r"(b[1]));
}
__device__ __forceinline__ void mma_bf16(float c[4], const uint32_t a[4], const uint32_t b[2]) {
    asm volatile(
        "mma.sync.aligned.m16n8k16.row.col.f32.bf16.bf16.f32 "
        "{%0,%1,%2,%3}, {%4,%5,%6,%7}, {%8,%9}, {%0,%1,%2,%3};"
        : "+f"(c[0]), "+f"(c[1]), "+f"(c[2]), "+f"(c[3])
        : "r"(a[0]), "r"(a[1]), "r"(a[2]), "r"(a[3]), "r"(b[0]), "r"(b[1]));
}
__device__ __forceinline__ uint32_t fpack_bf2(float lo, float hi) {
    __nv_bfloat162 h = __floats2bfloat162_rn(lo, hi);
    return *reinterpret_cast<uint32_t*>(&h);
}
__device__ __forceinline__ uint2 f4_bf(float4 v) {
    return make_uint2(fpack_bf2(v.x, v.y), fpack_bf2(v.z, v.w));
}
__device__ __forceinline__ uint32_t smem_u32(const void* p) {
    uint32_t a;
    asm("{ .reg .u64 t; cvta.to.shared.u64 t, %1; cvt.u32.u64 %0, t; }" : "=r"(a) : "l"(p));
    return a;
}
__device__ __forceinline__ void ldm_x4(uint32_t r[4], uint32_t a) {
    asm volatile("ldmatrix.sync.aligned.m8n8.x4.shared.b16 {%0,%1,%2,%3}, [%4];"
        : "=r"(r[0]), "=r"(r[1]), "=r"(r[2]), "=r"(r[3]) : "r"(a));
}
__device__ __forceinline__ void ldm_x4t(uint32_t r[4], uint32_t a) {
    asm volatile("ldmatrix.sync.aligned.m8n8.x4.trans.shared.b16 {%0,%1,%2,%3}, [%4];"
        : "=r"(r[0]), "=r"(r[1]), "=r"(r[2]), "=r"(r[3]) : "r"(a));
}

// tf32 SMEM geometry (words)
#define PA   36
#define PB   136
#define QK_A_W   (128 * PA)
#define QK_B_W   (32 * PB)
#define QK_BUF_W (QK_A_W + QK_B_W)
#define QK_SMEM  (2 * QK_BUF_W * 4)
#define LG_Q_W    (64 * PB)
#define LOGITS_SMEM (2 * LG_Q_W * 4)
// bf16 SMEM geometry (words; rows = 32k bf16 + 8 pad = 20 words = 5x16B, conflict-free ldmatrix)
#define VB_A_W   (128 * 20)           // 2560
#define VB_B_W   (32 * 68)            // 2176 ([k][128n+8pad] bf16; 68w = 17x16B)
#define VB_BUF_W (VB_A_W + VB_B_W)    // 4736
#define AVB_V_W   (256 * 20)          // 5120
#define AVB_T_W   (128 * 20)          // 2560
#define AVB_BUF_W (AVB_V_W + AVB_T_W) // 7680
#define AVB_SMEM  (2 * AVB_BUF_W * 4) // 61440

// ---------------- K1a: q/k projection (tf32, M=128) -----------------------------
__global__ void __launch_bounds__(256, 2)
qk_gemm_mma(const float* __restrict__ x,
            const float* __restrict__ Wq, const float* __restrict__ bq,
            const float* __restrict__ Wk, const float* __restrict__ bk) {
    extern __shared__ uint32_t sm[];

    const int tid  = threadIdx.x;
    const int lane = tid & 31, wid = tid >> 5;
    const int grp  = lane >> 2, tig = lane & 3;
    const int wm   = (wid >> 1) * 32;
    const int wn   = (wid & 1) * 64;
    const int n0   = blockIdx.x * 128;
    const int b    = blockIdx.y;

    const float* xb = x + (size_t)b * CC * NPIX;

    float acc[2][8][4] = {};
    float4 pa[4], pb[4];

    auto ldg_tile = [&](int k0) {
        #pragma unroll
        for (int l = 0; l < 4; l++) {
            int idx = l * 256 + tid;
            int m = idx >> 3, kq = idx & 7;
            const float* src = (m < 64) ? Wq + (size_t)m * CC : Wk + (size_t)(m - 64) * CC;
            pa[l] = *reinterpret_cast<const float4*>(src + k0 + kq * 4);
        }
        #pragma unroll
        for (int l = 0; l < 4; l++) {
            int idx = l * 256 + tid;
            int kk = idx >> 5, nq = idx & 31;
            pb[l] = *reinterpret_cast<const float4*>(
                xb + (size_t)(k0 + kk) * NPIX + n0 + nq * 4);
        }
    };
    auto sts_tile = [&](int buf) {
        uint32_t* A = sm + buf * QK_BUF_W;
        uint32_t* B = A + QK_A_W;
        #pragma unroll
        for (int l = 0; l < 4; l++) {
            int idx = l * 256 + tid;
            int m = idx >> 3, kq = idx & 7;
            *reinterpret_cast<uint4*>(A + m * PA + kq * 4) = tf32x4(pa[l]);
        }
        #pragma unroll
        for (int l = 0; l < 4; l++) {
            int idx = l * 256 + tid;
            int kk = idx >> 5, nq = idx & 31;
            *reinterpret_cast<uint4*>(B + kk * PB + nq * 4) = tf32x4(pb[l]);
        }
    };

    ldg_tile(0);
    sts_tile(0);
    __syncthreads();

    for (int i = 0; i < 16; i++) {
        if (i < 15) ldg_tile((i + 1) * 32);
        const uint32_t* A = sm + (i & 1) * QK_BUF_W;
        const uint32_t* B = A + QK_A_W;
        #pragma unroll
        for (int kk = 0; kk < 4; kk++) {
            const int kr = kk * 8 + tig;
            uint32_t a[2][4], bf[8][2];
            #pragma unroll
            for (int ii = 0; ii < 2; ii++) {
                a[ii][0] = A[(wm + ii * 16 + grp    ) * PA + kr];
                a[ii][1] = A[(wm + ii * 16 + grp + 8) * PA + kr];
                a[ii][2] = A[(wm + ii * 16 + grp    ) * PA + kr + 4];
                a[ii][3] = A[(wm + ii * 16 + grp + 8) * PA + kr + 4];
            }
            #pragma unroll
            for (int j = 0; j < 8; j++) {
                bf[j][0] = B[kr * PB       + wn + j * 8 + grp];
                bf[j][1] = B[(kr + 4) * PB + wn + j * 8 + grp];
            }
            #pragma unroll
            for (int ii = 0; ii < 2; ii++)
                #pragma unroll
                for (int j = 0; j < 8; j++)
                    mma_tf32(acc[ii][j], a[ii], bf[j]);
        }
        if (i < 15) { sts_tile((i + 1) & 1); __syncthreads(); }
    }

    #pragma unroll
    for (int i = 0; i < 2; i++) {
        #pragma unroll
        for (int r = 0; r < 2; r++) {
            int m = wm + i * 16 + grp + r * 8;
            float bias; float* dst;
            if (m < 64) { bias = bq[m];      dst = g_q + ((size_t)b * C8 + m) * SS; }
            else        { bias = bk[m - 64]; dst = g_k + ((size_t)b * C8 + m - 64) * SS; }
            float* row = dst + n0 + wn + tig * 2;
            #pragma unroll
            for (int j = 0; j < 8; j++) {
                float2 o;
                o.x = acc[i][j][r * 2 + 0] + bias;
                o.y = acc[i][j][r * 2 + 1] + bias;
                *reinterpret_cast<float2*>(row + j * 8) = o;
            }
        }
    }
}

// ---------------- K1b: v projection (bf16 m16n8k16 + ldmatrix) ------------------
__global__ void __launch_bounds__(256)
v_gemm_bf16(const float* __restrict__ x,
            const float* __restrict__ Wv, const float* __restrict__ bv) {
    __shared__ uint32_t sm[2 * VB_BUF_W];
    const uint32_t sb = smem_u32(sm);

    const int tid  = threadIdx.x;
    const int lane = tid & 31, wid = tid >> 5;
    const int grp  = lane >> 2, tig = lane & 3;
    const int wm   = (wid >> 1) * 32;
    const int wn   = (wid & 1) * 64;
    const int m0   = blockIdx.x * 128;     // v channel tile (0..384)
    const int n0   = blockIdx.y * 128;
    const int b    = blockIdx.z;

    const float* xb = x + (size_t)b * CC * NPIX;

    float acc[2][8][4] = {};
    float4 pa[4], pb[4];

    auto ldg_tile = [&](int k0) {
        #pragma unroll
        for (int l = 0; l < 4; l++) {
            int idx = l * 256 + tid;
            int m = idx >> 3, kq = idx & 7;
            pa[l] = *reinterpret_cast<const float4*>(Wv + (size_t)(m0 + m) * CC + k0 + kq * 4);
        }
        #pragma unroll
        for (int l = 0; l < 4; l++) {
            int idx = l * 256 + tid;
            int kk = idx >> 5, nq = idx & 31;
            pb[l] = *reinterpret_cast<const float4*>(
                xb + (size_t)(k0 + kk) * NPIX + n0 + nq * 4);
        }
    };
    auto sts_tile = [&](int buf) {
        uint32_t* A = sm + buf * VB_BUF_W;   // [m][32k bf16 + pad] (20 words/row)
        uint32_t* B = A + VB_A_W;            // [k][128n bf16 + pad] (68 words/row)
        #pragma unroll
        for (int l = 0; l < 4; l++) {
            int idx = l * 256 + tid;
            int m = idx >> 3, kq = idx & 7;
            *reinterpret_cast<uint2*>(A + m * 20 + kq * 2) = f4_bf(pa[l]);
        }
        #pragma unroll
        for (int l = 0; l < 4; l++) {
            int idx = l * 256 + tid;
            int kk = idx >> 5, nq = idx & 31;
            *reinterpret_cast<uint2*>(B + kk * 68 + nq * 2) = f4_bf(pb[l]);
        }
    };

    ldg_tile(0);
    sts_tile(0);
    __syncthreads();

    for (int i = 0; i < 16; i++) {
        if (i < 15) ldg_tile((i + 1) * 32);
        const uint32_t Abase = sb + ((i & 1) * VB_BUF_W) * 4;
        const uint32_t Bbase = Abase + VB_A_W * 4;
        #pragma unroll
        for (int s = 0; s < 2; s++) {           // k-steps of 16
            uint32_t a[2][4], bb[4][4];
            #pragma unroll
            for (int ii = 0; ii < 2; ii++) {
                uint32_t ad = Abase + 4 * ((wm + ii * 16 + (lane & 15)) * 20
                              + s * 8 + (lane >> 4) * 4);
                ldm_x4(a[ii], ad);
            }
            #pragma unroll
            for (int g = 0; g < 4; g++) {
                uint32_t bd = Bbase + 4 * ((s * 16 + (lane & 7) + ((lane >> 3) & 1) * 8) * 68
                              + ((wn + g * 16) >> 1) + (lane >> 4) * 4);
                ldm_x4t(bb[g], bd);
            }
            #pragma unroll
            for (int ii = 0; ii < 2; ii++)
                #pragma unroll
                for (int j = 0; j < 8; j++)
                    mma_bf16(acc[ii][j], a[ii], &bb[j >> 1][(j & 1) * 2]);
        }
        if (i < 15) { sts_tile((i + 1) & 1); __syncthreads(); }
    }

    #pragma unroll
    for (int i = 0; i < 2; i++) {
        #pragma unroll
        for (int r = 0; r < 2; r++) {
            int m = m0 + wm + i * 16 + grp + r * 8;
            float bias = bv[m];
            float* row = g_v + ((size_t)b * CC + m) * SS + n0 + wn + tig * 2;
            #pragma unroll
            for (int j = 0; j < 8; j++) {
                float2 o;
                o.x = acc[i][j][r * 2 + 0] + bias;
                o.y = acc[i][j][r * 2 + 1] + bias;
                *reinterpret_cast<float2*>(row + j * 8) = o;
            }
        }
    }
}

// ---------------- K2: plane transpose (w<->h), 128x128 planes ------------------
__global__ void transpose_wh(float* __restrict__ dst, const float* __restrict__ src) {
    __shared__ float t[32][33];
    const size_t base = (size_t)blockIdx.z * SS;
    const int x0 = blockIdx.x * 32, y0 = blockIdx.y * 32;
    const int tx = threadIdx.x, ty = threadIdx.y;
    #pragma unroll
    for (int i = 0; i < 32; i += 8)
        t[ty + i][tx] = src[base + (size_t)(y0 + ty + i) * S + x0 + tx];
    __syncthreads();
    #pragma unroll
    for (int i = 0; i < 32; i += 8)
        dst[base + (size_t)(x0 + ty + i) * S + y0 + tx] = t[tx][ty + i];
}

// ---------------- K3: logits + unnormalized exp + per-row (m,s) stats ----------
__global__ void __launch_bounds__(256, 2)
attn_logits_mma(const float* __restrict__ qsrc, const float* __restrict__ ksrc,
                float* __restrict__ att, float2* __restrict__ stat, int is_col) {
    extern __shared__ uint32_t sm[];
    uint32_t* Qs = sm;
    uint32_t* Ks = sm + LG_Q_W;
    __shared__ float redm[128][2];
    __shared__ float reds[128][2];

    const int p = blockIdx.x;
    const int b = blockIdx.y;
    const int tid  = threadIdx.x;
    const int lane = tid & 31, wid = tid >> 5;
    const int grp  = lane >> 2, tig = lane & 3;
    const int wm   = (wid >> 1) * 32;
    const int wc   = wid & 1;
    const int wn   = wc * 64;

    const size_t qbase = (size_t)b * C8 * SS + (size_t)p * S;

    #pragma unroll
    for (int l = 0; l < 8; l++) {
        int idx = l * 256 + tid;
        int cc  = idx >> 5;
        int nq  = idx & 31;
        size_t g = qbase + (size_t)cc * SS + nq * 4;
        *reinterpret_cast<uint4*>(Qs + cc * PB + nq * 4) =
            tf32x4(*reinterpret_cast<const float4*>(qsrc + g));
        *reinterpret_cast<uint4*>(Ks + cc * PB + nq * 4) =
            tf32x4(*reinterpret_cast<const float4*>(ksrc + g));
    }
    __syncthreads();

    float acc[2][8][4] = {};
    #pragma unroll
    for (int kk = 0; kk < 8; kk++) {
        const int kr = kk * 8 + tig;
        uint32_t a[2][4], bf[8][2];
        #pragma unroll
        for (int i = 0; i < 2; i++) {
            a[i][0] = Qs[kr * PB       + wm + i * 16 + grp];
            a[i][1] = Qs[kr * PB       + wm + i * 16 + grp + 8];
            a[i][2] = Qs[(kr + 4) * PB + wm + i * 16 + grp];
            a[i][3] = Qs[(kr + 4) * PB + wm + i * 16 + grp + 8];
        }
        #pragma unroll
        for (int j = 0; j < 8; j++) {
            bf[j][0] = Ks[kr * PB       + wn + j * 8 + grp];
            bf[j][1] = Ks[(kr + 4) * PB + wn + j * 8 + grp];
        }
        #pragma unroll
        for (int i = 0; i < 2; i++)
            #pragma unroll
            for (int j = 0; j < 8; j++)
                mma_tf32(acc[i][j], a[i], bf[j]);
    }

    if (is_col) {
        #pragma unroll
        for (int i = 0; i < 2; i++)
            #pragma unroll
            for (int r = 0; r < 2; r++) {
                int rr = wm + i * 16 + grp + r * 8;
                #pragma unroll
                for (int j = 0; j < 8; j++) {
                    int u = wn + j * 8 + tig * 2;
                    if (rr == u)     acc[i][j][r * 2 + 0] = NEG_INF_F;
                    if (rr == u + 1) acc[i][j][r * 2 + 1] = NEG_INF_F;
                }
            }
    }

    float mloc[2][2];
    #pragma unroll
    for (int i = 0; i < 2; i++)
        #pragma unroll
        for (int r = 0; r < 2; r++) {
            float ml = -3.4e38f;
            #pragma unroll
            for (int j = 0; j < 8; j++) {
                ml = fmaxf(ml, acc[i][j][r * 2 + 0]);
                ml = fmaxf(ml, acc[i][j][r * 2 + 1]);
            }
            ml = fmaxf(ml, __shfl_xor_sync(0xffffffff, ml, 1));
            ml = fmaxf(ml, __shfl_xor_sync(0xffffffff, ml, 2));
            mloc[i][r] = ml;
        }
    if (tig == 0) {
        #pragma unroll
        for (int i = 0; i < 2; i++)
            #pragma unroll
            for (int r = 0; r < 2; r++)
                redm[wm + i * 16 + grp + r * 8][wc] = mloc[i][r];
    }
    __syncthreads();

    float mrow[2][2], sloc[2][2];
    #pragma unroll
    for (int i = 0; i < 2; i++)
        #pragma unroll
        for (int r = 0; r < 2; r++) {
            int rr = wm + i * 16 + grp + r * 8;
            float m = fmaxf(redm[rr][0], redm[rr][1]);
            mrow[i][r] = m;
            float sl = 0.f;
            #pragma unroll
            for (int j = 0; j < 8; j++) {
                float e0 = __expf(acc[i][j][r * 2 + 0] - m);
                float e1 = __expf(acc[i][j][r * 2 + 1] - m);
                acc[i][j][r * 2 + 0] = e0;
                acc[i][j][r * 2 + 1] = e1;
                sl += e0 + e1;
            }
            sl += __shfl_xor_sync(0xffffffff, sl, 1);
            sl += __shfl_xor_sync(0xffffffff, sl, 2);
            sloc[i][r] = sl;
        }
    if (tig == 0) {
        #pragma unroll
        for (int i = 0; i < 2; i++)
            #pragma unroll
            for (int r = 0; r < 2; r++)
                reds[wm + i * 16 + grp + r * 8][wc] = sloc[i][r];
    }
    __syncthreads();

    if (tig == 0 && wc == 0) {
        #pragma unroll
        for (int i = 0; i < 2; i++)
            #pragma unroll
            for (int r = 0; r < 2; r++) {
                int rr = wm + i * 16 + grp + r * 8;
                stat[(size_t)b * SS + (size_t)p * S + rr] =
                    make_float2(mrow[i][r], reds[rr][0] + reds[rr][1]);
            }
    }

    const size_t obase  = (size_t)b * SS * 256 +
                          (is_col ? (size_t)p * 256 : (size_t)p * S * 256 + 128);
    const size_t rstride = is_col ? (size_t)S * 256 : 256;
    #pragma unroll
    for (int i = 0; i < 2; i++) {
        #pragma unroll
        for (int r = 0; r < 2; r++) {
            int rr = wm + i * 16 + grp + r * 8;
            float* row = att + obase + (size_t)rr * rstride + wn + tig * 2;
            #pragma unroll
            for (int j = 0; j < 8; j++) {
                float2 o;
                o.x = acc[i][j][r * 2 + 0];
                o.y = acc[i][j][r * 2 + 1];
                *reinterpret_cast<float2*>(row + j * 8) = o;
            }
        }
    }
}

// ---------------- K4: combine halves -> per-pixel normalization scales ---------
__global__ void softmax_combine(const float2* __restrict__ sc, const float2* __restrict__ sr,
                                float* __restrict__ scol, float* __restrict__ srow) {
    const int b = blockIdx.y;
    const int t = blockIdx.x * 256 + threadIdx.x;
    const int w = t & (S - 1), h = t >> 7;
    float2 c = sc[(size_t)b * SS + t];
    float2 r = sr[(size_t)b * SS + w * S + h];
    float m  = fmaxf(c.x, r.x);
    float ec = __expf(c.x - m), er = __expf(r.x - m);
    float inv = 1.f / (c.y * ec + r.y * er);
    scol[(size_t)b * SS + t]         = ec * inv;
    srow[(size_t)b * SS + w * S + h] = er * inv;
}

// ---------------- K5: attention @ V (bf16, M=256, ldmatrix) ---------------------
__global__ void __launch_bounds__(512, 1)
attn_av_bf16(const float* __restrict__ vsrc, const float* __restrict__ att,
             float* __restrict__ dst, const float* __restrict__ gammap,
             const float* __restrict__ xres, const float* __restrict__ scale,
             int is_col) {
    extern __shared__ uint32_t sm[];
    const uint32_t sb = smem_u32(sm);

    const int ct = blockIdx.x;
    const int p  = blockIdx.y;
    const int b  = blockIdx.z;
    const int tid  = threadIdx.x;
    const int lane = tid & 31, wid = tid >> 5;
    const int grp  = lane >> 2, tig = lane & 3;
    const int wm   = (wid >> 1) * 32;
    const int wn   = (wid & 1) * 64;

    const size_t vbase = (size_t)(b * CC + ct * 256) * SS + (size_t)p * S;
    const size_t abase = (size_t)b * SS * 256 +
                         (is_col ? (size_t)p * 256 : (size_t)p * S * 256 + 128);
    const size_t aq = is_col ? (size_t)S * 256 : 256;

    const float gm = gammap[0];

    float acc[2][8][4] = {};
    float4 pv[4], pt[2];

    auto ldg_tile = [&](int u0) {
        #pragma unroll
        for (int l = 0; l < 4; l++) {
            int idx = l * 512 + tid;
            int cp = idx >> 3, uq = idx & 7;
            pv[l] = *reinterpret_cast<const float4*>(
                vsrc + vbase + (size_t)cp * SS + u0 + uq * 4);
        }
        #pragma unroll
        for (int l = 0; l < 2; l++) {
            int idx = l * 512 + tid;
            int qp = idx >> 3, uq = idx & 7;
            pt[l] = *reinterpret_cast<const float4*>(
                att + abase + (size_t)qp * aq + u0 + uq * 4);
        }
    };
    auto sts_tile = [&](int buf) {
        uint32_t* V = sm + buf * AVB_BUF_W;   // [c][32u bf16+pad], 20 w/row
        uint32_t* T = V + AVB_V_W;            // [q][32u bf16+pad], 20 w/row
        #pragma unroll
        for (int l = 0; l < 4; l++) {
            int idx = l * 512 + tid;
            int cp = idx >> 3, uq = idx & 7;
            *reinterpret_cast<uint2*>(V + cp * 20 + uq * 2) = f4_bf(pv[l]);
        }
        #pragma unroll
        for (int l = 0; l < 2; l++) {
            int idx = l * 512 + tid;
            int qp = idx >> 3, uq = idx & 7;
            *reinterpret_cast<uint2*>(T + qp * 20 + uq * 2) = f4_bf(pt[l]);
        }
    };

    ldg_tile(0);
    sts_tile(0);
    __syncthreads();

    for (int i = 0; i < 4; i++) {
        if (i < 3) ldg_tile((i + 1) * 32);
        const uint32_t Vbase = sb + ((i & 1) * AVB_BUF_W) * 4;
        const uint32_t Tbase = Vbase + AVB_V_W * 4;
        #pragma unroll
        for (int s = 0; s < 2; s++) {
            uint32_t a[2][4], bb[4][4];
            #pragma unroll
            for (int ii = 0; ii < 2; ii++) {
                uint32_t ad = Vbase + 4 * ((wm + ii * 16 + (lane & 15)) * 20
                              + s * 8 + (lane >> 4) * 4);
                ldm_x4(a[ii], ad);
            }
            #pragma unroll
            for (int g = 0; g < 4; g++) {
                // non-trans x4 on [n][k] layout -> b-frags for n-blocks 2g, 2g+1
                uint32_t bd = Tbase + 4 * ((wn + g * 16 + ((lane >> 4) & 1) * 8 + (lane & 7)) * 20
                              + s * 8 + ((lane >> 3) & 1) * 4);
                ldm_x4(bb[g], bd);
            }
            #pragma unroll
            for (int ii = 0; ii < 2; ii++)
                #pragma unroll
                for (int j = 0; j < 8; j++)
                    mma_bf16(acc[ii][j], a[ii], &bb[j >> 1][(j & 1) * 2]);
        }
        if (i < 3) { sts_tile((i + 1) & 1); __syncthreads(); }
    }

    const float* scl = scale + (size_t)b * SS + (size_t)p * S;
    float2 scv[8];
    #pragma unroll
    for (int j = 0; j < 8; j++)
        scv[j] = *reinterpret_cast<const float2*>(scl + wn + j * 8 + tig * 2);

    #pragma unroll
    for (int i = 0; i < 2; i++) {
        #pragma unroll
        for (int r = 0; r < 2; r++) {
            int cl = wm + i * 16 + grp + r * 8;
            size_t off = vbase + (size_t)cl * SS + wn + tig * 2;
            float* row = dst + off;
            if (is_col) {
                #pragma unroll
                for (int j = 0; j < 8; j++) {
                    float2 o;
                    o.x = gm * scv[j].x * acc[i][j][r * 2 + 0];
                    o.y = gm * scv[j].y * acc[i][j][r * 2 + 1];
                    *reinterpret_cast<float2*>(row + j * 8) = o;
                }
            } else {
                const float* xrow = xres + off;
                #pragma unroll
                for (int j = 0; j < 8; j++) {
                    float2 xr = *reinterpret_cast<const float2*>(xrow + j * 8);
                    float2 o;
                    o.x = gm * scv[j].x * acc[i][j][r * 2 + 0] + xr.x;
                    o.y = gm * scv[j].y * acc[i][j][r * 2 + 1] + xr.y;
                    *reinterpret_cast<float2*>(row + j * 8) = o;
                }
            }
        }
    }
}

// ---------------- K6: out += transpose(ocolT) ----------------------------------
__global__ void final_combine(const float* __restrict__ ocolT, float* __restrict__ out) {
    __shared__ float t[32][33];
    const size_t base = (size_t)blockIdx.z * SS;
    const int w0 = blockIdx.x * 32, h0 = blockIdx.y * 32;
    const int tx = threadIdx.x, ty = threadIdx.y;
    #pragma unroll
    for (int i = 0; i < 32; i += 8)
        t[ty + i][tx] = ocolT[base + (size_t)(h0 + ty + i) * S + w0 + tx];
    __syncthreads();
    #pragma unroll
    for (int i = 0; i < 32; i += 8) {
        size_t o = base + (size_t)(w0 + ty + i) * S + h0 + tx;
        out[o] = out[o] + t[tx][ty + i];
    }
}

// ---------------- launch ------------------------------------------------------
extern "C" void kernel_launch(void* const* d_in, const int* in_sizes, int n_in,
                              void* d_out, int out_size) {
    const float* x     = (const float*)d_in[0];
    const float* Wq    = (const float*)d_in[1];
    const float* bq    = (const float*)d_in[2];
    const float* Wk    = (const float*)d_in[3];
    const float* bk    = (const float*)d_in[4];
    const float* Wv    = (const float*)d_in[5];
    const float* bv    = (const float*)d_in[6];
    const float* gamma = (const float*)d_in[7];
    float* out = (float*)d_out;

    float *q, *k, *qT, *kT, *v, *vT, *att, *ocolT, *scol, *srow;
    float2 *stc, *str;
    cudaGetSymbolAddress((void**)&q,     g_q);
    cudaGetSymbolAddress((void**)&k,     g_k);
    cudaGetSymbolAddress((void**)&qT,    g_qT);
    cudaGetSymbolAddress((void**)&kT,    g_kT);
    cudaGetSymbolAddress((void**)&v,     g_v);
    cudaGetSymbolAddress((void**)&vT,    g_vT);
    cudaGetSymbolAddress((void**)&att,   g_att);
    cudaGetSymbolAddress((void**)&ocolT, g_ocolT);
    cudaGetSymbolAddress((void**)&stc,   g_stat_col);
    cudaGetSymbolAddress((void**)&str,   g_stat_row);
    cudaGetSymbolAddress((void**)&scol,  g_scale_col);
    cudaGetSymbolAddress((void**)&srow,  g_scale_row);

    static cudaStream_t s1 = nullptr;
    static cudaEvent_t evV = nullptr, evT = nullptr;
    static bool init_done = false;
    if (!init_done) {
        cudaStreamCreateWithFlags(&s1, cudaStreamNonBlocking);
        cudaEventCreateWithFlags(&evV, cudaEventDisableTiming);
        cudaEventCreateWithFlags(&evT, cudaEventDisableTiming);
        cudaFuncSetAttribute(qk_gemm_mma,     cudaFuncAttributeMaxDynamicSharedMemorySize, QK_SMEM);
        cudaFuncSetAttribute(attn_logits_mma, cudaFuncAttributeMaxDynamicSharedMemorySize, LOGITS_SMEM);
        cudaFuncSetAttribute(attn_av_bf16,    cudaFuncAttributeMaxDynamicSharedMemorySize, AVB_SMEM);
        init_done = true;
    }

    // 1. V projection (bf16 tensor cores), then fork vT transpose onto s1
    v_gemm_bf16<<<dim3(4, NPIX / 128, BB), 256>>>(x, Wv, bv);
    cudaEventRecord(evV, 0);
    cudaStreamWaitEvent(s1, evV, 0);
    transpose_wh<<<dim3(4, 4, BB * CC), dim3(32, 8), 0, s1>>>(vT, v);
    cudaEventRecord(evT, s1);

    // 2. q/k projection (tf32) + transposes on main stream
    qk_gemm_mma<<<dim3(NPIX / 128, BB), 256, QK_SMEM>>>(x, Wq, bq, Wk, bk);
    transpose_wh<<<dim3(4, 4, BB * C8), dim3(32, 8)>>>(qT, q);
    transpose_wh<<<dim3(4, 4, BB * C8), dim3(32, 8)>>>(kT, k);

    // 3. logits -> exp + stats
    attn_logits_mma<<<dim3(S, BB), 256, LOGITS_SMEM>>>(qT, kT, att, stc, 1);
    attn_logits_mma<<<dim3(S, BB), 256, LOGITS_SMEM>>>(q,  k,  att, str, 0);

    // 4. normalization scales
    softmax_combine<<<dim3(SS / 256, BB), 256>>>(stc, str, scol, srow);

    // 5. attention @ V: row first (doesn't need vT), then join vT and do col
    attn_av_bf16<<<dim3(2, S, BB), 512, AVB_SMEM>>>(v, att, out, gamma, x, srow, 0);
    cudaStreamWaitEvent(0, evT, 0);
    attn_av_bf16<<<dim3(2, S, BB), 512, AVB_SMEM>>>(vT, att, ocolT, gamma, nullptr, scol, 1);

    // 6. combine: out += ocolT^T
    final_combine<<<dim3(4, 4, BB * CC), dim3(32, 8)>>>(ocolT, out);
}

// round 8
// speedup vs baseline: 1.1955x; 1.1955x over previous
#include <cuda_runtime.h>
#include <cuda_bf16.h>
#include <cstdint>

#define BB 8
#define CC 512
#define C8 64
#define S  128
#define SS (S*S)
#define NPIX (SS)
#define NEG_INF_F (-1000000000.0f)

// ---------------- scratch buffers (device globals; no allocation) ----------------
__device__ float  g_q    [BB * C8 * SS];
__device__ float  g_k    [BB * C8 * SS];
__device__ float  g_qT   [BB * C8 * SS];
__device__ float  g_kT   [BB * C8 * SS];
__device__ float  g_v    [BB * CC * SS];
__device__ float  g_vT   [BB * CC * SS];
__device__ uint32_t g_att[BB * SS * 2 * S / 2];   // bf16x2 words: [b][...][256 u]
__device__ float  g_ocolT[BB * CC * SS];
__device__ float2 g_stat_col[BB * SS];
__device__ float2 g_stat_row[BB * SS];
__device__ float  g_scale_col[BB * SS];
__device__ float  g_scale_row[BB * SS];

// ---------------- mma helpers ---------------------------------------------------
__device__ __forceinline__ uint32_t f2tf32(float f) {
    uint32_t u;
    asm("cvt.rn.tf32.f32 %0, %1;" : "=r"(u) : "f"(f));
    return u;
}
__device__ __forceinline__ uint4 tf32x4(float4 v) {
    return make_uint4(f2tf32(v.x), f2tf32(v.y), f2tf32(v.z), f2tf32(v.w));
}
__device__ __forceinline__ void mma_tf32(float c[4], const uint32_t a[4], const uint32_t b[2]) {
    asm volatile(
        "mma.sync.aligned.m16n8k8.row.col.f32.tf32.tf32.f32 "
        "{%0,%1,%2,%3}, {%4,%5,%6,%7}, {%8,%9}, {%0,%1,%2,%3};"
        : "+f"(c[0]), "+f"(c[1]), "+f"(c[2]), "+f"(c[3])
        : "r"(a[0]), "r"(a[1]), "r"(a[2]), "r"(a[3]), "r"(b[0]), "r"(b[1]));
}
__device__ __forceinline__ void mma_bf16(float c[4], const uint32_t a[4], const uint32_t b[2]) {
    asm volatile(
        "mma.sync.aligned.m16n8k16.row.col.f32.bf16.bf16.f32 "
        "{%0,%1,%2,%3}, {%4,%5,%6,%7}, {%8,%9}, {%0,%1,%2,%3};"
        : "+f"(c[0]), "+f"(c[1]), "+f"(c[2]), "+f"(c[3])
        : "r"(a[0]), "r"(a[1]), "r"(a[2]), "r"(a[3]), "r"(b[0]), "r"(b[1]));
}
__device__ __forceinline__ uint32_t fpack_bf2(float lo, float hi) {
    __nv_bfloat162 h = __floats2bfloat162_rn(lo, hi);
    return *reinterpret_cast<uint32_t*>(&h);
}
__device__ __forceinline__ uint2 f4_bf(float4 v) {
    return make_uint2(fpack_bf2(v.x, v.y), fpack_bf2(v.z, v.w));
}

// SMEM geometry (32-bit words)
#define PA   36      // tf32 [row][32k] rows
#define PB   136     // tf32 [32k][128n] rows
#define QKV_A_W   (128 * PA)
#define QKV_B_W   (32 * PB)
#define QKV_BUF_W (QKV_A_W + QKV_B_W)
#define QKV_SMEM  (2 * QKV_BUF_W * 4)
#define LG_Q_W    (64 * PB)
#define LOGITS_SMEM (2 * LG_Q_W * 4)
// bf16 av tiles: rows of 16 k-pair words + 4 pad = 20 (bank (20*grp+tig)%32 all distinct)
#define RW        20
#define AV_V_W    (256 * RW)          // 5120
#define AV_T_W    (128 * RW)          // 2560
#define AV_BUF_W  (AV_V_W + AV_T_W)   // 7680
#define AV_SMEM   (2 * AV_BUF_W * 4)  // 61440

// ---------------- K1: QKV projection (tf32, unchanged from R6) ------------------
__global__ void __launch_bounds__(256, 2)
qkv_gemm_mma(const float* __restrict__ x,
             const float* __restrict__ Wq, const float* __restrict__ bq,
             const float* __restrict__ Wk, const float* __restrict__ bk,
             const float* __restrict__ Wv, const float* __restrict__ bv) {
    extern __shared__ uint32_t sm[];

    const int tid  = threadIdx.x;
    const int lane = tid & 31, wid = tid >> 5;
    const int grp  = lane >> 2, tig = lane & 3;
    const int wm   = (wid >> 1) * 32;
    const int wn   = (wid & 1) * 64;
    const int m0   = blockIdx.x * 128;
    const int n0   = blockIdx.y * 128;
    const int b    = blockIdx.z;

    const float* xb = x + (size_t)b * CC * NPIX;

    float acc[2][8][4] = {};
    float4 pa[4], pb[4];

    auto ldg_tile = [&](int k0) {
        #pragma unroll
        for (int l = 0; l < 4; l++) {
            int idx = l * 256 + tid;
            int m = idx >> 3, kq = idx & 7;
            int mm = m0 + m;
            const float* src;
            if (mm < 64)        src = Wq + (size_t)mm * CC;
            else if (mm < 128)  src = Wk + (size_t)(mm - 64) * CC;
            else                src = Wv + (size_t)(mm - 128) * CC;
            pa[l] = *reinterpret_cast<const float4*>(src + k0 + kq * 4);
        }
        #pragma unroll
        for (int l = 0; l < 4; l++) {
            int idx = l * 256 + tid;
            int kk = idx >> 5, nq = idx & 31;
            pb[l] = *reinterpret_cast<const float4*>(
                xb + (size_t)(k0 + kk) * NPIX + n0 + nq * 4);
        }
    };
    auto sts_tile = [&](int buf) {
        uint32_t* A = sm + buf * QKV_BUF_W;
        uint32_t* B = A + QKV_A_W;
        #pragma unroll
        for (int l = 0; l < 4; l++) {
            int idx = l * 256 + tid;
            int m = idx >> 3, kq = idx & 7;
            *reinterpret_cast<uint4*>(A + m * PA + kq * 4) = tf32x4(pa[l]);
        }
        #pragma unroll
        for (int l = 0; l < 4; l++) {
            int idx = l * 256 + tid;
            int kk = idx >> 5, nq = idx & 31;
            *reinterpret_cast<uint4*>(B + kk * PB + nq * 4) = tf32x4(pb[l]);
        }
    };

    ldg_tile(0);
    sts_tile(0);
    __syncthreads();

    for (int i = 0; i < 16; i++) {
        if (i < 15) ldg_tile((i + 1) * 32);

        const uint32_t* A = sm + (i & 1) * QKV_BUF_W;
        const uint32_t* B = A + QKV_A_W;
        #pragma unroll
        for (int kk = 0; kk < 4; kk++) {
            const int kr = kk * 8 + tig;
            uint32_t a[2][4], bf[8][2];
            #pragma unroll
            for (int ii = 0; ii < 2; ii++) {
                a[ii][0] = A[(wm + ii * 16 + grp    ) * PA + kr];
                a[ii][1] = A[(wm + ii * 16 + grp + 8) * PA + kr];
                a[ii][2] = A[(wm + ii * 16 + grp    ) * PA + kr + 4];
                a[ii][3] = A[(wm + ii * 16 + grp + 8) * PA + kr + 4];
            }
            #pragma unroll
            for (int j = 0; j < 8; j++) {
                bf[j][0] = B[kr * PB       + wn + j * 8 + grp];
                bf[j][1] = B[(kr + 4) * PB + wn + j * 8 + grp];
            }
            #pragma unroll
            for (int ii = 0; ii < 2; ii++)
                #pragma unroll
                for (int j = 0; j < 8; j++)
                    mma_tf32(acc[ii][j], a[ii], bf[j]);
        }

        if (i < 15) {
            sts_tile((i + 1) & 1);
            __syncthreads();
        }
    }

    #pragma unroll
    for (int i = 0; i < 2; i++) {
        #pragma unroll
        for (int r = 0; r < 2; r++) {
            int m = m0 + wm + i * 16 + grp + r * 8;
            float bias; float* dst;
            if (m < 64)        { bias = bq[m];        dst = g_q + ((size_t)b * C8 + m) * SS; }
            else if (m < 128)  { bias = bk[m - 64];   dst = g_k + ((size_t)b * C8 + m - 64) * SS; }
            else               { bias = bv[m - 128];  dst = g_v + ((size_t)b * CC + m - 128) * SS; }
            float* row = dst + n0 + wn + tig * 2;
            #pragma unroll
            for (int j = 0; j < 8; j++) {
                float2 o;
                o.x = acc[i][j][r * 2 + 0] + bias;
                o.y = acc[i][j][r * 2 + 1] + bias;
                *reinterpret_cast<float2*>(row + j * 8) = o;
            }
        }
    }
}

// ---------------- K2: plane transpose (w<->h), 128x128 planes ------------------
__global__ void transpose_wh(float* __restrict__ dst, const float* __restrict__ src) {
    __shared__ float t[32][33];
    const size_t base = (size_t)blockIdx.z * SS;
    const int x0 = blockIdx.x * 32, y0 = blockIdx.y * 32;
    const int tx = threadIdx.x, ty = threadIdx.y;
    #pragma unroll
    for (int i = 0; i < 32; i += 8)
        t[ty + i][tx] = src[base + (size_t)(y0 + ty + i) * S + x0 + tx];
    __syncthreads();
    #pragma unroll
    for (int i = 0; i < 32; i += 8)
        dst[base + (size_t)(x0 + ty + i) * S + y0 + tx] = t[tx][ty + i];
}

// ---------------- K3: logits + unnormalized exp (bf16 out) + (m,s) stats -------
__global__ void __launch_bounds__(256, 2)
attn_logits_mma(const float* __restrict__ qsrc, const float* __restrict__ ksrc,
                uint32_t* __restrict__ attw, float2* __restrict__ stat, int is_col) {
    extern __shared__ uint32_t sm[];
    uint32_t* Qs = sm;
    uint32_t* Ks = sm + LG_Q_W;
    __shared__ float redm[128][2];
    __shared__ float reds[128][2];

    const int p = blockIdx.x;
    const int b = blockIdx.y;
    const int tid  = threadIdx.x;
    const int lane = tid & 31, wid = tid >> 5;
    const int grp  = lane >> 2, tig = lane & 3;
    const int wm   = (wid >> 1) * 32;
    const int wc   = wid & 1;
    const int wn   = wc * 64;

    const size_t qbase = (size_t)b * C8 * SS + (size_t)p * S;

    #pragma unroll
    for (int l = 0; l < 8; l++) {
        int idx = l * 256 + tid;
        int cc  = idx >> 5;
        int nq  = idx & 31;
        size_t g = qbase + (size_t)cc * SS + nq * 4;
        *reinterpret_cast<uint4*>(Qs + cc * PB + nq * 4) =
            tf32x4(*reinterpret_cast<const float4*>(qsrc + g));
        *reinterpret_cast<uint4*>(Ks + cc * PB + nq * 4) =
            tf32x4(*reinterpret_cast<const float4*>(ksrc + g));
    }
    __syncthreads();

    float acc[2][8][4] = {};
    #pragma unroll
    for (int kk = 0; kk < 8; kk++) {
        const int kr = kk * 8 + tig;
        uint32_t a[2][4], bf[8][2];
        #pragma unroll
        for (int i = 0; i < 2; i++) {
            a[i][0] = Qs[kr * PB       + wm + i * 16 + grp];
            a[i][1] = Qs[kr * PB       + wm + i * 16 + grp + 8];
            a[i][2] = Qs[(kr + 4) * PB + wm + i * 16 + grp];
            a[i][3] = Qs[(kr + 4) * PB + wm + i * 16 + grp + 8];
        }
        #pragma unroll
        for (int j = 0; j < 8; j++) {
            bf[j][0] = Ks[kr * PB       + wn + j * 8 + grp];
            bf[j][1] = Ks[(kr + 4) * PB + wn + j * 8 + grp];
        }
        #pragma unroll
        for (int i = 0; i < 2; i++)
            #pragma unroll
            for (int j = 0; j < 8; j++)
                mma_tf32(acc[i][j], a[i], bf[j]);
    }

    if (is_col) {
        #pragma unroll
        for (int i = 0; i < 2; i++)
            #pragma unroll
            for (int r = 0; r < 2; r++) {
                int rr = wm + i * 16 + grp + r * 8;
                #pragma unroll
                for (int j = 0; j < 8; j++) {
                    int u = wn + j * 8 + tig * 2;
                    if (rr == u)     acc[i][j][r * 2 + 0] = NEG_INF_F;
                    if (rr == u + 1) acc[i][j][r * 2 + 1] = NEG_INF_F;
                }
            }
    }

    float mloc[2][2];
    #pragma unroll
    for (int i = 0; i < 2; i++)
        #pragma unroll
        for (int r = 0; r < 2; r++) {
            float ml = -3.4e38f;
            #pragma unroll
            for (int j = 0; j < 8; j++) {
                ml = fmaxf(ml, acc[i][j][r * 2 + 0]);
                ml = fmaxf(ml, acc[i][j][r * 2 + 1]);
            }
            ml = fmaxf(ml, __shfl_xor_sync(0xffffffff, ml, 1));
            ml = fmaxf(ml, __shfl_xor_sync(0xffffffff, ml, 2));
            mloc[i][r] = ml;
        }
    if (tig == 0) {
        #pragma unroll
        for (int i = 0; i < 2; i++)
            #pragma unroll
            for (int r = 0; r < 2; r++)
                redm[wm + i * 16 + grp + r * 8][wc] = mloc[i][r];
    }
    __syncthreads();

    float mrow[2][2], sloc[2][2];
    #pragma unroll
    for (int i = 0; i < 2; i++)
        #pragma unroll
        for (int r = 0; r < 2; r++) {
            int rr = wm + i * 16 + grp + r * 8;
            float m = fmaxf(redm[rr][0], redm[rr][1]);
            mrow[i][r] = m;
            float sl = 0.f;
            #pragma unroll
            for (int j = 0; j < 8; j++) {
                float e0 = __expf(acc[i][j][r * 2 + 0] - m);
                float e1 = __expf(acc[i][j][r * 2 + 1] - m);
                acc[i][j][r * 2 + 0] = e0;
                acc[i][j][r * 2 + 1] = e1;
                sl += e0 + e1;
            }
            sl += __shfl_xor_sync(0xffffffff, sl, 1);
            sl += __shfl_xor_sync(0xffffffff, sl, 2);
            sloc[i][r] = sl;
        }
    if (tig == 0) {
        #pragma unroll
        for (int i = 0; i < 2; i++)
            #pragma unroll
            for (int r = 0; r < 2; r++)
                reds[wm + i * 16 + grp + r * 8][wc] = sloc[i][r];
    }
    __syncthreads();

    if (tig == 0 && wc == 0) {
        #pragma unroll
        for (int i = 0; i < 2; i++)
            #pragma unroll
            for (int r = 0; r < 2; r++) {
                int rr = wm + i * 16 + grp + r * 8;
                stat[(size_t)b * SS + (size_t)p * S + rr] =
                    make_float2(mrow[i][r], reds[rr][0] + reds[rr][1]);
            }
    }

    // store exp values as packed bf16 (word index = elem/2; all offsets even)
    const size_t obase_w  = ((size_t)b * SS * 256 +
                            (is_col ? (size_t)p * 256 : (size_t)p * S * 256 + 128)) >> 1;
    const size_t rstride_w = (is_col ? (size_t)S * 256 : 256) >> 1;
    #pragma unroll
    for (int i = 0; i < 2; i++) {
        #pragma unroll
        for (int r = 0; r < 2; r++) {
            int rr = wm + i * 16 + grp + r * 8;
            uint32_t* row = attw + obase_w + (size_t)rr * rstride_w + ((wn >> 1) + tig);
            #pragma unroll
            for (int j = 0; j < 8; j++)
                row[j * 4] = fpack_bf2(acc[i][j][r * 2 + 0], acc[i][j][r * 2 + 1]);
        }
    }
}

// ---------------- K4: combine halves -> per-pixel normalization scales ---------
__global__ void softmax_combine(const float2* __restrict__ sc, const float2* __restrict__ sr,
                                float* __restrict__ scol, float* __restrict__ srow) {
    const int b = blockIdx.y;
    const int t = blockIdx.x * 256 + threadIdx.x;
    const int w = t & (S - 1), h = t >> 7;
    float2 c = sc[(size_t)b * SS + t];
    float2 r = sr[(size_t)b * SS + w * S + h];
    float m  = fmaxf(c.x, r.x);
    float ec = __expf(c.x - m), er = __expf(r.x - m);
    float inv = 1.f / (c.y * ec + r.y * er);
    scol[(size_t)b * SS + t]         = ec * inv;
    srow[(size_t)b * SS + w * S + h] = er * inv;
}

// ---------------- K5: attention @ V, bf16 m16n8k16, M=256 ----------------------
__global__ void __launch_bounds__(512, 1)
attn_av_mma(const float* __restrict__ vsrc, const uint32_t* __restrict__ attw,
            float* __restrict__ dst, const float* __restrict__ gammap,
            const float* __restrict__ xres, const float* __restrict__ scale,
            int is_col) {
    extern __shared__ uint32_t sm[];

    const int ct = blockIdx.x;
    const int p  = blockIdx.y;
    const int b  = blockIdx.z;
    const int tid  = threadIdx.x;
    const int lane = tid & 31, wid = tid >> 5;
    const int grp  = lane >> 2, tig = lane & 3;
    const int wm   = (wid >> 1) * 32;
    const int wn   = (wid & 1) * 64;

    const size_t vbase   = (size_t)(b * CC + ct * 256) * SS + (size_t)p * S;
    const size_t abase_w = ((size_t)b * SS * 256 +
                           (is_col ? (size_t)p * 256 : (size_t)p * S * 256 + 128)) >> 1;
    const size_t aq_w    = (is_col ? (size_t)S * 256 : 256) >> 1;

    const float gm = gammap[0];

    float acc[2][8][4] = {};
    float4 pv[4];
    uint4  pt;

    auto ldg_tile = [&](int u0) {
        #pragma unroll
        for (int l = 0; l < 4; l++) {
            int idx = l * 512 + tid;
            int cp = idx >> 3, uq = idx & 7;
            pv[l] = *reinterpret_cast<const float4*>(
                vsrc + vbase + (size_t)cp * SS + u0 + uq * 4);
        }
        {
            int qp = tid >> 2, u4 = tid & 3;     // one uint4 (8 bf16) per thread
            pt = *reinterpret_cast<const uint4*>(
                attw + abase_w + (size_t)qp * aq_w + (u0 >> 1) + u4 * 4);
        }
    };
    auto sts_tile = [&](int buf) {
        uint32_t* V = sm + buf * AV_BUF_W;   // [c][16 k-pair words + 4 pad]
        uint32_t* T = V + AV_V_W;            // [q][16 k-pair words + 4 pad]
        #pragma unroll
        for (int l = 0; l < 4; l++) {
            int idx = l * 512 + tid;
            int cp = idx >> 3, uq = idx & 7;
            *reinterpret_cast<uint2*>(V + cp * RW + uq * 2) = f4_bf(pv[l]);
        }
        {
            int qp = tid >> 2, u4 = tid & 3;
            *reinterpret_cast<uint4*>(T + qp * RW + u4 * 4) = pt;
        }
    };

    ldg_tile(0);
    sts_tile(0);
    __syncthreads();

    for (int i = 0; i < 4; i++) {
        if (i < 3) ldg_tile((i + 1) * 32);

        const uint32_t* V = sm + (i & 1) * AV_BUF_W;
        const uint32_t* T = V + AV_V_W;
        #pragma unroll
        for (int s = 0; s < 2; s++) {            // two k=16 steps per 32-u buffer
            uint32_t a[2][4], bf[8][2];
            #pragma unroll
            for (int ii = 0; ii < 2; ii++) {
                a[ii][0] = V[(wm + ii * 16 + grp    ) * RW + s * 8 + tig];
                a[ii][1] = V[(wm + ii * 16 + grp + 8) * RW + s * 8 + tig];
                a[ii][2] = V[(wm + ii * 16 + grp    ) * RW + s * 8 + tig + 4];
                a[ii][3] = V[(wm + ii * 16 + grp + 8) * RW + s * 8 + tig + 4];
            }
            #pragma unroll
            for (int j = 0; j < 8; j++) {
                bf[j][0] = T[(wn + j * 8 + grp) * RW + s * 8 + tig];
                bf[j][1] = T[(wn + j * 8 + grp) * RW + s * 8 + tig + 4];
            }
            #pragma unroll
            for (int ii = 0; ii < 2; ii++)
                #pragma unroll
                for (int j = 0; j < 8; j++)
                    mma_bf16(acc[ii][j], a[ii], bf[j]);
        }

        if (i < 3) {
            sts_tile((i + 1) & 1);
            __syncthreads();
        }
    }

    const float* scl = scale + (size_t)b * SS + (size_t)p * S;
    float2 scv[8];
    #pragma unroll
    for (int j = 0; j < 8; j++)
        scv[j] = *reinterpret_cast<const float2*>(scl + wn + j * 8 + tig * 2);

    #pragma unroll
    for (int i = 0; i < 2; i++) {
        #pragma unroll
        for (int r = 0; r < 2; r++) {
            int cl = wm + i * 16 + grp + r * 8;
            size_t off = vbase + (size_t)cl * SS + wn + tig * 2;
            float* row = dst + off;
            if (is_col) {
                #pragma unroll
                for (int j = 0; j < 8; j++) {
                    float2 o;
                    o.x = gm * scv[j].x * acc[i][j][r * 2 + 0];
                    o.y = gm * scv[j].y * acc[i][j][r * 2 + 1];
                    *reinterpret_cast<float2*>(row + j * 8) = o;
                }
            } else {
                const float* xrow = xres + off;
                #pragma unroll
                for (int j = 0; j < 8; j++) {
                    float2 xr = *reinterpret_cast<const float2*>(xrow + j * 8);
                    float2 o;
                    o.x = gm * scv[j].x * acc[i][j][r * 2 + 0] + xr.x;
                    o.y = gm * scv[j].y * acc[i][j][r * 2 + 1] + xr.y;
                    *reinterpret_cast<float2*>(row + j * 8) = o;
                }
            }
        }
    }
}

// ---------------- K6: out += transpose(ocolT) ----------------------------------
__global__ void final_combine(const float* __restrict__ ocolT, float* __restrict__ out) {
    __shared__ float t[32][33];
    const size_t base = (size_t)blockIdx.z * SS;
    const int w0 = blockIdx.x * 32, h0 = blockIdx.y * 32;
    const int tx = threadIdx.x, ty = threadIdx.y;
    #pragma unroll
    for (int i = 0; i < 32; i += 8)
        t[ty + i][tx] = ocolT[base + (size_t)(h0 + ty + i) * S + w0 + tx];
    __syncthreads();
    #pragma unroll
    for (int i = 0; i < 32; i += 8) {
        size_t o = base + (size_t)(w0 + ty + i) * S + h0 + tx;
        out[o] = out[o] + t[tx][ty + i];
    }
}

// ---------------- launch ------------------------------------------------------
extern "C" void kernel_launch(void* const* d_in, const int* in_sizes, int n_in,
                              void* d_out, int out_size) {
    const float* x     = (const float*)d_in[0];
    const float* Wq    = (const float*)d_in[1];
    const float* bq    = (const float*)d_in[2];
    const float* Wk    = (const float*)d_in[3];
    const float* bk    = (const float*)d_in[4];
    const float* Wv    = (const float*)d_in[5];
    const float* bv    = (const float*)d_in[6];
    const float* gamma = (const float*)d_in[7];
    float* out = (float*)d_out;

    float *q, *k, *qT, *kT, *v, *vT, *ocolT, *scol, *srow;
    uint32_t *att;
    float2 *stc, *str;
    cudaGetSymbolAddress((void**)&q,     g_q);
    cudaGetSymbolAddress((void**)&k,     g_k);
    cudaGetSymbolAddress((void**)&qT,    g_qT);
    cudaGetSymbolAddress((void**)&kT,    g_kT);
    cudaGetSymbolAddress((void**)&v,     g_v);
    cudaGetSymbolAddress((void**)&vT,    g_vT);
    cudaGetSymbolAddress((void**)&att,   g_att);
    cudaGetSymbolAddress((void**)&ocolT, g_ocolT);
    cudaGetSymbolAddress((void**)&stc,   g_stat_col);
    cudaGetSymbolAddress((void**)&str,   g_stat_row);
    cudaGetSymbolAddress((void**)&scol,  g_scale_col);
    cudaGetSymbolAddress((void**)&srow,  g_scale_row);

    static bool attr_done = false;
    if (!attr_done) {
        cudaFuncSetAttribute(qkv_gemm_mma,    cudaFuncAttributeMaxDynamicSharedMemorySize, QKV_SMEM);
        cudaFuncSetAttribute(attn_logits_mma, cudaFuncAttributeMaxDynamicSharedMemorySize, LOGITS_SMEM);
        cudaFuncSetAttribute(attn_av_mma,     cudaFuncAttributeMaxDynamicSharedMemorySize, AV_SMEM);
        attr_done = true;
    }

    // 1. QKV projection (tf32)
    qkv_gemm_mma<<<dim3(5, NPIX / 128, BB), 256, QKV_SMEM>>>(x, Wq, bq, Wk, bk, Wv, bv);

    // 2. transposes (w<->h)
    transpose_wh<<<dim3(4, 4, BB * C8), dim3(32, 8)>>>(qT, q);
    transpose_wh<<<dim3(4, 4, BB * C8), dim3(32, 8)>>>(kT, k);
    transpose_wh<<<dim3(4, 4, BB * CC), dim3(32, 8)>>>(vT, v);

    // 3. logits (tf32) -> bf16 exp + stats
    attn_logits_mma<<<dim3(S, BB), 256, LOGITS_SMEM>>>(qT, kT, att, stc, 1);
    attn_logits_mma<<<dim3(S, BB), 256, LOGITS_SMEM>>>(q,  k,  att, str, 0);

    // 4. normalization scales
    softmax_combine<<<dim3(SS / 256, BB), 256>>>(stc, str, scol, srow);

    // 5. attention @ V (bf16 tensor cores, M=256; gamma*scale fused, row adds x)
    attn_av_mma<<<dim3(2, S, BB), 512, AV_SMEM>>>(vT, att, ocolT, gamma, nullptr, scol, 1);
    attn_av_mma<<<dim3(2, S, BB), 512, AV_SMEM>>>(v,  att, out,   gamma, x,       srow, 0);

    // 6. combine: out += ocolT^T
    final_combine<<<dim3(4, 4, BB * CC), dim3(32, 8)>>>(ocolT, out);
}

// round 9
// speedup vs baseline: 1.3811x; 1.1553x over previous
#include <cuda_runtime.h>
#include <cuda_bf16.h>
#include <cstdint>

#define BB 8
#define CC 512
#define C8 64
#define S  128
#define SS (S*S)
#define NPIX (SS)
#define SSW (SS/2)
#define NEG_INF_F (-1000000000.0f)

// ---------------- scratch buffers (device globals; no allocation) ----------------
__device__ float    g_q    [BB * C8 * SS];
__device__ float    g_k    [BB * C8 * SS];
__device__ float    g_qT   [BB * C8 * SS];
__device__ float    g_kT   [BB * C8 * SS];
__device__ uint32_t g_vbf  [BB * CC * SSW];   // v  packed bf16 [c][w][h]
__device__ uint32_t g_vTbf [BB * CC * SSW];   // vT packed bf16 [c][h][w]
__device__ uint32_t g_att  [BB * SS * S];     // bf16x2 words: [...][256 u]
__device__ float    g_ocolT[BB * CC * SS];
__device__ float2   g_stat_col[BB * SS];
__device__ float2   g_stat_row[BB * SS];
__device__ float    g_scale_col[BB * SS];
__device__ float    g_scale_row[BB * SS];

// ---------------- mma helpers ---------------------------------------------------
__device__ __forceinline__ uint32_t f2tf32(float f) {
    uint32_t u;
    asm("cvt.rn.tf32.f32 %0, %1;" : "=r"(u) : "f"(f));
    return u;
}
__device__ __forceinline__ uint4 tf32x4(float4 v) {
    return make_uint4(f2tf32(v.x), f2tf32(v.y), f2tf32(v.z), f2tf32(v.w));
}
__device__ __forceinline__ void mma_tf32(float c[4], const uint32_t a[4], const uint32_t b[2]) {
    asm volatile(
        "mma.sync.aligned.m16n8k8.row.col.f32.tf32.tf32.f32 "
        "{%0,%1,%2,%3}, {%4,%5,%6,%7}, {%8,%9}, {%0,%1,%2,%3};"
        : "+f"(c[0]), "+f"(c[1]), "+f"(c[2]), "+f"(c[3])
        : "r"(a[0]), "r"(a[1]), "r"(a[2]), "r"(a[3]), "r"(b[0]), "r"(b[1]));
}
__device__ __forceinline__ void mma_bf16(float c[4], const uint32_t a[4], const uint32_t b[2]) {
    asm volatile(
        "mma.sync.aligned.m16n8k16.row.col.f32.bf16.bf16.f32 "
        "{%0,%1,%2,%3}, {%4,%5,%6,%7}, {%8,%9}, {%0,%1,%2,%3};"
        : "+f"(c[0]), "+f"(c[1]), "+f"(c[2]), "+f"(c[3])
        : "r"(a[0]), "r"(a[1]), "r"(a[2]), "r"(a[3]), "r"(b[0]), "r"(b[1]));
}
__device__ __forceinline__ uint32_t fpack_bf2(float lo, float hi) {
    __nv_bfloat162 h = __floats2bfloat162_rn(lo, hi);
    return *reinterpret_cast<uint32_t*>(&h);
}
__device__ __forceinline__ uint2 f4_bf(float4 v) {
    return make_uint2(fpack_bf2(v.x, v.y), fpack_bf2(v.z, v.w));
}

// SMEM geometry (32-bit words)
#define PA   36      // tf32 [row][32k] rows
#define PB   136     // tf32 [32k][128n] rows
#define QK_A_W   (128 * PA)
#define QK_B_W   (32 * PB)
#define QK_BUF_W (QK_A_W + QK_B_W)
#define QK_SMEM  (2 * QK_BUF_W * 4)
#define LG_Q_W    (64 * PB)
#define LOGITS_SMEM (2 * LG_Q_W * 4)
// bf16 tiles: rows of 16 k-pair words + 4 pad = 20 (frag bank (20*grp+tig)%32 distinct)
#define RW        20
#define BF_A_W    (256 * RW)          // 5120 (256 m-rows)
#define BF_B_W    (128 * RW)          // 2560 (128 n-rows)
#define BF_BUF_W  (BF_A_W + BF_B_W)   // 7680
#define BF_SMEM   (2 * BF_BUF_W * 4)  // 61440

// ---------------- K1a: q/k projection (tf32, R6-proven pattern) -----------------
__global__ void __launch_bounds__(256, 2)
qk_gemm_mma(const float* __restrict__ x,
            const float* __restrict__ Wq, const float* __restrict__ bq,
            const float* __restrict__ Wk, const float* __restrict__ bk) {
    extern __shared__ uint32_t sm[];

    const int tid  = threadIdx.x;
    const int lane = tid & 31, wid = tid >> 5;
    const int grp  = lane >> 2, tig = lane & 3;
    const int wm   = (wid >> 1) * 32;
    const int wn   = (wid & 1) * 64;
    const int n0   = blockIdx.x * 128;
    const int b    = blockIdx.y;

    const float* xb = x + (size_t)b * CC * NPIX;

    float acc[2][8][4] = {};
    float4 pa[4], pb[4];

    auto ldg_tile = [&](int k0) {
        #pragma unroll
        for (int l = 0; l < 4; l++) {
            int idx = l * 256 + tid;
            int m = idx >> 3, kq = idx & 7;
            const float* src = (m < 64) ? Wq + (size_t)m * CC : Wk + (size_t)(m - 64) * CC;
            pa[l] = *reinterpret_cast<const float4*>(src + k0 + kq * 4);
        }
        #pragma unroll
        for (int l = 0; l < 4; l++) {
            int idx = l * 256 + tid;
            int kk = idx >> 5, nq = idx & 31;
            pb[l] = *reinterpret_cast<const float4*>(
                xb + (size_t)(k0 + kk) * NPIX + n0 + nq * 4);
        }
    };
    auto sts_tile = [&](int buf) {
        uint32_t* A = sm + buf * QK_BUF_W;
        uint32_t* B = A + QK_A_W;
        #pragma unroll
        for (int l = 0; l < 4; l++) {
            int idx = l * 256 + tid;
            int m = idx >> 3, kq = idx & 7;
            *reinterpret_cast<uint4*>(A + m * PA + kq * 4) = tf32x4(pa[l]);
        }
        #pragma unroll
        for (int l = 0; l < 4; l++) {
            int idx = l * 256 + tid;
            int kk = idx >> 5, nq = idx & 31;
            *reinterpret_cast<uint4*>(B + kk * PB + nq * 4) = tf32x4(pb[l]);
        }
    };

    ldg_tile(0);
    sts_tile(0);
    __syncthreads();

    for (int i = 0; i < 16; i++) {
        if (i < 15) ldg_tile((i + 1) * 32);
        const uint32_t* A = sm + (i & 1) * QK_BUF_W;
        const uint32_t* B = A + QK_A_W;
        #pragma unroll
        for (int kk = 0; kk < 4; kk++) {
            const int kr = kk * 8 + tig;
            uint32_t a[2][4], bf[8][2];
            #pragma unroll
            for (int ii = 0; ii < 2; ii++) {
                a[ii][0] = A[(wm + ii * 16 + grp    ) * PA + kr];
                a[ii][1] = A[(wm + ii * 16 + grp + 8) * PA + kr];
                a[ii][2] = A[(wm + ii * 16 + grp    ) * PA + kr + 4];
                a[ii][3] = A[(wm + ii * 16 + grp + 8) * PA + kr + 4];
            }
            #pragma unroll
            for (int j = 0; j < 8; j++) {
                bf[j][0] = B[kr * PB       + wn + j * 8 + grp];
                bf[j][1] = B[(kr + 4) * PB + wn + j * 8 + grp];
            }
            #pragma unroll
            for (int ii = 0; ii < 2; ii++)
                #pragma unroll
                for (int j = 0; j < 8; j++)
                    mma_tf32(acc[ii][j], a[ii], bf[j]);
        }
        if (i < 15) { sts_tile((i + 1) & 1); __syncthreads(); }
    }

    #pragma unroll
    for (int i = 0; i < 2; i++) {
        #pragma unroll
        for (int r = 0; r < 2; r++) {
            int m = wm + i * 16 + grp + r * 8;
            float bias; float* dst;
            if (m < 64) { bias = bq[m];      dst = g_q + ((size_t)b * C8 + m) * SS; }
            else        { bias = bk[m - 64]; dst = g_k + ((size_t)b * C8 + m - 64) * SS; }
            float* row = dst + n0 + wn + tig * 2;
            #pragma unroll
            for (int j = 0; j < 8; j++) {
                float2 o;
                o.x = acc[i][j][r * 2 + 0] + bias;
                o.y = acc[i][j][r * 2 + 1] + bias;
                *reinterpret_cast<float2*>(row + j * 8) = o;
            }
        }
    }
}

// ---------------- K1b: v projection (bf16, R8-proven fragment pattern) ----------
// O[m=channel 256-tile][n=pixel 128-tile] = Wv[m][k] @ x[k][n], K=512.
// A tile [m][k-pairs] RW=20 (same as av V tile); B tile [n][k-pairs] RW=20,
// built by in-kernel transpose (pack two k-rows per word). Output packed bf16.
__global__ void __launch_bounds__(512, 1)
v_gemm_bf16(const float* __restrict__ x,
            const float* __restrict__ Wv, const float* __restrict__ bv) {
    extern __shared__ uint32_t sm[];

    const int tid  = threadIdx.x;
    const int lane = tid & 31, wid = tid >> 5;
    const int grp  = lane >> 2, tig = lane & 3;
    const int wm   = (wid >> 1) * 32;
    const int wn   = (wid & 1) * 64;
    const int m0   = blockIdx.x * 256;
    const int n0   = blockIdx.y * 128;
    const int b    = blockIdx.z;

    const float* xb = x + (size_t)b * CC * NPIX;

    float acc[2][8][4] = {};
    float4 pa[4], pxlo, pxhi;

    auto ldg_tile = [&](int k0) {
        #pragma unroll
        for (int l = 0; l < 4; l++) {
            int idx = l * 512 + tid;
            int m = idx >> 3, kq = idx & 7;            // m 0..255, kq 0..7
            pa[l] = *reinterpret_cast<const float4*>(
                Wv + (size_t)(m0 + m) * CC + k0 + kq * 4);
        }
        {
            int kp = tid >> 5, g = tid & 31;           // kp 0..15, pixel group 0..31
            const float* p0 = xb + (size_t)(k0 + 2 * kp) * NPIX + n0 + g * 4;
            pxlo = *reinterpret_cast<const float4*>(p0);
            pxhi = *reinterpret_cast<const float4*>(p0 + NPIX);
        }
    };
    auto sts_tile = [&](int buf) {
        uint32_t* A = sm + buf * BF_BUF_W;
        uint32_t* B = A + BF_A_W;
        #pragma unroll
        for (int l = 0; l < 4; l++) {
            int idx = l * 512 + tid;
            int m = idx >> 3, kq = idx & 7;
            *reinterpret_cast<uint2*>(A + m * RW + kq * 2) = f4_bf(pa[l]);
        }
        {
            int kp = tid >> 5, g = tid & 31;
            B[(g * 4 + 0) * RW + kp] = fpack_bf2(pxlo.x, pxhi.x);
            B[(g * 4 + 1) * RW + kp] = fpack_bf2(pxlo.y, pxhi.y);
            B[(g * 4 + 2) * RW + kp] = fpack_bf2(pxlo.z, pxhi.z);
            B[(g * 4 + 3) * RW + kp] = fpack_bf2(pxlo.w, pxhi.w);
        }
    };

    ldg_tile(0);
    sts_tile(0);
    __syncthreads();

    for (int i = 0; i < 16; i++) {
        if (i < 15) ldg_tile((i + 1) * 32);

        const uint32_t* A = sm + (i & 1) * BF_BUF_W;
        const uint32_t* B = A + BF_A_W;
        #pragma unroll
        for (int s = 0; s < 2; s++) {
            uint32_t a[2][4], bf[8][2];
            #pragma unroll
            for (int ii = 0; ii < 2; ii++) {
                a[ii][0] = A[(wm + ii * 16 + grp    ) * RW + s * 8 + tig];
                a[ii][1] = A[(wm + ii * 16 + grp + 8) * RW + s * 8 + tig];
                a[ii][2] = A[(wm + ii * 16 + grp    ) * RW + s * 8 + tig + 4];
                a[ii][3] = A[(wm + ii * 16 + grp + 8) * RW + s * 8 + tig + 4];
            }
            #pragma unroll
            for (int j = 0; j < 8; j++) {
                bf[j][0] = B[(wn + j * 8 + grp) * RW + s * 8 + tig];
                bf[j][1] = B[(wn + j * 8 + grp) * RW + s * 8 + tig + 4];
            }
            #pragma unroll
            for (int ii = 0; ii < 2; ii++)
                #pragma unroll
                for (int j = 0; j < 8; j++)
                    mma_bf16(acc[ii][j], a[ii], bf[j]);
        }

        if (i < 15) { sts_tile((i + 1) & 1); __syncthreads(); }
    }

    // epilogue: pack bf16 pairs into g_vbf
    #pragma unroll
    for (int i = 0; i < 2; i++) {
        #pragma unroll
        for (int r = 0; r < 2; r++) {
            int m = m0 + wm + i * 16 + grp + r * 8;
            float bias = bv[m];
            uint32_t* row = g_vbf + ((size_t)b * CC + m) * SSW
                            + ((n0 + wn + tig * 2) >> 1);
            #pragma unroll
            for (int j = 0; j < 8; j++)
                row[j * 4] = fpack_bf2(acc[i][j][r * 2 + 0] + bias,
                                       acc[i][j][r * 2 + 1] + bias);
        }
    }
}

// ---------------- K2a: fp32 plane transpose (q, k) ------------------------------
__global__ void transpose_wh(float* __restrict__ dst, const float* __restrict__ src) {
    __shared__ float t[32][33];
    const size_t base = (size_t)blockIdx.z * SS;
    const int x0 = blockIdx.x * 32, y0 = blockIdx.y * 32;
    const int tx = threadIdx.x, ty = threadIdx.y;
    #pragma unroll
    for (int i = 0; i < 32; i += 8)
        t[ty + i][tx] = src[base + (size_t)(y0 + ty + i) * S + x0 + tx];
    __syncthreads();
    #pragma unroll
    for (int i = 0; i < 32; i += 8)
        dst[base + (size_t)(x0 + ty + i) * S + y0 + tx] = t[tx][ty + i];
}

// ---------------- K2b: bf16 plane transpose (v) ---------------------------------
// planes of 128x128 bf16 stored as 64 words per row. 64x64-elem tiles.
__global__ void transpose_wh_bf16(uint32_t* __restrict__ dst, const uint32_t* __restrict__ src) {
    __shared__ unsigned short t[64][66];
    const size_t base = (size_t)blockIdx.z * SSW;
    const int w0 = blockIdx.x * 64, h0 = blockIdx.y * 64;
    const int tx = threadIdx.x, ty = threadIdx.y;    // 32 x 8
    #pragma unroll
    for (int i = 0; i < 64; i += 8) {
        int w = w0 + ty + i;
        uint32_t word = src[base + (size_t)w * 64 + (h0 >> 1) + tx];
        t[tx * 2 + 0][ty + i] = (unsigned short)(word & 0xffff);
        t[tx * 2 + 1][ty + i] = (unsigned short)(word >> 16);
    }
    __syncthreads();
    #pragma unroll
    for (int i = 0; i < 64; i += 8) {
        int h = h0 + ty + i;
        uint32_t word = *reinterpret_cast<const uint32_t*>(&t[ty + i][tx * 2]);
        dst[base + (size_t)h * 64 + (w0 >> 1) + tx] = word;
    }
}

// ---------------- K3: logits + unnormalized exp (bf16 out) + (m,s) stats -------
__global__ void __launch_bounds__(256, 2)
attn_logits_mma(const float* __restrict__ qsrc, const float* __restrict__ ksrc,
                uint32_t* __restrict__ attw, float2* __restrict__ stat, int is_col) {
    extern __shared__ uint32_t sm[];
    uint32_t* Qs = sm;
    uint32_t* Ks = sm + LG_Q_W;
    __shared__ float redm[128][2];
    __shared__ float reds[128][2];

    const int p = blockIdx.x;
    const int b = blockIdx.y;
    const int tid  = threadIdx.x;
    const int lane = tid & 31, wid = tid >> 5;
    const int grp  = lane >> 2, tig = lane & 3;
    const int wm   = (wid >> 1) * 32;
    const int wc   = wid & 1;
    const int wn   = wc * 64;

    const size_t qbase = (size_t)b * C8 * SS + (size_t)p * S;

    #pragma unroll
    for (int l = 0; l < 8; l++) {
        int idx = l * 256 + tid;
        int cc  = idx >> 5;
        int nq  = idx & 31;
        size_t g = qbase + (size_t)cc * SS + nq * 4;
        *reinterpret_cast<uint4*>(Qs + cc * PB + nq * 4) =
            tf32x4(*reinterpret_cast<const float4*>(qsrc + g));
        *reinterpret_cast<uint4*>(Ks + cc * PB + nq * 4) =
            tf32x4(*reinterpret_cast<const float4*>(ksrc + g));
    }
    __syncthreads();

    float acc[2][8][4] = {};
    #pragma unroll
    for (int kk = 0; kk < 8; kk++) {
        const int kr = kk * 8 + tig;
        uint32_t a[2][4], bf[8][2];
        #pragma unroll
        for (int i = 0; i < 2; i++) {
            a[i][0] = Qs[kr * PB       + wm + i * 16 + grp];
            a[i][1] = Qs[kr * PB       + wm + i * 16 + grp + 8];
            a[i][2] = Qs[(kr + 4) * PB + wm + i * 16 + grp];
            a[i][3] = Qs[(kr + 4) * PB + wm + i * 16 + grp + 8];
        }
        #pragma unroll
        for (int j = 0; j < 8; j++) {
            bf[j][0] = Ks[kr * PB       + wn + j * 8 + grp];
            bf[j][1] = Ks[(kr + 4) * PB + wn + j * 8 + grp];
        }
        #pragma unroll
        for (int i = 0; i < 2; i++)
            #pragma unroll
            for (int j = 0; j < 8; j++)
                mma_tf32(acc[i][j], a[i], bf[j]);
    }

    if (is_col) {
        #pragma unroll
        for (int i = 0; i < 2; i++)
            #pragma unroll
            for (int r = 0; r < 2; r++) {
                int rr = wm + i * 16 + grp + r * 8;
                #pragma unroll
                for (int j = 0; j < 8; j++) {
                    int u = wn + j * 8 + tig * 2;
                    if (rr == u)     acc[i][j][r * 2 + 0] = NEG_INF_F;
                    if (rr == u + 1) acc[i][j][r * 2 + 1] = NEG_INF_F;
                }
            }
    }

    float mloc[2][2];
    #pragma unroll
    for (int i = 0; i < 2; i++)
        #pragma unroll
        for (int r = 0; r < 2; r++) {
            float ml = -3.4e38f;
            #pragma unroll
            for (int j = 0; j < 8; j++) {
                ml = fmaxf(ml, acc[i][j][r * 2 + 0]);
                ml = fmaxf(ml, acc[i][j][r * 2 + 1]);
            }
            ml = fmaxf(ml, __shfl_xor_sync(0xffffffff, ml, 1));
            ml = fmaxf(ml, __shfl_xor_sync(0xffffffff, ml, 2));
            mloc[i][r] = ml;
        }
    if (tig == 0) {
        #pragma unroll
        for (int i = 0; i < 2; i++)
            #pragma unroll
            for (int r = 0; r < 2; r++)
                redm[wm + i * 16 + grp + r * 8][wc] = mloc[i][r];
    }
    __syncthreads();

    float mrow[2][2], sloc[2][2];
    #pragma unroll
    for (int i = 0; i < 2; i++)
        #pragma unroll
        for (int r = 0; r < 2; r++) {
            int rr = wm + i * 16 + grp + r * 8;
            float m = fmaxf(redm[rr][0], redm[rr][1]);
            mrow[i][r] = m;
            float sl = 0.f;
            #pragma unroll
            for (int j = 0; j < 8; j++) {
                float e0 = __expf(acc[i][j][r * 2 + 0] - m);
                float e1 = __expf(acc[i][j][r * 2 + 1] - m);
                acc[i][j][r * 2 + 0] = e0;
                acc[i][j][r * 2 + 1] = e1;
                sl += e0 + e1;
            }
            sl += __shfl_xor_sync(0xffffffff, sl, 1);
            sl += __shfl_xor_sync(0xffffffff, sl, 2);
            sloc[i][r] = sl;
        }
    if (tig == 0) {
        #pragma unroll
        for (int i = 0; i < 2; i++)
            #pragma unroll
            for (int r = 0; r < 2; r++)
                reds[wm + i * 16 + grp + r * 8][wc] = sloc[i][r];
    }
    __syncthreads();

    if (tig == 0 && wc == 0) {
        #pragma unroll
        for (int i = 0; i < 2; i++)
            #pragma unroll
            for (int r = 0; r < 2; r++) {
                int rr = wm + i * 16 + grp + r * 8;
                stat[(size_t)b * SS + (size_t)p * S + rr] =
                    make_float2(mrow[i][r], reds[rr][0] + reds[rr][1]);
            }
    }

    const size_t obase_w  = ((size_t)b * SS * 256 +
                            (is_col ? (size_t)p * 256 : (size_t)p * S * 256 + 128)) >> 1;
    const size_t rstride_w = (is_col ? (size_t)S * 256 : 256) >> 1;
    #pragma unroll
    for (int i = 0; i < 2; i++) {
        #pragma unroll
        for (int r = 0; r < 2; r++) {
            int rr = wm + i * 16 + grp + r * 8;
            uint32_t* row = attw + obase_w + (size_t)rr * rstride_w + ((wn >> 1) + tig);
            #pragma unroll
            for (int j = 0; j < 8; j++)
                row[j * 4] = fpack_bf2(acc[i][j][r * 2 + 0], acc[i][j][r * 2 + 1]);
        }
    }
}

// ---------------- K4: combine halves -> per-pixel normalization scales ---------
__global__ void softmax_combine(const float2* __restrict__ sc, const float2* __restrict__ sr,
                                float* __restrict__ scol, float* __restrict__ srow) {
    const int b = blockIdx.y;
    const int t = blockIdx.x * 256 + threadIdx.x;
    const int w = t & (S - 1), h = t >> 7;
    float2 c = sc[(size_t)b * SS + t];
    float2 r = sr[(size_t)b * SS + w * S + h];
    float m  = fmaxf(c.x, r.x);
    float ec = __expf(c.x - m), er = __expf(r.x - m);
    float inv = 1.f / (c.y * ec + r.y * er);
    scol[(size_t)b * SS + t]         = ec * inv;
    srow[(size_t)b * SS + w * S + h] = er * inv;
}

// ---------------- K5: attention @ V, bf16 m16n8k16, M=256 ----------------------
__global__ void __launch_bounds__(512, 1)
attn_av_mma(const uint32_t* __restrict__ vsrc, const uint32_t* __restrict__ attw,
            float* __restrict__ dst, const float* __restrict__ gammap,
            const float* __restrict__ xres, const float* __restrict__ scale,
            int is_col) {
    extern __shared__ uint32_t sm[];

    const int ct = blockIdx.x;
    const int p  = blockIdx.y;
    const int b  = blockIdx.z;
    const int tid  = threadIdx.x;
    const int lane = tid & 31, wid = tid >> 5;
    const int grp  = lane >> 2, tig = lane & 3;
    const int wm   = (wid >> 1) * 32;
    const int wn   = (wid & 1) * 64;

    const size_t vbase_f = (size_t)(b * CC + ct * 256) * SS + (size_t)p * S;  // fp32 elem base for output
    const size_t vbase_w = vbase_f >> 1;                                      // bf16 word base for v
    const size_t abase_w = ((size_t)b * SS * 256 +
                           (is_col ? (size_t)p * 256 : (size_t)p * S * 256 + 128)) >> 1;
    const size_t aq_w    = (is_col ? (size_t)S * 256 : 256) >> 1;

    const float gm = gammap[0];

    float acc[2][8][4] = {};
    uint4 pvw[2], pt;

    auto ldg_tile = [&](int u0) {
        #pragma unroll
        for (int l = 0; l < 2; l++) {
            int idx = l * 512 + tid;
            int cp = idx >> 2, u4 = idx & 3;           // cp 0..255, u4 0..3
            pvw[l] = *reinterpret_cast<const uint4*>(
                vsrc + vbase_w + (size_t)cp * SSW + (u0 >> 1) + u4 * 4);
        }
        {
            int qp = tid >> 2, u4 = tid & 3;
            pt = *reinterpret_cast<const uint4*>(
                attw + abase_w + (size_t)qp * aq_w + (u0 >> 1) + u4 * 4);
        }
    };
    auto sts_tile = [&](int buf) {
        uint32_t* V = sm + buf * BF_BUF_W;
        uint32_t* T = V + BF_A_W;
        #pragma unroll
        for (int l = 0; l < 2; l++) {
            int idx = l * 512 + tid;
            int cp = idx >> 2, u4 = idx & 3;
            *reinterpret_cast<uint4*>(V + cp * RW + u4 * 4) = pvw[l];
        }
        {
            int qp = tid >> 2, u4 = tid & 3;
            *reinterpret_cast<uint4*>(T + qp * RW + u4 * 4) = pt;
        }
    };

    ldg_tile(0);
    sts_tile(0);
    __syncthreads();

    for (int i = 0; i < 4; i++) {
        if (i < 3) ldg_tile((i + 1) * 32);

        const uint32_t* V = sm + (i & 1) * BF_BUF_W;
        const uint32_t* T = V + BF_A_W;
        #pragma unroll
        for (int s = 0; s < 2; s++) {
            uint32_t a[2][4], bf[8][2];
            #pragma unroll
            for (int ii = 0; ii < 2; ii++) {
                a[ii][0] = V[(wm + ii * 16 + grp    ) * RW + s * 8 + tig];
                a[ii][1] = V[(wm + ii * 16 + grp + 8) * RW + s * 8 + tig];
                a[ii][2] = V[(wm + ii * 16 + grp    ) * RW + s * 8 + tig + 4];
                a[ii][3] = V[(wm + ii * 16 + grp + 8) * RW + s * 8 + tig + 4];
            }
            #pragma unroll
            for (int j = 0; j < 8; j++) {
                bf[j][0] = T[(wn + j * 8 + grp) * RW + s * 8 + tig];
                bf[j][1] = T[(wn + j * 8 + grp) * RW + s * 8 + tig + 4];
            }
            #pragma unroll
            for (int ii = 0; ii < 2; ii++)
                #pragma unroll
                for (int j = 0; j < 8; j++)
                    mma_bf16(acc[ii][j], a[ii], bf[j]);
        }

        if (i < 3) { sts_tile((i + 1) & 1); __syncthreads(); }
    }

    const float* scl = scale + (size_t)b * SS + (size_t)p * S;
    float2 scv[8];
    #pragma unroll
    for (int j = 0; j < 8; j++)
        scv[j] = *reinterpret_cast<const float2*>(scl + wn + j * 8 + tig * 2);

    #pragma unroll
    for (int i = 0; i < 2; i++) {
        #pragma unroll
        for (int r = 0; r < 2; r++) {
            int cl = wm + i * 16 + grp + r * 8;
            size_t off = vbase_f + (size_t)cl * SS + wn + tig * 2;
            float* row = dst + off;
            if (is_col) {
                #pragma unroll
                for (int j = 0; j < 8; j++) {
                    float2 o;
                    o.x = gm * scv[j].x * acc[i][j][r * 2 + 0];
                    o.y = gm * scv[j].y * acc[i][j][r * 2 + 1];
                    *reinterpret_cast<float2*>(row + j * 8) = o;
                }
            } else {
                const float* xrow = xres + off;
                #pragma unroll
                for (int j = 0; j < 8; j++) {
                    float2 xr = *reinterpret_cast<const float2*>(xrow + j * 8);
                    float2 o;
                    o.x = gm * scv[j].x * acc[i][j][r * 2 + 0] + xr.x;
                    o.y = gm * scv[j].y * acc[i][j][r * 2 + 1] + xr.y;
                    *reinterpret_cast<float2*>(row + j * 8) = o;
                }
            }
        }
    }
}

// ---------------- K6: out += transpose(ocolT) ----------------------------------
__global__ void final_combine(const float* __restrict__ ocolT, float* __restrict__ out) {
    __shared__ float t[32][33];
    const size_t base = (size_t)blockIdx.z * SS;
    const int w0 = blockIdx.x * 32, h0 = blockIdx.y * 32;
    const int tx = threadIdx.x, ty = threadIdx.y;
    #pragma unroll
    for (int i = 0; i < 32; i += 8)
        t[ty + i][tx] = ocolT[base + (size_t)(h0 + ty + i) * S + w0 + tx];
    __syncthreads();
    #pragma unroll
    for (int i = 0; i < 32; i += 8) {
        size_t o = base + (size_t)(w0 + ty + i) * S + h0 + tx;
        out[o] = out[o] + t[tx][ty + i];
    }
}

// ---------------- launch ------------------------------------------------------
extern "C" void kernel_launch(void* const* d_in, const int* in_sizes, int n_in,
                              void* d_out, int out_size) {
    const float* x     = (const float*)d_in[0];
    const float* Wq    = (const float*)d_in[1];
    const float* bq    = (const float*)d_in[2];
    const float* Wk    = (const float*)d_in[3];
    const float* bk    = (const float*)d_in[4];
    const float* Wv    = (const float*)d_in[5];
    const float* bv    = (const float*)d_in[6];
    const float* gamma = (const float*)d_in[7];
    float* out = (float*)d_out;

    float *q, *k, *qT, *kT, *ocolT, *scol, *srow;
    uint32_t *vbf, *vTbf, *att;
    float2 *stc, *str;
    cudaGetSymbolAddress((void**)&q,     g_q);
    cudaGetSymbolAddress((void**)&k,     g_k);
    cudaGetSymbolAddress((void**)&qT,    g_qT);
    cudaGetSymbolAddress((void**)&kT,    g_kT);
    cudaGetSymbolAddress((void**)&vbf,   g_vbf);
    cudaGetSymbolAddress((void**)&vTbf,  g_vTbf);
    cudaGetSymbolAddress((void**)&att,   g_att);
    cudaGetSymbolAddress((void**)&ocolT, g_ocolT);
    cudaGetSymbolAddress((void**)&stc,   g_stat_col);
    cudaGetSymbolAddress((void**)&str,   g_stat_row);
    cudaGetSymbolAddress((void**)&scol,  g_scale_col);
    cudaGetSymbolAddress((void**)&srow,  g_scale_row);

    static bool attr_done = false;
    if (!attr_done) {
        cudaFuncSetAttribute(qk_gemm_mma,     cudaFuncAttributeMaxDynamicSharedMemorySize, QK_SMEM);
        cudaFuncSetAttribute(v_gemm_bf16,     cudaFuncAttributeMaxDynamicSharedMemorySize, BF_SMEM);
        cudaFuncSetAttribute(attn_logits_mma, cudaFuncAttributeMaxDynamicSharedMemorySize, LOGITS_SMEM);
        cudaFuncSetAttribute(attn_av_mma,     cudaFuncAttributeMaxDynamicSharedMemorySize, BF_SMEM);
        attr_done = true;
    }

    // 1. projections: v (bf16 m16n8k16), q/k (tf32)
    v_gemm_bf16<<<dim3(CC / 256, NPIX / 128, BB), 512, BF_SMEM>>>(x, Wv, bv);
    qk_gemm_mma<<<dim3(NPIX / 128, BB), 256, QK_SMEM>>>(x, Wq, bq, Wk, bk);

    // 2. transposes (w<->h)
    transpose_wh<<<dim3(4, 4, BB * C8), dim3(32, 8)>>>(qT, q);
    transpose_wh<<<dim3(4, 4, BB * C8), dim3(32, 8)>>>(kT, k);
    transpose_wh_bf16<<<dim3(2, 2, BB * CC), dim3(32, 8)>>>(vTbf, vbf);

    // 3. logits (tf32) -> bf16 exp + stats
    attn_logits_mma<<<dim3(S, BB), 256, LOGITS_SMEM>>>(qT, kT, att, stc, 1);
    attn_logits_mma<<<dim3(S, BB), 256, LOGITS_SMEM>>>(q,  k,  att, str, 0);

    // 4. normalization scales
    softmax_combine<<<dim3(SS / 256, BB), 256>>>(stc, str, scol, srow);

    // 5. attention @ V (bf16 tensor cores, M=256; gamma*scale fused, row adds x)
    attn_av_mma<<<dim3(2, S, BB), 512, BF_SMEM>>>(vTbf, att, ocolT, gamma, nullptr, scol, 1);
    attn_av_mma<<<dim3(2, S, BB), 512, BF_SMEM>>>(vbf,  att, out,   gamma, x,       srow, 0);

    // 6. combine: out += ocolT^T
    final_combine<<<dim3(4, 4, BB * CC), dim3(32, 8)>>>(ocolT, out);
}

// round 10
// speedup vs baseline: 1.4912x; 1.0797x over previous
#include <cuda_runtime.h>
#include <cuda_bf16.h>
#include <cstdint>

#define BB 8
#define CC 512
#define C8 64
#define S  128
#define SS (S*S)
#define NPIX (SS)
#define SSW (SS/2)
#define NEG_INF_F (-1000000000.0f)

// ---------------- scratch buffers (device globals; no allocation) ----------------
__device__ float    g_q    [BB * C8 * SS];
__device__ float    g_k    [BB * C8 * SS];
__device__ float    g_qT   [BB * C8 * SS];
__device__ float    g_kT   [BB * C8 * SS];
__device__ uint32_t g_vbf  [BB * CC * SSW];   // v  packed bf16 [c][w][h]
__device__ uint32_t g_vTbf [BB * CC * SSW];   // vT packed bf16 [c][h][w]
__device__ uint32_t g_att  [BB * SS * S];     // bf16x2 words: [...][256 u]
__device__ uint32_t g_ocolTbf[BB * CC * SSW]; // o_col^T packed bf16 [c][h][w]
__device__ float2   g_stat_col[BB * SS];
__device__ float2   g_stat_row[BB * SS];
__device__ float    g_scale_col[BB * SS];
__device__ float    g_scale_row[BB * SS];

// ---------------- mma helpers ---------------------------------------------------
__device__ __forceinline__ uint32_t f2tf32(float f) {
    uint32_t u;
    asm("cvt.rn.tf32.f32 %0, %1;" : "=r"(u) : "f"(f));
    return u;
}
__device__ __forceinline__ uint4 tf32x4(float4 v) {
    return make_uint4(f2tf32(v.x), f2tf32(v.y), f2tf32(v.z), f2tf32(v.w));
}
__device__ __forceinline__ void mma_tf32(float c[4], const uint32_t a[4], const uint32_t b[2]) {
    asm volatile(
        "mma.sync.aligned.m16n8k8.row.col.f32.tf32.tf32.f32 "
        "{%0,%1,%2,%3}, {%4,%5,%6,%7}, {%8,%9}, {%0,%1,%2,%3};"
        : "+f"(c[0]), "+f"(c[1]), "+f"(c[2]), "+f"(c[3])
        : "r"(a[0]), "r"(a[1]), "r"(a[2]), "r"(a[3]), "r"(b[0]), "r"(b[1]));
}
__device__ __forceinline__ void mma_bf16(float c[4], const uint32_t a[4], const uint32_t b[2]) {
    asm volatile(
        "mma.sync.aligned.m16n8k16.row.col.f32.bf16.bf16.f32 "
        "{%0,%1,%2,%3}, {%4,%5,%6,%7}, {%8,%9}, {%0,%1,%2,%3};"
        : "+f"(c[0]), "+f"(c[1]), "+f"(c[2]), "+f"(c[3])
        : "r"(a[0]), "r"(a[1]), "r"(a[2]), "r"(a[3]), "r"(b[0]), "r"(b[1]));
}
__device__ __forceinline__ uint32_t fpack_bf2(float lo, float hi) {
    __nv_bfloat162 h = __floats2bfloat162_rn(lo, hi);
    return *reinterpret_cast<uint32_t*>(&h);
}
__device__ __forceinline__ uint2 f4_bf(float4 v) {
    return make_uint2(fpack_bf2(v.x, v.y), fpack_bf2(v.z, v.w));
}

// SMEM geometry (32-bit words)
#define PA   36
#define PB   136
#define QK_A_W   (128 * PA)
#define QK_B_W   (32 * PB)
#define QK_BUF_W (QK_A_W + QK_B_W)
#define QK_SMEM  (2 * QK_BUF_W * 4)
#define LG_Q_W    (64 * PB)
#define LOGITS_SMEM (2 * LG_Q_W * 4)
#define RW        20
#define BF_A_W    (256 * RW)
#define BF_B_W    (128 * RW)
#define BF_BUF_W  (BF_A_W + BF_B_W)
#define BF_SMEM   (2 * BF_BUF_W * 4)

// ---------------- K1a: q/k projection (tf32) ------------------------------------
__global__ void __launch_bounds__(256, 2)
qk_gemm_mma(const float* __restrict__ x,
            const float* __restrict__ Wq, const float* __restrict__ bq,
            const float* __restrict__ Wk, const float* __restrict__ bk) {
    extern __shared__ uint32_t sm[];

    const int tid  = threadIdx.x;
    const int lane = tid & 31, wid = tid >> 5;
    const int grp  = lane >> 2, tig = lane & 3;
    const int wm   = (wid >> 1) * 32;
    const int wn   = (wid & 1) * 64;
    const int n0   = blockIdx.x * 128;
    const int b    = blockIdx.y;

    const float* xb = x + (size_t)b * CC * NPIX;

    float acc[2][8][4] = {};
    float4 pa[4], pb[4];

    auto ldg_tile = [&](int k0) {
        #pragma unroll
        for (int l = 0; l < 4; l++) {
            int idx = l * 256 + tid;
            int m = idx >> 3, kq = idx & 7;
            const float* src = (m < 64) ? Wq + (size_t)m * CC : Wk + (size_t)(m - 64) * CC;
            pa[l] = *reinterpret_cast<const float4*>(src + k0 + kq * 4);
        }
        #pragma unroll
        for (int l = 0; l < 4; l++) {
            int idx = l * 256 + tid;
            int kk = idx >> 5, nq = idx & 31;
            pb[l] = *reinterpret_cast<const float4*>(
                xb + (size_t)(k0 + kk) * NPIX + n0 + nq * 4);
        }
    };
    auto sts_tile = [&](int buf) {
        uint32_t* A = sm + buf * QK_BUF_W;
        uint32_t* B = A + QK_A_W;
        #pragma unroll
        for (int l = 0; l < 4; l++) {
            int idx = l * 256 + tid;
            int m = idx >> 3, kq = idx & 7;
            *reinterpret_cast<uint4*>(A + m * PA + kq * 4) = tf32x4(pa[l]);
        }
        #pragma unroll
        for (int l = 0; l < 4; l++) {
            int idx = l * 256 + tid;
            int kk = idx >> 5, nq = idx & 31;
            *reinterpret_cast<uint4*>(B + kk * PB + nq * 4) = tf32x4(pb[l]);
        }
    };

    ldg_tile(0);
    sts_tile(0);
    __syncthreads();

    for (int i = 0; i < 16; i++) {
        if (i < 15) ldg_tile((i + 1) * 32);
        const uint32_t* A = sm + (i & 1) * QK_BUF_W;
        const uint32_t* B = A + QK_A_W;
        #pragma unroll
        for (int kk = 0; kk < 4; kk++) {
            const int kr = kk * 8 + tig;
            uint32_t a[2][4], bf[8][2];
            #pragma unroll
            for (int ii = 0; ii < 2; ii++) {
                a[ii][0] = A[(wm + ii * 16 + grp    ) * PA + kr];
                a[ii][1] = A[(wm + ii * 16 + grp + 8) * PA + kr];
                a[ii][2] = A[(wm + ii * 16 + grp    ) * PA + kr + 4];
                a[ii][3] = A[(wm + ii * 16 + grp + 8) * PA + kr + 4];
            }
            #pragma unroll
            for (int j = 0; j < 8; j++) {
                bf[j][0] = B[kr * PB       + wn + j * 8 + grp];
                bf[j][1] = B[(kr + 4) * PB + wn + j * 8 + grp];
            }
            #pragma unroll
            for (int ii = 0; ii < 2; ii++)
                #pragma unroll
                for (int j = 0; j < 8; j++)
                    mma_tf32(acc[ii][j], a[ii], bf[j]);
        }
        if (i < 15) { sts_tile((i + 1) & 1); __syncthreads(); }
    }

    #pragma unroll
    for (int i = 0; i < 2; i++) {
        #pragma unroll
        for (int r = 0; r < 2; r++) {
            int m = wm + i * 16 + grp + r * 8;
            float bias; float* dst;
            if (m < 64) { bias = bq[m];      dst = g_q + ((size_t)b * C8 + m) * SS; }
            else        { bias = bk[m - 64]; dst = g_k + ((size_t)b * C8 + m - 64) * SS; }
            float* row = dst + n0 + wn + tig * 2;
            #pragma unroll
            for (int j = 0; j < 8; j++) {
                float2 o;
                o.x = acc[i][j][r * 2 + 0] + bias;
                o.y = acc[i][j][r * 2 + 1] + bias;
                *reinterpret_cast<float2*>(row + j * 8) = o;
            }
        }
    }
}

// ---------------- K1b: v projection (bf16) --------------------------------------
__global__ void __launch_bounds__(512, 1)
v_gemm_bf16(const float* __restrict__ x,
            const float* __restrict__ Wv, const float* __restrict__ bv) {
    extern __shared__ uint32_t sm[];

    const int tid  = threadIdx.x;
    const int lane = tid & 31, wid = tid >> 5;
    const int grp  = lane >> 2, tig = lane & 3;
    const int wm   = (wid >> 1) * 32;
    const int wn   = (wid & 1) * 64;
    const int m0   = blockIdx.x * 256;
    const int n0   = blockIdx.y * 128;
    const int b    = blockIdx.z;

    const float* xb = x + (size_t)b * CC * NPIX;

    float acc[2][8][4] = {};
    float4 pa[4], pxlo, pxhi;

    auto ldg_tile = [&](int k0) {
        #pragma unroll
        for (int l = 0; l < 4; l++) {
            int idx = l * 512 + tid;
            int m = idx >> 3, kq = idx & 7;
            pa[l] = *reinterpret_cast<const float4*>(
                Wv + (size_t)(m0 + m) * CC + k0 + kq * 4);
        }
        {
            int kp = tid >> 5, g = tid & 31;
            const float* p0 = xb + (size_t)(k0 + 2 * kp) * NPIX + n0 + g * 4;
            pxlo = *reinterpret_cast<const float4*>(p0);
            pxhi = *reinterpret_cast<const float4*>(p0 + NPIX);
        }
    };
    auto sts_tile = [&](int buf) {
        uint32_t* A = sm + buf * BF_BUF_W;
        uint32_t* B = A + BF_A_W;
        #pragma unroll
        for (int l = 0; l < 4; l++) {
            int idx = l * 512 + tid;
            int m = idx >> 3, kq = idx & 7;
            *reinterpret_cast<uint2*>(A + m * RW + kq * 2) = f4_bf(pa[l]);
        }
        {
            int kp = tid >> 5, g = tid & 31;
            B[(g * 4 + 0) * RW + kp] = fpack_bf2(pxlo.x, pxhi.x);
            B[(g * 4 + 1) * RW + kp] = fpack_bf2(pxlo.y, pxhi.y);
            B[(g * 4 + 2) * RW + kp] = fpack_bf2(pxlo.z, pxhi.z);
            B[(g * 4 + 3) * RW + kp] = fpack_bf2(pxlo.w, pxhi.w);
        }
    };

    ldg_tile(0);
    sts_tile(0);
    __syncthreads();

    for (int i = 0; i < 16; i++) {
        if (i < 15) ldg_tile((i + 1) * 32);

        const uint32_t* A = sm + (i & 1) * BF_BUF_W;
        const uint32_t* B = A + BF_A_W;
        #pragma unroll
        for (int s = 0; s < 2; s++) {
            uint32_t a[2][4], bf[8][2];
            #pragma unroll
            for (int ii = 0; ii < 2; ii++) {
                a[ii][0] = A[(wm + ii * 16 + grp    ) * RW + s * 8 + tig];
                a[ii][1] = A[(wm + ii * 16 + grp + 8) * RW + s * 8 + tig];
                a[ii][2] = A[(wm + ii * 16 + grp    ) * RW + s * 8 + tig + 4];
                a[ii][3] = A[(wm + ii * 16 + grp + 8) * RW + s * 8 + tig + 4];
            }
            #pragma unroll
            for (int j = 0; j < 8; j++) {
                bf[j][0] = B[(wn + j * 8 + grp) * RW + s * 8 + tig];
                bf[j][1] = B[(wn + j * 8 + grp) * RW + s * 8 + tig + 4];
            }
            #pragma unroll
            for (int ii = 0; ii < 2; ii++)
                #pragma unroll
                for (int j = 0; j < 8; j++)
                    mma_bf16(acc[ii][j], a[ii], bf[j]);
        }

        if (i < 15) { sts_tile((i + 1) & 1); __syncthreads(); }
    }

    #pragma unroll
    for (int i = 0; i < 2; i++) {
        #pragma unroll
        for (int r = 0; r < 2; r++) {
            int m = m0 + wm + i * 16 + grp + r * 8;
            float bias = bv[m];
            uint32_t* row = g_vbf + ((size_t)b * CC + m) * SSW
                            + ((n0 + wn + tig * 2) >> 1);
            #pragma unroll
            for (int j = 0; j < 8; j++)
                row[j * 4] = fpack_bf2(acc[i][j][r * 2 + 0] + bias,
                                       acc[i][j][r * 2 + 1] + bias);
        }
    }
}

// ---------------- K2a: fp32 plane transpose (q, k) ------------------------------
__global__ void transpose_wh(float* __restrict__ dst, const float* __restrict__ src) {
    __shared__ float t[32][33];
    const size_t base = (size_t)blockIdx.z * SS;
    const int x0 = blockIdx.x * 32, y0 = blockIdx.y * 32;
    const int tx = threadIdx.x, ty = threadIdx.y;
    #pragma unroll
    for (int i = 0; i < 32; i += 8)
        t[ty + i][tx] = src[base + (size_t)(y0 + ty + i) * S + x0 + tx];
    __syncthreads();
    #pragma unroll
    for (int i = 0; i < 32; i += 8)
        dst[base + (size_t)(x0 + ty + i) * S + y0 + tx] = t[tx][ty + i];
}

// ---------------- K2b: bf16 plane transpose (v) ---------------------------------
__global__ void transpose_wh_bf16(uint32_t* __restrict__ dst, const uint32_t* __restrict__ src) {
    __shared__ unsigned short t[64][66];
    const size_t base = (size_t)blockIdx.z * SSW;
    const int w0 = blockIdx.x * 64, h0 = blockIdx.y * 64;
    const int tx = threadIdx.x, ty = threadIdx.y;
    #pragma unroll
    for (int i = 0; i < 64; i += 8) {
        int w = w0 + ty + i;
        uint32_t word = src[base + (size_t)w * 64 + (h0 >> 1) + tx];
        t[tx * 2 + 0][ty + i] = (unsigned short)(word & 0xffff);
        t[tx * 2 + 1][ty + i] = (unsigned short)(word >> 16);
    }
    __syncthreads();
    #pragma unroll
    for (int i = 0; i < 64; i += 8) {
        int h = h0 + ty + i;
        uint32_t word = *reinterpret_cast<const uint32_t*>(&t[ty + i][tx * 2]);
        dst[base + (size_t)h * 64 + (w0 >> 1) + tx] = word;
    }
}

// ---------------- K3: logits + unnormalized exp (bf16 out) + (m,s) stats -------
__global__ void __launch_bounds__(256, 2)
attn_logits_mma(const float* __restrict__ qsrc, const float* __restrict__ ksrc,
                uint32_t* __restrict__ attw, float2* __restrict__ stat, int is_col) {
    extern __shared__ uint32_t sm[];
    uint32_t* Qs = sm;
    uint32_t* Ks = sm + LG_Q_W;
    __shared__ float redm[128][2];
    __shared__ float reds[128][2];

    const int p = blockIdx.x;
    const int b = blockIdx.y;
    const int tid  = threadIdx.x;
    const int lane = tid & 31, wid = tid >> 5;
    const int grp  = lane >> 2, tig = lane & 3;
    const int wm   = (wid >> 1) * 32;
    const int wc   = wid & 1;
    const int wn   = wc * 64;

    const size_t qbase = (size_t)b * C8 * SS + (size_t)p * S;

    #pragma unroll
    for (int l = 0; l < 8; l++) {
        int idx = l * 256 + tid;
        int cc  = idx >> 5;
        int nq  = idx & 31;
        size_t g = qbase + (size_t)cc * SS + nq * 4;
        *reinterpret_cast<uint4*>(Qs + cc * PB + nq * 4) =
            tf32x4(*reinterpret_cast<const float4*>(qsrc + g));
        *reinterpret_cast<uint4*>(Ks + cc * PB + nq * 4) =
            tf32x4(*reinterpret_cast<const float4*>(ksrc + g));
    }
    __syncthreads();

    float acc[2][8][4] = {};
    #pragma unroll
    for (int kk = 0; kk < 8; kk++) {
        const int kr = kk * 8 + tig;
        uint32_t a[2][4], bf[8][2];
        #pragma unroll
        for (int i = 0; i < 2; i++) {
            a[i][0] = Qs[kr * PB       + wm + i * 16 + grp];
            a[i][1] = Qs[kr * PB       + wm + i * 16 + grp + 8];
            a[i][2] = Qs[(kr + 4) * PB + wm + i * 16 + grp];
            a[i][3] = Qs[(kr + 4) * PB + wm + i * 16 + grp + 8];
        }
        #pragma unroll
        for (int j = 0; j < 8; j++) {
            bf[j][0] = Ks[kr * PB       + wn + j * 8 + grp];
            bf[j][1] = Ks[(kr + 4) * PB + wn + j * 8 + grp];
        }
        #pragma unroll
        for (int i = 0; i < 2; i++)
            #pragma unroll
            for (int j = 0; j < 8; j++)
                mma_tf32(acc[i][j], a[i], bf[j]);
    }

    if (is_col) {
        #pragma unroll
        for (int i = 0; i < 2; i++)
            #pragma unroll
            for (int r = 0; r < 2; r++) {
                int rr = wm + i * 16 + grp + r * 8;
                #pragma unroll
                for (int j = 0; j < 8; j++) {
                    int u = wn + j * 8 + tig * 2;
                    if (rr == u)     acc[i][j][r * 2 + 0] = NEG_INF_F;
                    if (rr == u + 1) acc[i][j][r * 2 + 1] = NEG_INF_F;
                }
            }
    }

    float mloc[2][2];
    #pragma unroll
    for (int i = 0; i < 2; i++)
        #pragma unroll
        for (int r = 0; r < 2; r++) {
            float ml = -3.4e38f;
            #pragma unroll
            for (int j = 0; j < 8; j++) {
                ml = fmaxf(ml, acc[i][j][r * 2 + 0]);
                ml = fmaxf(ml, acc[i][j][r * 2 + 1]);
            }
            ml = fmaxf(ml, __shfl_xor_sync(0xffffffff, ml, 1));
            ml = fmaxf(ml, __shfl_xor_sync(0xffffffff, ml, 2));
            mloc[i][r] = ml;
        }
    if (tig == 0) {
        #pragma unroll
        for (int i = 0; i < 2; i++)
            #pragma unroll
            for (int r = 0; r < 2; r++)
                redm[wm + i * 16 + grp + r * 8][wc] = mloc[i][r];
    }
    __syncthreads();

    float mrow[2][2], sloc[2][2];
    #pragma unroll
    for (int i = 0; i < 2; i++)
        #pragma unroll
        for (int r = 0; r < 2; r++) {
            int rr = wm + i * 16 + grp + r * 8;
            float m = fmaxf(redm[rr][0], redm[rr][1]);
            mrow[i][r] = m;
            float sl = 0.f;
            #pragma unroll
            for (int j = 0; j < 8; j++) {
                float e0 = __expf(acc[i][j][r * 2 + 0] - m);
                float e1 = __expf(acc[i][j][r * 2 + 1] - m);
                acc[i][j][r * 2 + 0] = e0;
                acc[i][j][r * 2 + 1] = e1;
                sl += e0 + e1;
            }
            sl += __shfl_xor_sync(0xffffffff, sl, 1);
            sl += __shfl_xor_sync(0xffffffff, sl, 2);
            sloc[i][r] = sl;
        }
    if (tig == 0) {
        #pragma unroll
        for (int i = 0; i < 2; i++)
            #pragma unroll
            for (int r = 0; r < 2; r++)
                reds[wm + i * 16 + grp + r * 8][wc] = sloc[i][r];
    }
    __syncthreads();

    if (tig == 0 && wc == 0) {
        #pragma unroll
        for (int i = 0; i < 2; i++)
            #pragma unroll
            for (int r = 0; r < 2; r++) {
                int rr = wm + i * 16 + grp + r * 8;
                stat[(size_t)b * SS + (size_t)p * S + rr] =
                    make_float2(mrow[i][r], reds[rr][0] + reds[rr][1]);
            }
    }

    const size_t obase_w  = ((size_t)b * SS * 256 +
                            (is_col ? (size_t)p * 256 : (size_t)p * S * 256 + 128)) >> 1;
    const size_t rstride_w = (is_col ? (size_t)S * 256 : 256) >> 1;
    #pragma unroll
    for (int i = 0; i < 2; i++) {
        #pragma unroll
        for (int r = 0; r < 2; r++) {
            int rr = wm + i * 16 + grp + r * 8;
            uint32_t* row = attw + obase_w + (size_t)rr * rstride_w + ((wn >> 1) + tig);
            #pragma unroll
            for (int j = 0; j < 8; j++)
                row[j * 4] = fpack_bf2(acc[i][j][r * 2 + 0], acc[i][j][r * 2 + 1]);
        }
    }
}

// ---------------- K4: combine halves -> per-pixel normalization scales ---------
__global__ void softmax_combine(const float2* __restrict__ sc, const float2* __restrict__ sr,
                                float* __restrict__ scol, float* __restrict__ srow) {
    const int b = blockIdx.y;
    const int t = blockIdx.x * 256 + threadIdx.x;
    const int w = t & (S - 1), h = t >> 7;
    float2 c = sc[(size_t)b * SS + t];
    float2 r = sr[(size_t)b * SS + w * S + h];
    float m  = fmaxf(c.x, r.x);
    float ec = __expf(c.x - m), er = __expf(r.x - m);
    float inv = 1.f / (c.y * ec + r.y * er);
    scol[(size_t)b * SS + t]         = ec * inv;
    srow[(size_t)b * SS + w * S + h] = er * inv;
}

// ---------------- K5: attention @ V, bf16 m16n8k16, M=256 ----------------------
// is_col=1: dst -> packed bf16 ocolT; is_col=0: dst -> fp32 out (+x residual)
__global__ void __launch_bounds__(512, 1)
attn_av_mma(const uint32_t* __restrict__ vsrc, const uint32_t* __restrict__ attw,
            float* __restrict__ dstf, uint32_t* __restrict__ dstw,
            const float* __restrict__ gammap,
            const float* __restrict__ xres, const float* __restrict__ scale,
            int is_col) {
    extern __shared__ uint32_t sm[];

    const int ct = blockIdx.x;
    const int p  = blockIdx.y;
    const int b  = blockIdx.z;
    const int tid  = threadIdx.x;
    const int lane = tid & 31, wid = tid >> 5;
    const int grp  = lane >> 2, tig = lane & 3;
    const int wm   = (wid >> 1) * 32;
    const int wn   = (wid & 1) * 64;

    const size_t vbase_f = (size_t)(b * CC + ct * 256) * SS + (size_t)p * S;
    const size_t vbase_w = vbase_f >> 1;
    const size_t abase_w = ((size_t)b * SS * 256 +
                           (is_col ? (size_t)p * 256 : (size_t)p * S * 256 + 128)) >> 1;
    const size_t aq_w    = (is_col ? (size_t)S * 256 : 256) >> 1;

    const float gm = gammap[0];

    float acc[2][8][4] = {};
    uint4 pvw[2], pt;

    auto ldg_tile = [&](int u0) {
        #pragma unroll
        for (int l = 0; l < 2; l++) {
            int idx = l * 512 + tid;
            int cp = idx >> 2, u4 = idx & 3;
            pvw[l] = *reinterpret_cast<const uint4*>(
                vsrc + vbase_w + (size_t)cp * SSW + (u0 >> 1) + u4 * 4);
        }
        {
            int qp = tid >> 2, u4 = tid & 3;
            pt = *reinterpret_cast<const uint4*>(
                attw + abase_w + (size_t)qp * aq_w + (u0 >> 1) + u4 * 4);
        }
    };
    auto sts_tile = [&](int buf) {
        uint32_t* V = sm + buf * BF_BUF_W;
        uint32_t* T = V + BF_A_W;
        #pragma unroll
        for (int l = 0; l < 2; l++) {
            int idx = l * 512 + tid;
            int cp = idx >> 2, u4 = idx & 3;
            *reinterpret_cast<uint4*>(V + cp * RW + u4 * 4) = pvw[l];
        }
        {
            int qp = tid >> 2, u4 = tid & 3;
            *reinterpret_cast<uint4*>(T + qp * RW + u4 * 4) = pt;
        }
    };

    ldg_tile(0);
    sts_tile(0);
    __syncthreads();

    for (int i = 0; i < 4; i++) {
        if (i < 3) ldg_tile((i + 1) * 32);

        const uint32_t* V = sm + (i & 1) * BF_BUF_W;
        const uint32_t* T = V + BF_A_W;
        #pragma unroll
        for (int s = 0; s < 2; s++) {
            uint32_t a[2][4], bf[8][2];
            #pragma unroll
            for (int ii = 0; ii < 2; ii++) {
                a[ii][0] = V[(wm + ii * 16 + grp    ) * RW + s * 8 + tig];
                a[ii][1] = V[(wm + ii * 16 + grp + 8) * RW + s * 8 + tig];
                a[ii][2] = V[(wm + ii * 16 + grp    ) * RW + s * 8 + tig + 4];
                a[ii][3] = V[(wm + ii * 16 + grp + 8) * RW + s * 8 + tig + 4];
            }
            #pragma unroll
            for (int j = 0; j < 8; j++) {
                bf[j][0] = T[(wn + j * 8 + grp) * RW + s * 8 + tig];
                bf[j][1] = T[(wn + j * 8 + grp) * RW + s * 8 + tig + 4];
            }
            #pragma unroll
            for (int ii = 0; ii < 2; ii++)
                #pragma unroll
                for (int j = 0; j < 8; j++)
                    mma_bf16(acc[ii][j], a[ii], bf[j]);
        }

        if (i < 3) { sts_tile((i + 1) & 1); __syncthreads(); }
    }

    const float* scl = scale + (size_t)b * SS + (size_t)p * S;
    float2 scv[8];
    #pragma unroll
    for (int j = 0; j < 8; j++)
        scv[j] = *reinterpret_cast<const float2*>(scl + wn + j * 8 + tig * 2);

    #pragma unroll
    for (int i = 0; i < 2; i++) {
        #pragma unroll
        for (int r = 0; r < 2; r++) {
            int cl = wm + i * 16 + grp + r * 8;
            size_t off = vbase_f + (size_t)cl * SS + wn + tig * 2;
            if (is_col) {
                uint32_t* roww = dstw + (off >> 1);
                #pragma unroll
                for (int j = 0; j < 8; j++)
                    roww[j * 4] = fpack_bf2(gm * scv[j].x * acc[i][j][r * 2 + 0],
                                            gm * scv[j].y * acc[i][j][r * 2 + 1]);
            } else {
                float* row = dstf + off;
                const float* xrow = xres + off;
                #pragma unroll
                for (int j = 0; j < 8; j++) {
                    float2 xr = *reinterpret_cast<const float2*>(xrow + j * 8);
                    float2 o;
                    o.x = gm * scv[j].x * acc[i][j][r * 2 + 0] + xr.x;
                    o.y = gm * scv[j].y * acc[i][j][r * 2 + 1] + xr.y;
                    *reinterpret_cast<float2*>(row + j * 8) = o;
                }
            }
        }
    }
}

// ---------------- K6: out += transpose(ocolT bf16) -----------------------------
__global__ void final_combine(const uint32_t* __restrict__ ocolT, float* __restrict__ out) {
    __shared__ unsigned short t[64][66];
    const size_t base_w = (size_t)blockIdx.z * SSW;
    const size_t base_f = (size_t)blockIdx.z * SS;
    const int w0 = blockIdx.x * 64, h0 = blockIdx.y * 64;
    const int tx = threadIdx.x, ty = threadIdx.y;     // 32 x 8

    // load ocolT plane [h][w] (w packed in pairs) -> t[w_local][h_local]
    #pragma unroll
    for (int i = 0; i < 64; i += 8) {
        int h = h0 + ty + i;
        uint32_t word = ocolT[base_w + (size_t)h * 64 + (w0 >> 1) + tx];
        t[tx * 2 + 0][ty + i] = (unsigned short)(word & 0xffff);
        t[tx * 2 + 1][ty + i] = (unsigned short)(word >> 16);
    }
    __syncthreads();
    // write: out[w][h] += o_col[w][h], float2 over h pairs
    #pragma unroll
    for (int i = 0; i < 64; i += 8) {
        int w = w0 + ty + i;
        uint32_t word = *reinterpret_cast<const uint32_t*>(&t[ty + i][tx * 2]);
        __nv_bfloat162 bf = *reinterpret_cast<__nv_bfloat162*>(&word);
        float* o = out + base_f + (size_t)w * S + h0 + tx * 2;
        float2 cur = *reinterpret_cast<float2*>(o);
        cur.x += __bfloat162float(bf.x);
        cur.y += __bfloat162float(bf.y);
        *reinterpret_cast<float2*>(o) = cur;
    }
}

// ---------------- launch ------------------------------------------------------
extern "C" void kernel_launch(void* const* d_in, const int* in_sizes, int n_in,
                              void* d_out, int out_size) {
    const float* x     = (const float*)d_in[0];
    const float* Wq    = (const float*)d_in[1];
    const float* bq    = (const float*)d_in[2];
    const float* Wk    = (const float*)d_in[3];
    const float* bk    = (const float*)d_in[4];
    const float* Wv    = (const float*)d_in[5];
    const float* bv    = (const float*)d_in[6];
    const float* gamma = (const float*)d_in[7];
    float* out = (float*)d_out;

    float *q, *k, *qT, *kT, *scol, *srow;
    uint32_t *vbf, *vTbf, *att, *ocolT;
    float2 *stc, *str;
    cudaGetSymbolAddress((void**)&q,     g_q);
    cudaGetSymbolAddress((void**)&k,     g_k);
    cudaGetSymbolAddress((void**)&qT,    g_qT);
    cudaGetSymbolAddress((void**)&kT,    g_kT);
    cudaGetSymbolAddress((void**)&vbf,   g_vbf);
    cudaGetSymbolAddress((void**)&vTbf,  g_vTbf);
    cudaGetSymbolAddress((void**)&att,   g_att);
    cudaGetSymbolAddress((void**)&ocolT, g_ocolTbf);
    cudaGetSymbolAddress((void**)&stc,   g_stat_col);
    cudaGetSymbolAddress((void**)&str,   g_stat_row);
    cudaGetSymbolAddress((void**)&scol,  g_scale_col);
    cudaGetSymbolAddress((void**)&srow,  g_scale_row);

    static cudaStream_t s1 = nullptr;
    static cudaEvent_t evFork = nullptr, evV = nullptr, evT = nullptr;
    static bool init_done = false;
    if (!init_done) {
        cudaStreamCreateWithFlags(&s1, cudaStreamNonBlocking);
        cudaEventCreateWithFlags(&evFork, cudaEventDisableTiming);
        cudaEventCreateWithFlags(&evV,    cudaEventDisableTiming);
        cudaEventCreateWithFlags(&evT,    cudaEventDisableTiming);
        cudaFuncSetAttribute(qk_gemm_mma,     cudaFuncAttributeMaxDynamicSharedMemorySize, QK_SMEM);
        cudaFuncSetAttribute(v_gemm_bf16,     cudaFuncAttributeMaxDynamicSharedMemorySize, BF_SMEM);
        cudaFuncSetAttribute(attn_logits_mma, cudaFuncAttributeMaxDynamicSharedMemorySize, LOGITS_SMEM);
        cudaFuncSetAttribute(attn_av_mma,     cudaFuncAttributeMaxDynamicSharedMemorySize, BF_SMEM);
        init_done = true;
    }

    // fork: v chain on s1 (v_gemm -> vT transpose), qk chain on stream 0
    cudaEventRecord(evFork, 0);
    cudaStreamWaitEvent(s1, evFork, 0);
    v_gemm_bf16<<<dim3(CC / 256, NPIX / 128, BB), 512, BF_SMEM, s1>>>(x, Wv, bv);
    cudaEventRecord(evV, s1);
    transpose_wh_bf16<<<dim3(2, 2, BB * CC), dim3(32, 8), 0, s1>>>(vTbf, vbf);
    cudaEventRecord(evT, s1);

    qk_gemm_mma<<<dim3(NPIX / 128, BB), 256, QK_SMEM>>>(x, Wq, bq, Wk, bk);
    transpose_wh<<<dim3(4, 4, BB * C8), dim3(32, 8)>>>(qT, q);
    transpose_wh<<<dim3(4, 4, BB * C8), dim3(32, 8)>>>(kT, k);
    attn_logits_mma<<<dim3(S, BB), 256, LOGITS_SMEM>>>(qT, kT, att, stc, 1);
    attn_logits_mma<<<dim3(S, BB), 256, LOGITS_SMEM>>>(q,  k,  att, str, 0);
    softmax_combine<<<dim3(SS / 256, BB), 256>>>(stc, str, scol, srow);

    // join: av-row needs vbf (evV); av-col needs vTbf (evT)
    cudaStreamWaitEvent(0, evV, 0);
    attn_av_mma<<<dim3(2, S, BB), 512, BF_SMEM>>>(vbf,  att, out, nullptr, gamma, x, srow, 0);
    cudaStreamWaitEvent(0, evT, 0);
    attn_av_mma<<<dim3(2, S, BB), 512, BF_SMEM>>>(vTbf, att, nullptr, ocolT, gamma, nullptr, scol, 1);

    // out += ocolT^T
    final_combine<<<dim3(2, 2, BB * CC), dim3(32, 8)>>>(ocolT, out);
}

// round 11
// speedup vs baseline: 1.5423x; 1.0343x over previous
#include <cuda_runtime.h>
#include <cuda_bf16.h>
#include <cstdint>

#define BB 8
#define CC 512
#define C8 64
#define S  128
#define SS (S*S)
#define NPIX (SS)
#define SSW (SS/2)
#define NEG_INF_F (-1000000000.0f)

// ---------------- scratch buffers (device globals; no allocation) ----------------
__device__ float    g_q    [BB * C8 * SS];
__device__ float    g_k    [BB * C8 * SS];
__device__ float    g_qT   [BB * C8 * SS];
__device__ float    g_kT   [BB * C8 * SS];
__device__ uint32_t g_wvbf [CC * CC / 2];     // Wv packed bf16 [m][k-pair]
__device__ uint32_t g_vbf  [BB * CC * SSW];   // v  packed bf16 [c][w][h]
__device__ uint32_t g_vTbf [BB * CC * SSW];   // vT packed bf16 [c][h][w]
__device__ uint32_t g_att  [BB * SS * S];     // bf16x2 words: [...][256 u]
__device__ uint32_t g_ocolTbf[BB * CC * SSW]; // o_col^T packed bf16 [c][h][w]
__device__ float2   g_stat_col[BB * SS];
__device__ float2   g_stat_row[BB * SS];
__device__ float    g_scale_col[BB * SS];
__device__ float    g_scale_row[BB * SS];

// ---------------- mma helpers ---------------------------------------------------
__device__ __forceinline__ uint32_t f2tf32(float f) {
    uint32_t u;
    asm("cvt.rn.tf32.f32 %0, %1;" : "=r"(u) : "f"(f));
    return u;
}
__device__ __forceinline__ uint4 tf32x4(float4 v) {
    return make_uint4(f2tf32(v.x), f2tf32(v.y), f2tf32(v.z), f2tf32(v.w));
}
__device__ __forceinline__ void mma_tf32(float c[4], const uint32_t a[4], const uint32_t b[2]) {
    asm volatile(
        "mma.sync.aligned.m16n8k8.row.col.f32.tf32.tf32.f32 "
        "{%0,%1,%2,%3}, {%4,%5,%6,%7}, {%8,%9}, {%0,%1,%2,%3};"
        : "+f"(c[0]), "+f"(c[1]), "+f"(c[2]), "+f"(c[3])
        : "r"(a[0]), "r"(a[1]), "r"(a[2]), "r"(a[3]), "r"(b[0]), "r"(b[1]));
}
__device__ __forceinline__ void mma_bf16(float c[4], const uint32_t a[4], const uint32_t b[2]) {
    asm volatile(
        "mma.sync.aligned.m16n8k16.row.col.f32.bf16.bf16.f32 "
        "{%0,%1,%2,%3}, {%4,%5,%6,%7}, {%8,%9}, {%0,%1,%2,%3};"
        : "+f"(c[0]), "+f"(c[1]), "+f"(c[2]), "+f"(c[3])
        : "r"(a[0]), "r"(a[1]), "r"(a[2]), "r"(a[3]), "r"(b[0]), "r"(b[1]));
}
__device__ __forceinline__ uint32_t fpack_bf2(float lo, float hi) {
    __nv_bfloat162 h = __floats2bfloat162_rn(lo, hi);
    return *reinterpret_cast<uint32_t*>(&h);
}
__device__ __forceinline__ uint2 f4_bf(float4 v) {
    return make_uint2(fpack_bf2(v.x, v.y), fpack_bf2(v.z, v.w));
}

// SMEM geometry (32-bit words)
#define PA   36
#define PB   136
#define QK_A_W   (128 * PA)
#define QK_B_W   (32 * PB)
#define QK_BUF_W (QK_A_W + QK_B_W)
#define QK_SMEM  (2 * QK_BUF_W * 4)
#define LG_Q_W    (64 * PB)
#define LOGITS_SMEM (2 * LG_Q_W * 4)
#define RW        20
#define BF_A_W    (256 * RW)
#define BF_B_W    (128 * RW)
#define BF_BUF_W  (BF_A_W + BF_B_W)
#define BF_SMEM   (2 * BF_BUF_W * 4)
// v_gemm M=512 tiles
#define VG_A_W    (512 * RW)          // 10240
#define VG_B_W    (64 * RW)           // 1280
#define VG_BUF_W  (VG_A_W + VG_B_W)   // 11520
#define VG_SMEM   (2 * VG_BUF_W * 4)  // 92160

// ---------------- K0: pack Wv to bf16 k-pair words ------------------------------
__global__ void pack_wv(const float* __restrict__ Wv, uint32_t* __restrict__ wvbf) {
    int i = blockIdx.x * 256 + threadIdx.x;    // 131072 words
    wvbf[i] = fpack_bf2(Wv[2 * i], Wv[2 * i + 1]);
}

// ---------------- K1a: q/k projection (tf32) ------------------------------------
__global__ void __launch_bounds__(256, 2)
qk_gemm_mma(const float* __restrict__ x,
            const float* __restrict__ Wq, const float* __restrict__ bq,
            const float* __restrict__ Wk, const float* __restrict__ bk) {
    extern __shared__ uint32_t sm[];

    const int tid  = threadIdx.x;
    const int lane = tid & 31, wid = tid >> 5;
    const int grp  = lane >> 2, tig = lane & 3;
    const int wm   = (wid >> 1) * 32;
    const int wn   = (wid & 1) * 64;
    const int n0   = blockIdx.x * 128;
    const int b    = blockIdx.y;

    const float* xb = x + (size_t)b * CC * NPIX;

    float acc[2][8][4] = {};
    float4 pa[4], pb[4];

    auto ldg_tile = [&](int k0) {
        #pragma unroll
        for (int l = 0; l < 4; l++) {
            int idx = l * 256 + tid;
            int m = idx >> 3, kq = idx & 7;
            const float* src = (m < 64) ? Wq + (size_t)m * CC : Wk + (size_t)(m - 64) * CC;
            pa[l] = *reinterpret_cast<const float4*>(src + k0 + kq * 4);
        }
        #pragma unroll
        for (int l = 0; l < 4; l++) {
            int idx = l * 256 + tid;
            int kk = idx >> 5, nq = idx & 31;
            pb[l] = *reinterpret_cast<const float4*>(
                xb + (size_t)(k0 + kk) * NPIX + n0 + nq * 4);
        }
    };
    auto sts_tile = [&](int buf) {
        uint32_t* A = sm + buf * QK_BUF_W;
        uint32_t* B = A + QK_A_W;
        #pragma unroll
        for (int l = 0; l < 4; l++) {
            int idx = l * 256 + tid;
            int m = idx >> 3, kq = idx & 7;
            *reinterpret_cast<uint4*>(A + m * PA + kq * 4) = tf32x4(pa[l]);
        }
        #pragma unroll
        for (int l = 0; l < 4; l++) {
            int idx = l * 256 + tid;
            int kk = idx >> 5, nq = idx & 31;
            *reinterpret_cast<uint4*>(B + kk * PB + nq * 4) = tf32x4(pb[l]);
        }
    };

    ldg_tile(0);
    sts_tile(0);
    __syncthreads();

    for (int i = 0; i < 16; i++) {
        if (i < 15) ldg_tile((i + 1) * 32);
        const uint32_t* A = sm + (i & 1) * QK_BUF_W;
        const uint32_t* B = A + QK_A_W;
        #pragma unroll
        for (int kk = 0; kk < 4; kk++) {
            const int kr = kk * 8 + tig;
            uint32_t a[2][4], bf[8][2];
            #pragma unroll
            for (int ii = 0; ii < 2; ii++) {
                a[ii][0] = A[(wm + ii * 16 + grp    ) * PA + kr];
                a[ii][1] = A[(wm + ii * 16 + grp + 8) * PA + kr];
                a[ii][2] = A[(wm + ii * 16 + grp    ) * PA + kr + 4];
                a[ii][3] = A[(wm + ii * 16 + grp + 8) * PA + kr + 4];
            }
            #pragma unroll
            for (int j = 0; j < 8; j++) {
                bf[j][0] = B[kr * PB       + wn + j * 8 + grp];
                bf[j][1] = B[(kr + 4) * PB + wn + j * 8 + grp];
            }
            #pragma unroll
            for (int ii = 0; ii < 2; ii++)
                #pragma unroll
                for (int j = 0; j < 8; j++)
                    mma_tf32(acc[ii][j], a[ii], bf[j]);
        }
        if (i < 15) { sts_tile((i + 1) & 1); __syncthreads(); }
    }

    #pragma unroll
    for (int i = 0; i < 2; i++) {
        #pragma unroll
        for (int r = 0; r < 2; r++) {
            int m = wm + i * 16 + grp + r * 8;
            float bias; float* dst;
            if (m < 64) { bias = bq[m];      dst = g_q + ((size_t)b * C8 + m) * SS; }
            else        { bias = bk[m - 64]; dst = g_k + ((size_t)b * C8 + m - 64) * SS; }
            float* row = dst + n0 + wn + tig * 2;
            #pragma unroll
            for (int j = 0; j < 8; j++) {
                float2 o;
                o.x = acc[i][j][r * 2 + 0] + bias;
                o.y = acc[i][j][r * 2 + 1] + bias;
                *reinterpret_cast<float2*>(row + j * 8) = o;
            }
        }
    }
}

// ---------------- K1b: v projection, M=512 x N=64, bf16 -------------------------
__global__ void __launch_bounds__(512, 1)
v_gemm_bf16(const float* __restrict__ x, const uint32_t* __restrict__ wvbf,
            const float* __restrict__ bv) {
    extern __shared__ uint32_t sm[];

    const int tid  = threadIdx.x;
    const int lane = tid & 31, wid = tid >> 5;   // 16 warps
    const int grp  = lane >> 2, tig = lane & 3;
    const int wm   = wid * 32;                   // 0..480
    const int n0   = blockIdx.x * 64;
    const int b    = blockIdx.y;
    const int bkp  = tid >> 4;                   // 0..31 (B uses tid<256 -> 0..15)
    const int bg   = tid & 15;

    const float* xb = x + (size_t)b * CC * NPIX;

    float acc[2][8][4] = {};
    uint4 pa[4];
    float4 pxlo, pxhi;

    auto ldg_tile = [&](int k0) {
        const int kw0 = k0 >> 1;
        #pragma unroll
        for (int l = 0; l < 4; l++) {
            int idx = l * 512 + tid;    // 2048 slots: m(512) x q(4)
            int m = idx >> 2, q = idx & 3;
            pa[l] = *reinterpret_cast<const uint4*>(
                wvbf + (size_t)m * (CC / 2) + kw0 + q * 4);
        }
        if (tid < 256) {
            const float* p0 = xb + (size_t)(k0 + 2 * bkp) * NPIX + n0 + bg * 4;
            pxlo = *reinterpret_cast<const float4*>(p0);
            pxhi = *reinterpret_cast<const float4*>(p0 + NPIX);
        }
    };
    auto sts_tile = [&](int buf) {
        uint32_t* A = sm + buf * VG_BUF_W;   // [m][16 k-pair words + 4 pad]
        uint32_t* B = A + VG_A_W;            // [n][16 k-pair words + 4 pad]
        #pragma unroll
        for (int l = 0; l < 4; l++) {
            int idx = l * 512 + tid;
            int m = idx >> 2, q = idx & 3;
            *reinterpret_cast<uint4*>(A + m * RW + q * 4) = pa[l];
        }
        if (tid < 256) {
            B[(bg * 4 + 0) * RW + bkp] = fpack_bf2(pxlo.x, pxhi.x);
            B[(bg * 4 + 1) * RW + bkp] = fpack_bf2(pxlo.y, pxhi.y);
            B[(bg * 4 + 2) * RW + bkp] = fpack_bf2(pxlo.z, pxhi.z);
            B[(bg * 4 + 3) * RW + bkp] = fpack_bf2(pxlo.w, pxhi.w);
        }
    };

    ldg_tile(0);
    sts_tile(0);
    __syncthreads();

    for (int i = 0; i < 16; i++) {
        if (i < 15) ldg_tile((i + 1) * 32);

        const uint32_t* A = sm + (i & 1) * VG_BUF_W;
        const uint32_t* B = A + VG_A_W;
        #pragma unroll
        for (int s = 0; s < 2; s++) {
            uint32_t a[2][4], bf[8][2];
            #pragma unroll
            for (int ii = 0; ii < 2; ii++) {
                a[ii][0] = A[(wm + ii * 16 + grp    ) * RW + s * 8 + tig];
                a[ii][1] = A[(wm + ii * 16 + grp + 8) * RW + s * 8 + tig];
                a[ii][2] = A[(wm + ii * 16 + grp    ) * RW + s * 8 + tig + 4];
                a[ii][3] = A[(wm + ii * 16 + grp + 8) * RW + s * 8 + tig + 4];
            }
            #pragma unroll
            for (int j = 0; j < 8; j++) {
                bf[j][0] = B[(j * 8 + grp) * RW + s * 8 + tig];
                bf[j][1] = B[(j * 8 + grp) * RW + s * 8 + tig + 4];
            }
            #pragma unroll
            for (int ii = 0; ii < 2; ii++)
                #pragma unroll
                for (int j = 0; j < 8; j++)
                    mma_bf16(acc[ii][j], a[ii], bf[j]);
        }

        if (i < 15) { sts_tile((i + 1) & 1); __syncthreads(); }
    }

    #pragma unroll
    for (int i = 0; i < 2; i++) {
        #pragma unroll
        for (int r = 0; r < 2; r++) {
            int m = wm + i * 16 + grp + r * 8;
            float bias = bv[m];
            uint32_t* row = g_vbf + ((size_t)b * CC + m) * SSW + (n0 >> 1) + tig;
            #pragma unroll
            for (int j = 0; j < 8; j++)
                row[j * 4] = fpack_bf2(acc[i][j][r * 2 + 0] + bias,
                                       acc[i][j][r * 2 + 1] + bias);
        }
    }
}

// ---------------- K2a: fp32 plane transpose (q, k) ------------------------------
__global__ void transpose_wh(float* __restrict__ dst, const float* __restrict__ src) {
    __shared__ float t[32][33];
    const size_t base = (size_t)blockIdx.z * SS;
    const int x0 = blockIdx.x * 32, y0 = blockIdx.y * 32;
    const int tx = threadIdx.x, ty = threadIdx.y;
    #pragma unroll
    for (int i = 0; i < 32; i += 8)
        t[ty + i][tx] = src[base + (size_t)(y0 + ty + i) * S + x0 + tx];
    __syncthreads();
    #pragma unroll
    for (int i = 0; i < 32; i += 8)
        dst[base + (size_t)(x0 + ty + i) * S + y0 + tx] = t[tx][ty + i];
}

// ---------------- K2b: bf16 plane transpose (v) ---------------------------------
__global__ void transpose_wh_bf16(uint32_t* __restrict__ dst, const uint32_t* __restrict__ src) {
    __shared__ unsigned short t[64][66];
    const size_t base = (size_t)blockIdx.z * SSW;
    const int w0 = blockIdx.x * 64, h0 = blockIdx.y * 64;
    const int tx = threadIdx.x, ty = threadIdx.y;
    #pragma unroll
    for (int i = 0; i < 64; i += 8) {
        int w = w0 + ty + i;
        uint32_t word = src[base + (size_t)w * 64 + (h0 >> 1) + tx];
        t[tx * 2 + 0][ty + i] = (unsigned short)(word & 0xffff);
        t[tx * 2 + 1][ty + i] = (unsigned short)(word >> 16);
    }
    __syncthreads();
    #pragma unroll
    for (int i = 0; i < 64; i += 8) {
        int h = h0 + ty + i;
        uint32_t word = *reinterpret_cast<const uint32_t*>(&t[ty + i][tx * 2]);
        dst[base + (size_t)h * 64 + (w0 >> 1) + tx] = word;
    }
}

// ---------------- K3: logits + unnormalized exp (bf16 out) + (m,s) stats -------
__global__ void __launch_bounds__(256, 2)
attn_logits_mma(const float* __restrict__ qsrc, const float* __restrict__ ksrc,
                uint32_t* __restrict__ attw, float2* __restrict__ stat, int is_col) {
    extern __shared__ uint32_t sm[];
    uint32_t* Qs = sm;
    uint32_t* Ks = sm + LG_Q_W;
    __shared__ float redm[128][2];
    __shared__ float reds[128][2];

    const int p = blockIdx.x;
    const int b = blockIdx.y;
    const int tid  = threadIdx.x;
    const int lane = tid & 31, wid = tid >> 5;
    const int grp  = lane >> 2, tig = lane & 3;
    const int wm   = (wid >> 1) * 32;
    const int wc   = wid & 1;
    const int wn   = wc * 64;

    const size_t qbase = (size_t)b * C8 * SS + (size_t)p * S;

    #pragma unroll
    for (int l = 0; l < 8; l++) {
        int idx = l * 256 + tid;
        int cc  = idx >> 5;
        int nq  = idx & 31;
        size_t g = qbase + (size_t)cc * SS + nq * 4;
        *reinterpret_cast<uint4*>(Qs + cc * PB + nq * 4) =
            tf32x4(*reinterpret_cast<const float4*>(qsrc + g));
        *reinterpret_cast<uint4*>(Ks + cc * PB + nq * 4) =
            tf32x4(*reinterpret_cast<const float4*>(ksrc + g));
    }
    __syncthreads();

    float acc[2][8][4] = {};
    #pragma unroll
    for (int kk = 0; kk < 8; kk++) {
        const int kr = kk * 8 + tig;
        uint32_t a[2][4], bf[8][2];
        #pragma unroll
        for (int i = 0; i < 2; i++) {
            a[i][0] = Qs[kr * PB       + wm + i * 16 + grp];
            a[i][1] = Qs[kr * PB       + wm + i * 16 + grp + 8];
            a[i][2] = Qs[(kr + 4) * PB + wm + i * 16 + grp];
            a[i][3] = Qs[(kr + 4) * PB + wm + i * 16 + grp + 8];
        }
        #pragma unroll
        for (int j = 0; j < 8; j++) {
            bf[j][0] = Ks[kr * PB       + wn + j * 8 + grp];
            bf[j][1] = Ks[(kr + 4) * PB + wn + j * 8 + grp];
        }
        #pragma unroll
        for (int i = 0; i < 2; i++)
            #pragma unroll
            for (int j = 0; j < 8; j++)
                mma_tf32(acc[i][j], a[i], bf[j]);
    }

    if (is_col) {
        #pragma unroll
        for (int i = 0; i < 2; i++)
            #pragma unroll
            for (int r = 0; r < 2; r++) {
                int rr = wm + i * 16 + grp + r * 8;
                #pragma unroll
                for (int j = 0; j < 8; j++) {
                    int u = wn + j * 8 + tig * 2;
                    if (rr == u)     acc[i][j][r * 2 + 0] = NEG_INF_F;
                    if (rr == u + 1) acc[i][j][r * 2 + 1] = NEG_INF_F;
                }
            }
    }

    float mloc[2][2];
    #pragma unroll
    for (int i = 0; i < 2; i++)
        #pragma unroll
        for (int r = 0; r < 2; r++) {
            float ml = -3.4e38f;
            #pragma unroll
            for (int j = 0; j < 8; j++) {
                ml = fmaxf(ml, acc[i][j][r * 2 + 0]);
                ml = fmaxf(ml, acc[i][j][r * 2 + 1]);
            }
            ml = fmaxf(ml, __shfl_xor_sync(0xffffffff, ml, 1));
            ml = fmaxf(ml, __shfl_xor_sync(0xffffffff, ml, 2));
            mloc[i][r] = ml;
        }
    if (tig == 0) {
        #pragma unroll
        for (int i = 0; i < 2; i++)
            #pragma unroll
            for (int r = 0; r < 2; r++)
                redm[wm + i * 16 + grp + r * 8][wc] = mloc[i][r];
    }
    __syncthreads();

    float mrow[2][2], sloc[2][2];
    #pragma unroll
    for (int i = 0; i < 2; i++)
        #pragma unroll
        for (int r = 0; r < 2; r++) {
            int rr = wm + i * 16 + grp + r * 8;
            float m = fmaxf(redm[rr][0], redm[rr][1]);
            mrow[i][r] = m;
            float sl = 0.f;
            #pragma unroll
            for (int j = 0; j < 8; j++) {
                float e0 = __expf(acc[i][j][r * 2 + 0] - m);
                float e1 = __expf(acc[i][j][r * 2 + 1] - m);
                acc[i][j][r * 2 + 0] = e0;
                acc[i][j][r * 2 + 1] = e1;
                sl += e0 + e1;
            }
            sl += __shfl_xor_sync(0xffffffff, sl, 1);
            sl += __shfl_xor_sync(0xffffffff, sl, 2);
            sloc[i][r] = sl;
        }
    if (tig == 0) {
        #pragma unroll
        for (int i = 0; i < 2; i++)
            #pragma unroll
            for (int r = 0; r < 2; r++)
                reds[wm + i * 16 + grp + r * 8][wc] = sloc[i][r];
    }
    __syncthreads();

    if (tig == 0 && wc == 0) {
        #pragma unroll
        for (int i = 0; i < 2; i++)
            #pragma unroll
            for (int r = 0; r < 2; r++) {
                int rr = wm + i * 16 + grp + r * 8;
                stat[(size_t)b * SS + (size_t)p * S + rr] =
                    make_float2(mrow[i][r], reds[rr][0] + reds[rr][1]);
            }
    }

    const size_t obase_w  = ((size_t)b * SS * 256 +
                            (is_col ? (size_t)p * 256 : (size_t)p * S * 256 + 128)) >> 1;
    const size_t rstride_w = (is_col ? (size_t)S * 256 : 256) >> 1;
    #pragma unroll
    for (int i = 0; i < 2; i++) {
        #pragma unroll
        for (int r = 0; r < 2; r++) {
            int rr = wm + i * 16 + grp + r * 8;
            uint32_t* row = attw + obase_w + (size_t)rr * rstride_w + ((wn >> 1) + tig);
            #pragma unroll
            for (int j = 0; j < 8; j++)
                row[j * 4] = fpack_bf2(acc[i][j][r * 2 + 0], acc[i][j][r * 2 + 1]);
        }
    }
}

// ---------------- K4: combine halves -> per-pixel normalization scales ---------
__global__ void softmax_combine(const float2* __restrict__ sc, const float2* __restrict__ sr,
                                float* __restrict__ scol, float* __restrict__ srow) {
    const int b = blockIdx.y;
    const int t = blockIdx.x * 256 + threadIdx.x;
    const int w = t & (S - 1), h = t >> 7;
    float2 c = sc[(size_t)b * SS + t];
    float2 r = sr[(size_t)b * SS + w * S + h];
    float m  = fmaxf(c.x, r.x);
    float ec = __expf(c.x - m), er = __expf(r.x - m);
    float inv = 1.f / (c.y * ec + r.y * er);
    scol[(size_t)b * SS + t]         = ec * inv;
    srow[(size_t)b * SS + w * S + h] = er * inv;
}

// ---------------- K5: attention @ V, bf16 m16n8k16, M=256 ----------------------
__global__ void __launch_bounds__(512, 1)
attn_av_mma(const uint32_t* __restrict__ vsrc, const uint32_t* __restrict__ attw,
            float* __restrict__ dstf, uint32_t* __restrict__ dstw,
            const float* __restrict__ gammap,
            const float* __restrict__ xres, const float* __restrict__ scale,
            int is_col) {
    extern __shared__ uint32_t sm[];

    const int ct = blockIdx.x;
    const int p  = blockIdx.y;
    const int b  = blockIdx.z;
    const int tid  = threadIdx.x;
    const int lane = tid & 31, wid = tid >> 5;
    const int grp  = lane >> 2, tig = lane & 3;
    const int wm   = (wid >> 1) * 32;
    const int wn   = (wid & 1) * 64;

    const size_t vbase_f = (size_t)(b * CC + ct * 256) * SS + (size_t)p * S;
    const size_t vbase_w = vbase_f >> 1;
    const size_t abase_w = ((size_t)b * SS * 256 +
                           (is_col ? (size_t)p * 256 : (size_t)p * S * 256 + 128)) >> 1;
    const size_t aq_w    = (is_col ? (size_t)S * 256 : 256) >> 1;

    const float gm = gammap[0];

    float acc[2][8][4] = {};
    uint4 pvw[2], pt;

    auto ldg_tile = [&](int u0) {
        #pragma unroll
        for (int l = 0; l < 2; l++) {
            int idx = l * 512 + tid;
            int cp = idx >> 2, u4 = idx & 3;
            pvw[l] = *reinterpret_cast<const uint4*>(
                vsrc + vbase_w + (size_t)cp * SSW + (u0 >> 1) + u4 * 4);
        }
        {
            int qp = tid >> 2, u4 = tid & 3;
            pt = *reinterpret_cast<const uint4*>(
                attw + abase_w + (size_t)qp * aq_w + (u0 >> 1) + u4 * 4);
        }
    };
    auto sts_tile = [&](int buf) {
        uint32_t* V = sm + buf * BF_BUF_W;
        uint32_t* T = V + BF_A_W;
        #pragma unroll
        for (int l = 0; l < 2; l++) {
            int idx = l * 512 + tid;
            int cp = idx >> 2, u4 = idx & 3;
            *reinterpret_cast<uint4*>(V + cp * RW + u4 * 4) = pvw[l];
        }
        {
            int qp = tid >> 2, u4 = tid & 3;
            *reinterpret_cast<uint4*>(T + qp * RW + u4 * 4) = pt;
        }
    };

    ldg_tile(0);
    sts_tile(0);
    __syncthreads();

    for (int i = 0; i < 4; i++) {
        if (i < 3) ldg_tile((i + 1) * 32);

        const uint32_t* V = sm + (i & 1) * BF_BUF_W;
        const uint32_t* T = V + BF_A_W;
        #pragma unroll
        for (int s = 0; s < 2; s++) {
            uint32_t a[2][4], bf[8][2];
            #pragma unroll
            for (int ii = 0; ii < 2; ii++) {
                a[ii][0] = V[(wm + ii * 16 + grp    ) * RW + s * 8 + tig];
                a[ii][1] = V[(wm + ii * 16 + grp + 8) * RW + s * 8 + tig];
                a[ii][2] = V[(wm + ii * 16 + grp    ) * RW + s * 8 + tig + 4];
                a[ii][3] = V[(wm + ii * 16 + grp + 8) * RW + s * 8 + tig + 4];
            }
            #pragma unroll
            for (int j = 0; j < 8; j++) {
                bf[j][0] = T[(wn + j * 8 + grp) * RW + s * 8 + tig];
                bf[j][1] = T[(wn + j * 8 + grp) * RW + s * 8 + tig + 4];
            }
            #pragma unroll
            for (int ii = 0; ii < 2; ii++)
                #pragma unroll
                for (int j = 0; j < 8; j++)
                    mma_bf16(acc[ii][j], a[ii], bf[j]);
        }

        if (i < 3) { sts_tile((i + 1) & 1); __syncthreads(); }
    }

    const float* scl = scale + (size_t)b * SS + (size_t)p * S;
    float2 scv[8];
    #pragma unroll
    for (int j = 0; j < 8; j++)
        scv[j] = *reinterpret_cast<const float2*>(scl + wn + j * 8 + tig * 2);

    #pragma unroll
    for (int i = 0; i < 2; i++) {
        #pragma unroll
        for (int r = 0; r < 2; r++) {
            int cl = wm + i * 16 + grp + r * 8;
            size_t off = vbase_f + (size_t)cl * SS + wn + tig * 2;
            if (is_col) {
                uint32_t* roww = dstw + (off >> 1);
                #pragma unroll
                for (int j = 0; j < 8; j++)
                    roww[j * 4] = fpack_bf2(gm * scv[j].x * acc[i][j][r * 2 + 0],
                                            gm * scv[j].y * acc[i][j][r * 2 + 1]);
            } else {
                float* row = dstf + off;
                const float* xrow = xres + off;
                #pragma unroll
                for (int j = 0; j < 8; j++) {
                    float2 xr = *reinterpret_cast<const float2*>(xrow + j * 8);
                    float2 o;
                    o.x = gm * scv[j].x * acc[i][j][r * 2 + 0] + xr.x;
                    o.y = gm * scv[j].y * acc[i][j][r * 2 + 1] + xr.y;
                    *reinterpret_cast<float2*>(row + j * 8) = o;
                }
            }
        }
    }
}

// ---------------- K6: out += transpose(ocolT bf16) -----------------------------
__global__ void final_combine(const uint32_t* __restrict__ ocolT, float* __restrict__ out) {
    __shared__ unsigned short t[64][66];
    const size_t base_w = (size_t)blockIdx.z * SSW;
    const size_t base_f = (size_t)blockIdx.z * SS;
    const int w0 = blockIdx.x * 64, h0 = blockIdx.y * 64;
    const int tx = threadIdx.x, ty = threadIdx.y;

    #pragma unroll
    for (int i = 0; i < 64; i += 8) {
        int h = h0 + ty + i;
        uint32_t word = ocolT[base_w + (size_t)h * 64 + (w0 >> 1) + tx];
        t[tx * 2 + 0][ty + i] = (unsigned short)(word & 0xffff);
        t[tx * 2 + 1][ty + i] = (unsigned short)(word >> 16);
    }
    __syncthreads();
    #pragma unroll
    for (int i = 0; i < 64; i += 8) {
        int w = w0 + ty + i;
        uint32_t word = *reinterpret_cast<const uint32_t*>(&t[ty + i][tx * 2]);
        __nv_bfloat162 bf = *reinterpret_cast<__nv_bfloat162*>(&word);
        float* o = out + base_f + (size_t)w * S + h0 + tx * 2;
        float2 cur = *reinterpret_cast<float2*>(o);
        cur.x += __bfloat162float(bf.x);
        cur.y += __bfloat162float(bf.y);
        *reinterpret_cast<float2*>(o) = cur;
    }
}

// ---------------- launch ------------------------------------------------------
extern "C" void kernel_launch(void* const* d_in, const int* in_sizes, int n_in,
                              void* d_out, int out_size) {
    const float* x     = (const float*)d_in[0];
    const float* Wq    = (const float*)d_in[1];
    const float* bq    = (const float*)d_in[2];
    const float* Wk    = (const float*)d_in[3];
    const float* bk    = (const float*)d_in[4];
    const float* Wv    = (const float*)d_in[5];
    const float* bv    = (const float*)d_in[6];
    const float* gamma = (const float*)d_in[7];
    float* out = (float*)d_out;

    float *q, *k, *qT, *kT, *scol, *srow;
    uint32_t *wvbf, *vbf, *vTbf, *att, *ocolT;
    float2 *stc, *str;
    cudaGetSymbolAddress((void**)&q,     g_q);
    cudaGetSymbolAddress((void**)&k,     g_k);
    cudaGetSymbolAddress((void**)&qT,    g_qT);
    cudaGetSymbolAddress((void**)&kT,    g_kT);
    cudaGetSymbolAddress((void**)&wvbf,  g_wvbf);
    cudaGetSymbolAddress((void**)&vbf,   g_vbf);
    cudaGetSymbolAddress((void**)&vTbf,  g_vTbf);
    cudaGetSymbolAddress((void**)&att,   g_att);
    cudaGetSymbolAddress((void**)&ocolT, g_ocolTbf);
    cudaGetSymbolAddress((void**)&stc,   g_stat_col);
    cudaGetSymbolAddress((void**)&str,   g_stat_row);
    cudaGetSymbolAddress((void**)&scol,  g_scale_col);
    cudaGetSymbolAddress((void**)&srow,  g_scale_row);

    static cudaStream_t s1 = nullptr;
    static cudaEvent_t evFork = nullptr, evV = nullptr, evT = nullptr,
                       evSoft = nullptr, evCol = nullptr;
    static bool init_done = false;
    if (!init_done) {
        cudaStreamCreateWithFlags(&s1, cudaStreamNonBlocking);
        cudaEventCreateWithFlags(&evFork, cudaEventDisableTiming);
        cudaEventCreateWithFlags(&evV,    cudaEventDisableTiming);
        cudaEventCreateWithFlags(&evT,    cudaEventDisableTiming);
        cudaEventCreateWithFlags(&evSoft, cudaEventDisableTiming);
        cudaEventCreateWithFlags(&evCol,  cudaEventDisableTiming);
        cudaFuncSetAttribute(qk_gemm_mma,     cudaFuncAttributeMaxDynamicSharedMemorySize, QK_SMEM);
        cudaFuncSetAttribute(v_gemm_bf16,     cudaFuncAttributeMaxDynamicSharedMemorySize, VG_SMEM);
        cudaFuncSetAttribute(attn_logits_mma, cudaFuncAttributeMaxDynamicSharedMemorySize, LOGITS_SMEM);
        cudaFuncSetAttribute(attn_av_mma,     cudaFuncAttributeMaxDynamicSharedMemorySize, BF_SMEM);
        init_done = true;
    }

    // fork: v chain on s1 (pack_wv -> v_gemm -> vT transpose)
    cudaEventRecord(evFork, 0);
    cudaStreamWaitEvent(s1, evFork, 0);
    pack_wv<<<512, 256, 0, s1>>>(Wv, wvbf);
    v_gemm_bf16<<<dim3(NPIX / 64, BB), 512, VG_SMEM, s1>>>(x, wvbf, bv);
    cudaEventRecord(evV, s1);
    transpose_wh_bf16<<<dim3(2, 2, BB * CC), dim3(32, 8), 0, s1>>>(vTbf, vbf);
    cudaEventRecord(evT, s1);

    // qk chain on stream 0
    qk_gemm_mma<<<dim3(NPIX / 128, BB), 256, QK_SMEM>>>(x, Wq, bq, Wk, bk);
    transpose_wh<<<dim3(4, 4, BB * C8), dim3(32, 8)>>>(qT, q);
    transpose_wh<<<dim3(4, 4, BB * C8), dim3(32, 8)>>>(kT, k);
    attn_logits_mma<<<dim3(S, BB), 256, LOGITS_SMEM>>>(qT, kT, att, stc, 1);
    attn_logits_mma<<<dim3(S, BB), 256, LOGITS_SMEM>>>(q,  k,  att, str, 0);
    softmax_combine<<<dim3(SS / 256, BB), 256>>>(stc, str, scol, srow);
    cudaEventRecord(evSoft, 0);

    // av-row on stream 0 (needs vbf); av-col on s1 (needs vTbf + att/scol)
    cudaStreamWaitEvent(0, evV, 0);
    attn_av_mma<<<dim3(2, S, BB), 512, BF_SMEM>>>(vbf, att, out, nullptr, gamma, x, srow, 0);
    cudaStreamWaitEvent(s1, evSoft, 0);
    attn_av_mma<<<dim3(2, S, BB), 512, BF_SMEM, s1>>>(vTbf, att, nullptr, ocolT, gamma, nullptr, scol, 1);
    cudaEventRecord(evCol, s1);

    // join: out += ocolT^T
    cudaStreamWaitEvent(0, evCol, 0);
    final_combine<<<dim3(2, 2, BB * CC), dim3(32, 8)>>>(ocolT, out);
}

// round 12
// speedup vs baseline: 1.5527x; 1.0068x over previous
#include <cuda_runtime.h>
#include <cuda_bf16.h>
#include <cstdint>

#define BB 8
#define CC 512
#define C8 64
#define S  128
#define SS (S*S)
#define NPIX (SS)
#define SSW (SS/2)
#define NEG_INF_F (-1000000000.0f)

// ---------------- scratch buffers (device globals; no allocation) ----------------
__device__ float    g_q    [BB * C8 * SS];
__device__ float    g_k    [BB * C8 * SS];
__device__ float    g_qT   [BB * C8 * SS];
__device__ float    g_kT   [BB * C8 * SS];
__device__ uint32_t g_wvbf [CC * CC / 2];
__device__ uint32_t g_vbf  [BB * CC * SSW];
__device__ uint32_t g_vTbf [BB * CC * SSW];
__device__ uint32_t g_att  [BB * SS * S];
__device__ uint32_t g_ocolTbf[BB * CC * SSW];
__device__ float2   g_stat_col[BB * SS];
__device__ float2   g_stat_row[BB * SS];
__device__ float    g_scale_col[BB * SS];
__device__ float    g_scale_row[BB * SS];

// ---------------- helpers --------------------------------------------------------
__device__ __forceinline__ uint32_t f2tf32(float f) {
    uint32_t u;
    asm("cvt.rn.tf32.f32 %0, %1;" : "=r"(u) : "f"(f));
    return u;
}
__device__ __forceinline__ uint4 tf32x4(float4 v) {
    return make_uint4(f2tf32(v.x), f2tf32(v.y), f2tf32(v.z), f2tf32(v.w));
}
__device__ __forceinline__ void mma_tf32(float c[4], const uint32_t a[4], const uint32_t b[2]) {
    asm volatile(
        "mma.sync.aligned.m16n8k8.row.col.f32.tf32.tf32.f32 "
        "{%0,%1,%2,%3}, {%4,%5,%6,%7}, {%8,%9}, {%0,%1,%2,%3};"
        : "+f"(c[0]), "+f"(c[1]), "+f"(c[2]), "+f"(c[3])
        : "r"(a[0]), "r"(a[1]), "r"(a[2]), "r"(a[3]), "r"(b[0]), "r"(b[1]));
}
__device__ __forceinline__ void mma_bf16(float c[4], const uint32_t a[4], const uint32_t b[2]) {
    asm volatile(
        "mma.sync.aligned.m16n8k16.row.col.f32.bf16.bf16.f32 "
        "{%0,%1,%2,%3}, {%4,%5,%6,%7}, {%8,%9}, {%0,%1,%2,%3};"
        : "+f"(c[0]), "+f"(c[1]), "+f"(c[2]), "+f"(c[3])
        : "r"(a[0]), "r"(a[1]), "r"(a[2]), "r"(a[3]), "r"(b[0]), "r"(b[1]));
}
__device__ __forceinline__ uint32_t fpack_bf2(float lo, float hi) {
    __nv_bfloat162 h = __floats2bfloat162_rn(lo, hi);
    return *reinterpret_cast<uint32_t*>(&h);
}
__device__ __forceinline__ void cp_async16(uint32_t saddr, const void* gptr) {
    asm volatile("cp.async.cg.shared.global [%0], [%1], 16;"
                 :: "r"(saddr), "l"(gptr) : "memory");
}
#define CP_COMMIT() asm volatile("cp.async.commit_group;" ::: "memory")
#define CP_WAIT0()  asm volatile("cp.async.wait_group 0;" ::: "memory")

// SMEM geometry (32-bit words)
#define PA   36
#define PB   136
#define QK_A_W   (128 * PA)
#define QK_B_W   (32 * PB)
#define QK_BUF_W (QK_A_W + QK_B_W)
#define QK_SMEM  (2 * QK_BUF_W * 4)
#define LG_Q_W    (64 * PB)
#define LOGITS_SMEM (2 * LG_Q_W * 4)
#define RW        20
#define BF_A_W    (256 * RW)
#define BF_B_W    (128 * RW)
#define BF_BUF_W  (BF_A_W + BF_B_W)
#define BF_SMEM   (2 * BF_BUF_W * 4)
#define VG_A_W    (512 * RW)
#define VG_B_W    (64 * RW)
#define VG_BUF_W  (VG_A_W + VG_B_W)
#define VG_SMEM   (2 * VG_BUF_W * 4)

// ---------------- K0: pack Wv to bf16 k-pair words ------------------------------
__global__ void pack_wv(const float* __restrict__ Wv, uint32_t* __restrict__ wvbf) {
    int i = blockIdx.x * 256 + threadIdx.x;
    wvbf[i] = fpack_bf2(Wv[2 * i], Wv[2 * i + 1]);
}

// ---------------- K1a: q/k projection (tf32, cp.async pipelined) ----------------
// Raw fp32 bits fed to tf32 MMA (HW truncation of low mantissa bits).
__global__ void __launch_bounds__(256, 2)
qk_gemm_mma(const float* __restrict__ x,
            const float* __restrict__ Wq, const float* __restrict__ bq,
            const float* __restrict__ Wk, const float* __restrict__ bk) {
    extern __shared__ uint32_t sm[];
    const uint32_t sb = (uint32_t)__cvta_generic_to_shared(sm);

    const int tid  = threadIdx.x;
    const int lane = tid & 31, wid = tid >> 5;
    const int grp  = lane >> 2, tig = lane & 3;
    const int wm   = (wid >> 1) * 32;
    const int wn   = (wid & 1) * 64;
    const int n0   = blockIdx.x * 128;
    const int b    = blockIdx.y;

    const float* xb = x + (size_t)b * CC * NPIX;

    float acc[2][8][4] = {};

    auto cp_tile = [&](int k0, int buf) {
        uint32_t A = sb + (buf * QK_BUF_W) * 4;
        uint32_t B = A + QK_A_W * 4;
        #pragma unroll
        for (int l = 0; l < 4; l++) {
            int idx = l * 256 + tid;
            int m = idx >> 3, kq = idx & 7;
            const float* src = (m < 64) ? Wq + (size_t)m * CC : Wk + (size_t)(m - 64) * CC;
            cp_async16(A + (m * PA + kq * 4) * 4, src + k0 + kq * 4);
        }
        #pragma unroll
        for (int l = 0; l < 4; l++) {
            int idx = l * 256 + tid;
            int kk = idx >> 5, nq = idx & 31;
            cp_async16(B + (kk * PB + nq * 4) * 4,
                       xb + (size_t)(k0 + kk) * NPIX + n0 + nq * 4);
        }
        CP_COMMIT();
    };

    cp_tile(0, 0);
    CP_WAIT0();
    __syncthreads();

    for (int i = 0; i < 16; i++) {
        if (i < 15) cp_tile((i + 1) * 32, (i + 1) & 1);

        const uint32_t* A = sm + (i & 1) * QK_BUF_W;
        const uint32_t* B = A + QK_A_W;
        #pragma unroll
        for (int kk = 0; kk < 4; kk++) {
            const int kr = kk * 8 + tig;
            uint32_t a[2][4], bf[8][2];
            #pragma unroll
            for (int ii = 0; ii < 2; ii++) {
                a[ii][0] = A[(wm + ii * 16 + grp    ) * PA + kr];
                a[ii][1] = A[(wm + ii * 16 + grp + 8) * PA + kr];
                a[ii][2] = A[(wm + ii * 16 + grp    ) * PA + kr + 4];
                a[ii][3] = A[(wm + ii * 16 + grp + 8) * PA + kr + 4];
            }
            #pragma unroll
            for (int j = 0; j < 8; j++) {
                bf[j][0] = B[kr * PB       + wn + j * 8 + grp];
                bf[j][1] = B[(kr + 4) * PB + wn + j * 8 + grp];
            }
            #pragma unroll
            for (int ii = 0; ii < 2; ii++)
                #pragma unroll
                for (int j = 0; j < 8; j++)
                    mma_tf32(acc[ii][j], a[ii], bf[j]);
        }

        if (i < 15) {
            CP_WAIT0();
            __syncthreads();
        }
    }

    #pragma unroll
    for (int i = 0; i < 2; i++) {
        #pragma unroll
        for (int r = 0; r < 2; r++) {
            int m = wm + i * 16 + grp + r * 8;
            float bias; float* dst;
            if (m < 64) { bias = bq[m];      dst = g_q + ((size_t)b * C8 + m) * SS; }
            else        { bias = bk[m - 64]; dst = g_k + ((size_t)b * C8 + m - 64) * SS; }
            float* row = dst + n0 + wn + tig * 2;
            #pragma unroll
            for (int j = 0; j < 8; j++) {
                float2 o;
                o.x = acc[i][j][r * 2 + 0] + bias;
                o.y = acc[i][j][r * 2 + 1] + bias;
                *reinterpret_cast<float2*>(row + j * 8) = o;
            }
        }
    }
}

// ---------------- K1b: v projection, M=512 x N=64, bf16 (A via cp.async) -------
__global__ void __launch_bounds__(512, 1)
v_gemm_bf16(const float* __restrict__ x, const uint32_t* __restrict__ wvbf,
            const float* __restrict__ bv) {
    extern __shared__ uint32_t sm[];
    const uint32_t sb = (uint32_t)__cvta_generic_to_shared(sm);

    const int tid  = threadIdx.x;
    const int lane = tid & 31, wid = tid >> 5;
    const int grp  = lane >> 2, tig = lane & 3;
    const int wm   = wid * 32;
    const int n0   = blockIdx.x * 64;
    const int b    = blockIdx.y;
    const int bkp  = tid >> 4;
    const int bg   = tid & 15;

    const float* xb = x + (size_t)b * CC * NPIX;

    float acc[2][8][4] = {};
    float4 pxlo, pxhi;

    auto cpA_tile = [&](int k0, int buf) {
        uint32_t A = sb + (buf * VG_BUF_W) * 4;
        const int kw0 = k0 >> 1;
        #pragma unroll
        for (int l = 0; l < 4; l++) {
            int idx = l * 512 + tid;
            int m = idx >> 2, q = idx & 3;
            cp_async16(A + (m * RW + q * 4) * 4,
                       wvbf + (size_t)m * (CC / 2) + kw0 + q * 4);
        }
        CP_COMMIT();
    };
    auto ldgB = [&](int k0) {
        if (tid < 256) {
            const float* p0 = xb + (size_t)(k0 + 2 * bkp) * NPIX + n0 + bg * 4;
            pxlo = *reinterpret_cast<const float4*>(p0);
            pxhi = *reinterpret_cast<const float4*>(p0 + NPIX);
        }
    };
    auto stsB = [&](int buf) {
        uint32_t* B = sm + buf * VG_BUF_W + VG_A_W;
        if (tid < 256) {
            B[(bg * 4 + 0) * RW + bkp] = fpack_bf2(pxlo.x, pxhi.x);
            B[(bg * 4 + 1) * RW + bkp] = fpack_bf2(pxlo.y, pxhi.y);
            B[(bg * 4 + 2) * RW + bkp] = fpack_bf2(pxlo.z, pxhi.z);
            B[(bg * 4 + 3) * RW + bkp] = fpack_bf2(pxlo.w, pxhi.w);
        }
    };

    cpA_tile(0, 0);
    ldgB(0);
    stsB(0);
    CP_WAIT0();
    __syncthreads();

    for (int i = 0; i < 16; i++) {
        if (i < 15) { cpA_tile((i + 1) * 32, (i + 1) & 1); ldgB((i + 1) * 32); }

        const uint32_t* A = sm + (i & 1) * VG_BUF_W;
        const uint32_t* B = A + VG_A_W;
        #pragma unroll
        for (int s = 0; s < 2; s++) {
            uint32_t a[2][4], bf[8][2];
            #pragma unroll
            for (int ii = 0; ii < 2; ii++) {
                a[ii][0] = A[(wm + ii * 16 + grp    ) * RW + s * 8 + tig];
                a[ii][1] = A[(wm + ii * 16 + grp + 8) * RW + s * 8 + tig];
                a[ii][2] = A[(wm + ii * 16 + grp    ) * RW + s * 8 + tig + 4];
                a[ii][3] = A[(wm + ii * 16 + grp + 8) * RW + s * 8 + tig + 4];
            }
            #pragma unroll
            for (int j = 0; j < 8; j++) {
                bf[j][0] = B[(j * 8 + grp) * RW + s * 8 + tig];
                bf[j][1] = B[(j * 8 + grp) * RW + s * 8 + tig + 4];
            }
            #pragma unroll
            for (int ii = 0; ii < 2; ii++)
                #pragma unroll
                for (int j = 0; j < 8; j++)
                    mma_bf16(acc[ii][j], a[ii], bf[j]);
        }

        if (i < 15) {
            stsB((i + 1) & 1);
            CP_WAIT0();
            __syncthreads();
        }
    }

    #pragma unroll
    for (int i = 0; i < 2; i++) {
        #pragma unroll
        for (int r = 0; r < 2; r++) {
            int m = wm + i * 16 + grp + r * 8;
            float bias = bv[m];
            uint32_t* row = g_vbf + ((size_t)b * CC + m) * SSW + (n0 >> 1) + tig;
            #pragma unroll
            for (int j = 0; j < 8; j++)
                row[j * 4] = fpack_bf2(acc[i][j][r * 2 + 0] + bias,
                                       acc[i][j][r * 2 + 1] + bias);
        }
    }
}

// ---------------- K2a: fp32 plane transpose (q, k) ------------------------------
__global__ void transpose_wh(float* __restrict__ dst, const float* __restrict__ src) {
    __shared__ float t[32][33];
    const size_t base = (size_t)blockIdx.z * SS;
    const int x0 = blockIdx.x * 32, y0 = blockIdx.y * 32;
    const int tx = threadIdx.x, ty = threadIdx.y;
    #pragma unroll
    for (int i = 0; i < 32; i += 8)
        t[ty + i][tx] = src[base + (size_t)(y0 + ty + i) * S + x0 + tx];
    __syncthreads();
    #pragma unroll
    for (int i = 0; i < 32; i += 8)
        dst[base + (size_t)(x0 + ty + i) * S + y0 + tx] = t[tx][ty + i];
}

// ---------------- K2b: bf16 plane transpose (v) ---------------------------------
__global__ void transpose_wh_bf16(uint32_t* __restrict__ dst, const uint32_t* __restrict__ src) {
    __shared__ unsigned short t[64][66];
    const size_t base = (size_t)blockIdx.z * SSW;
    const int w0 = blockIdx.x * 64, h0 = blockIdx.y * 64;
    const int tx = threadIdx.x, ty = threadIdx.y;
    #pragma unroll
    for (int i = 0; i < 64; i += 8) {
        int w = w0 + ty + i;
        uint32_t word = src[base + (size_t)w * 64 + (h0 >> 1) + tx];
        t[tx * 2 + 0][ty + i] = (unsigned short)(word & 0xffff);
        t[tx * 2 + 1][ty + i] = (unsigned short)(word >> 16);
    }
    __syncthreads();
    #pragma unroll
    for (int i = 0; i < 64; i += 8) {
        int h = h0 + ty + i;
        uint32_t word = *reinterpret_cast<const uint32_t*>(&t[ty + i][tx * 2]);
        dst[base + (size_t)h * 64 + (w0 >> 1) + tx] = word;
    }
}

// ---------------- K3: logits + unnormalized exp (bf16 out) + (m,s) stats -------
__global__ void __launch_bounds__(256, 2)
attn_logits_mma(const float* __restrict__ qsrc, const float* __restrict__ ksrc,
                uint32_t* __restrict__ attw, float2* __restrict__ stat, int is_col) {
    extern __shared__ uint32_t sm[];
    uint32_t* Qs = sm;
    uint32_t* Ks = sm + LG_Q_W;
    __shared__ float redm[128][2];
    __shared__ float reds[128][2];

    const int p = blockIdx.x;
    const int b = blockIdx.y;
    const int tid  = threadIdx.x;
    const int lane = tid & 31, wid = tid >> 5;
    const int grp  = lane >> 2, tig = lane & 3;
    const int wm   = (wid >> 1) * 32;
    const int wc   = wid & 1;
    const int wn   = wc * 64;

    const size_t qbase = (size_t)b * C8 * SS + (size_t)p * S;

    #pragma unroll
    for (int l = 0; l < 8; l++) {
        int idx = l * 256 + tid;
        int cc  = idx >> 5;
        int nq  = idx & 31;
        size_t g = qbase + (size_t)cc * SS + nq * 4;
        *reinterpret_cast<uint4*>(Qs + cc * PB + nq * 4) =
            tf32x4(*reinterpret_cast<const float4*>(qsrc + g));
        *reinterpret_cast<uint4*>(Ks + cc * PB + nq * 4) =
            tf32x4(*reinterpret_cast<const float4*>(ksrc + g));
    }
    __syncthreads();

    float acc[2][8][4] = {};
    #pragma unroll
    for (int kk = 0; kk < 8; kk++) {
        const int kr = kk * 8 + tig;
        uint32_t a[2][4], bf[8][2];
        #pragma unroll
        for (int i = 0; i < 2; i++) {
            a[i][0] = Qs[kr * PB       + wm + i * 16 + grp];
            a[i][1] = Qs[kr * PB       + wm + i * 16 + grp + 8];
            a[i][2] = Qs[(kr + 4) * PB + wm + i * 16 + grp];
            a[i][3] = Qs[(kr + 4) * PB + wm + i * 16 + grp + 8];
        }
        #pragma unroll
        for (int j = 0; j < 8; j++) {
            bf[j][0] = Ks[kr * PB       + wn + j * 8 + grp];
            bf[j][1] = Ks[(kr + 4) * PB + wn + j * 8 + grp];
        }
        #pragma unroll
        for (int i = 0; i < 2; i++)
            #pragma unroll
            for (int j = 0; j < 8; j++)
                mma_tf32(acc[i][j], a[i], bf[j]);
    }

    if (is_col) {
        #pragma unroll
        for (int i = 0; i < 2; i++)
            #pragma unroll
            for (int r = 0; r < 2; r++) {
                int rr = wm + i * 16 + grp + r * 8;
                #pragma unroll
                for (int j = 0; j < 8; j++) {
                    int u = wn + j * 8 + tig * 2;
                    if (rr == u)     acc[i][j][r * 2 + 0] = NEG_INF_F;
                    if (rr == u + 1) acc[i][j][r * 2 + 1] = NEG_INF_F;
                }
            }
    }

    float mloc[2][2];
    #pragma unroll
    for (int i = 0; i < 2; i++)
        #pragma unroll
        for (int r = 0; r < 2; r++) {
            float ml = -3.4e38f;
            #pragma unroll
            for (int j = 0; j < 8; j++) {
                ml = fmaxf(ml, acc[i][j][r * 2 + 0]);
                ml = fmaxf(ml, acc[i][j][r * 2 + 1]);
            }
            ml = fmaxf(ml, __shfl_xor_sync(0xffffffff, ml, 1));
            ml = fmaxf(ml, __shfl_xor_sync(0xffffffff, ml, 2));
            mloc[i][r] = ml;
        }
    if (tig == 0) {
        #pragma unroll
        for (int i = 0; i < 2; i++)
            #pragma unroll
            for (int r = 0; r < 2; r++)
                redm[wm + i * 16 + grp + r * 8][wc] = mloc[i][r];
    }
    __syncthreads();

    float mrow[2][2], sloc[2][2];
    #pragma unroll
    for (int i = 0; i < 2; i++)
        #pragma unroll
        for (int r = 0; r < 2; r++) {
            int rr = wm + i * 16 + grp + r * 8;
            float m = fmaxf(redm[rr][0], redm[rr][1]);
            mrow[i][r] = m;
            float sl = 0.f;
            #pragma unroll
            for (int j = 0; j < 8; j++) {
                float e0 = __expf(acc[i][j][r * 2 + 0] - m);
                float e1 = __expf(acc[i][j][r * 2 + 1] - m);
                acc[i][j][r * 2 + 0] = e0;
                acc[i][j][r * 2 + 1] = e1;
                sl += e0 + e1;
            }
            sl += __shfl_xor_sync(0xffffffff, sl, 1);
            sl += __shfl_xor_sync(0xffffffff, sl, 2);
            sloc[i][r] = sl;
        }
    if (tig == 0) {
        #pragma unroll
        for (int i = 0; i < 2; i++)
            #pragma unroll
            for (int r = 0; r < 2; r++)
                reds[wm + i * 16 + grp + r * 8][wc] = sloc[i][r];
    }
    __syncthreads();

    if (tig == 0 && wc == 0) {
        #pragma unroll
        for (int i = 0; i < 2; i++)
            #pragma unroll
            for (int r = 0; r < 2; r++) {
                int rr = wm + i * 16 + grp + r * 8;
                stat[(size_t)b * SS + (size_t)p * S + rr] =
                    make_float2(mrow[i][r], reds[rr][0] + reds[rr][1]);
            }
    }

    const size_t obase_w  = ((size_t)b * SS * 256 +
                            (is_col ? (size_t)p * 256 : (size_t)p * S * 256 + 128)) >> 1;
    const size_t rstride_w = (is_col ? (size_t)S * 256 : 256) >> 1;
    #pragma unroll
    for (int i = 0; i < 2; i++) {
        #pragma unroll
        for (int r = 0; r < 2; r++) {
            int rr = wm + i * 16 + grp + r * 8;
            uint32_t* row = attw + obase_w + (size_t)rr * rstride_w + ((wn >> 1) + tig);
            #pragma unroll
            for (int j = 0; j < 8; j++)
                row[j * 4] = fpack_bf2(acc[i][j][r * 2 + 0], acc[i][j][r * 2 + 1]);
        }
    }
}

// ---------------- K4: combine halves -> per-pixel normalization scales ---------
__global__ void softmax_combine(const float2* __restrict__ sc, const float2* __restrict__ sr,
                                float* __restrict__ scol, float* __restrict__ srow) {
    const int b = blockIdx.y;
    const int t = blockIdx.x * 256 + threadIdx.x;
    const int w = t & (S - 1), h = t >> 7;
    float2 c = sc[(size_t)b * SS + t];
    float2 r = sr[(size_t)b * SS + w * S + h];
    float m  = fmaxf(c.x, r.x);
    float ec = __expf(c.x - m), er = __expf(r.x - m);
    float inv = 1.f / (c.y * ec + r.y * er);
    scol[(size_t)b * SS + t]         = ec * inv;
    srow[(size_t)b * SS + w * S + h] = er * inv;
}

// ---------------- K5: attention @ V, bf16 m16n8k16, M=256 (cp.async) -----------
__global__ void __launch_bounds__(512, 1)
attn_av_mma(const uint32_t* __restrict__ vsrc, const uint32_t* __restrict__ attw,
            float* __restrict__ dstf, uint32_t* __restrict__ dstw,
            const float* __restrict__ gammap,
            const float* __restrict__ xres, const float* __restrict__ scale,
            int is_col) {
    extern __shared__ uint32_t sm[];
    const uint32_t sb = (uint32_t)__cvta_generic_to_shared(sm);

    const int ct = blockIdx.x;
    const int p  = blockIdx.y;
    const int b  = blockIdx.z;
    const int tid  = threadIdx.x;
    const int lane = tid & 31, wid = tid >> 5;
    const int grp  = lane >> 2, tig = lane & 3;
    const int wm   = (wid >> 1) * 32;
    const int wn   = (wid & 1) * 64;

    const size_t vbase_f = (size_t)(b * CC + ct * 256) * SS + (size_t)p * S;
    const size_t vbase_w = vbase_f >> 1;
    const size_t abase_w = ((size_t)b * SS * 256 +
                           (is_col ? (size_t)p * 256 : (size_t)p * S * 256 + 128)) >> 1;
    const size_t aq_w    = (is_col ? (size_t)S * 256 : 256) >> 1;

    const float gm = gammap[0];

    float acc[2][8][4] = {};

    auto cp_tile = [&](int u0, int buf) {
        uint32_t V = sb + (buf * BF_BUF_W) * 4;
        uint32_t T = V + BF_A_W * 4;
        #pragma unroll
        for (int l = 0; l < 2; l++) {
            int idx = l * 512 + tid;
            int cp = idx >> 2, u4 = idx & 3;
            cp_async16(V + (cp * RW + u4 * 4) * 4,
                       vsrc + vbase_w + (size_t)cp * SSW + (u0 >> 1) + u4 * 4);
        }
        {
            int qp = tid >> 2, u4 = tid & 3;
            cp_async16(T + (qp * RW + u4 * 4) * 4,
                       attw + abase_w + (size_t)qp * aq_w + (u0 >> 1) + u4 * 4);
        }
        CP_COMMIT();
    };

    cp_tile(0, 0);
    CP_WAIT0();
    __syncthreads();

    for (int i = 0; i < 4; i++) {
        if (i < 3) cp_tile((i + 1) * 32, (i + 1) & 1);

        const uint32_t* V = sm + (i & 1) * BF_BUF_W;
        const uint32_t* T = V + BF_A_W;
        #pragma unroll
        for (int s = 0; s < 2; s++) {
            uint32_t a[2][4], bf[8][2];
            #pragma unroll
            for (int ii = 0; ii < 2; ii++) {
                a[ii][0] = V[(wm + ii * 16 + grp    ) * RW + s * 8 + tig];
                a[ii][1] = V[(wm + ii * 16 + grp + 8) * RW + s * 8 + tig];
                a[ii][2] = V[(wm + ii * 16 + grp    ) * RW + s * 8 + tig + 4];
                a[ii][3] = V[(wm + ii * 16 + grp + 8) * RW + s * 8 + tig + 4];
            }
            #pragma unroll
            for (int j = 0; j < 8; j++) {
                bf[j][0] = T[(wn + j * 8 + grp) * RW + s * 8 + tig];
                bf[j][1] = T[(wn + j * 8 + grp) * RW + s * 8 + tig + 4];
            }
            #pragma unroll
            for (int ii = 0; ii < 2; ii++)
                #pragma unroll
                for (int j = 0; j < 8; j++)
                    mma_bf16(acc[ii][j], a[ii], bf[j]);
        }

        if (i < 3) {
            CP_WAIT0();
            __syncthreads();
        }
    }

    const float* scl = scale + (size_t)b * SS + (size_t)p * S;
    float2 scv[8];
    #pragma unroll
    for (int j = 0; j < 8; j++)
        scv[j] = *reinterpret_cast<const float2*>(scl + wn + j * 8 + tig * 2);

    #pragma unroll
    for (int i = 0; i < 2; i++) {
        #pragma unroll
        for (int r = 0; r < 2; r++) {
            int cl = wm + i * 16 + grp + r * 8;
            size_t off = vbase_f + (size_t)cl * SS + wn + tig * 2;
            if (is_col) {
                uint32_t* roww = dstw + (off >> 1);
                #pragma unroll
                for (int j = 0; j < 8; j++)
                    roww[j * 4] = fpack_bf2(gm * scv[j].x * acc[i][j][r * 2 + 0],
                                            gm * scv[j].y * acc[i][j][r * 2 + 1]);
            } else {
                float* row = dstf + off;
                const float* xrow = xres + off;
                #pragma unroll
                for (int j = 0; j < 8; j++) {
                    float2 xr = *reinterpret_cast<const float2*>(xrow + j * 8);
                    float2 o;
                    o.x = gm * scv[j].x * acc[i][j][r * 2 + 0] + xr.x;
                    o.y = gm * scv[j].y * acc[i][j][r * 2 + 1] + xr.y;
                    *reinterpret_cast<float2*>(row + j * 8) = o;
                }
            }
        }
    }
}

// ---------------- K6: out += transpose(ocolT bf16) -----------------------------
__global__ void final_combine(const uint32_t* __restrict__ ocolT, float* __restrict__ out) {
    __shared__ unsigned short t[64][66];
    const size_t base_w = (size_t)blockIdx.z * SSW;
    const size_t base_f = (size_t)blockIdx.z * SS;
    const int w0 = blockIdx.x * 64, h0 = blockIdx.y * 64;
    const int tx = threadIdx.x, ty = threadIdx.y;

    #pragma unroll
    for (int i = 0; i < 64; i += 8) {
        int h = h0 + ty + i;
        uint32_t word = ocolT[base_w + (size_t)h * 64 + (w0 >> 1) + tx];
        t[tx * 2 + 0][ty + i] = (unsigned short)(word & 0xffff);
        t[tx * 2 + 1][ty + i] = (unsigned short)(word >> 16);
    }
    __syncthreads();
    #pragma unroll
    for (int i = 0; i < 64; i += 8) {
        int w = w0 + ty + i;
        uint32_t word = *reinterpret_cast<const uint32_t*>(&t[ty + i][tx * 2]);
        __nv_bfloat162 bf = *reinterpret_cast<__nv_bfloat162*>(&word);
        float* o = out + base_f + (size_t)w * S + h0 + tx * 2;
        float2 cur = *reinterpret_cast<float2*>(o);
        cur.x += __bfloat162float(bf.x);
        cur.y += __bfloat162float(bf.y);
        *reinterpret_cast<float2*>(o) = cur;
    }
}

// ---------------- launch ------------------------------------------------------
extern "C" void kernel_launch(void* const* d_in, const int* in_sizes, int n_in,
                              void* d_out, int out_size) {
    const float* x     = (const float*)d_in[0];
    const float* Wq    = (const float*)d_in[1];
    const float* bq    = (const float*)d_in[2];
    const float* Wk    = (const float*)d_in[3];
    const float* bk    = (const float*)d_in[4];
    const float* Wv    = (const float*)d_in[5];
    const float* bv    = (const float*)d_in[6];
    const float* gamma = (const float*)d_in[7];
    float* out = (float*)d_out;

    float *q, *k, *qT, *kT, *scol, *srow;
    uint32_t *wvbf, *vbf, *vTbf, *att, *ocolT;
    float2 *stc, *str;
    cudaGetSymbolAddress((void**)&q,     g_q);
    cudaGetSymbolAddress((void**)&k,     g_k);
    cudaGetSymbolAddress((void**)&qT,    g_qT);
    cudaGetSymbolAddress((void**)&kT,    g_kT);
    cudaGetSymbolAddress((void**)&wvbf,  g_wvbf);
    cudaGetSymbolAddress((void**)&vbf,   g_vbf);
    cudaGetSymbolAddress((void**)&vTbf,  g_vTbf);
    cudaGetSymbolAddress((void**)&att,   g_att);
    cudaGetSymbolAddress((void**)&ocolT, g_ocolTbf);
    cudaGetSymbolAddress((void**)&stc,   g_stat_col);
    cudaGetSymbolAddress((void**)&str,   g_stat_row);
    cudaGetSymbolAddress((void**)&scol,  g_scale_col);
    cudaGetSymbolAddress((void**)&srow,  g_scale_row);

    static cudaStream_t s1 = nullptr;
    static cudaEvent_t evFork = nullptr, evV = nullptr, evT = nullptr,
                       evSoft = nullptr, evCol = nullptr;
    static bool init_done = false;
    if (!init_done) {
        cudaStreamCreateWithFlags(&s1, cudaStreamNonBlocking);
        cudaEventCreateWithFlags(&evFork, cudaEventDisableTiming);
        cudaEventCreateWithFlags(&evV,    cudaEventDisableTiming);
        cudaEventCreateWithFlags(&evT,    cudaEventDisableTiming);
        cudaEventCreateWithFlags(&evSoft, cudaEventDisableTiming);
        cudaEventCreateWithFlags(&evCol,  cudaEventDisableTiming);
        cudaFuncSetAttribute(qk_gemm_mma,     cudaFuncAttributeMaxDynamicSharedMemorySize, QK_SMEM);
        cudaFuncSetAttribute(v_gemm_bf16,     cudaFuncAttributeMaxDynamicSharedMemorySize, VG_SMEM);
        cudaFuncSetAttribute(attn_logits_mma, cudaFuncAttributeMaxDynamicSharedMemorySize, LOGITS_SMEM);
        cudaFuncSetAttribute(attn_av_mma,     cudaFuncAttributeMaxDynamicSharedMemorySize, BF_SMEM);
        init_done = true;
    }

    // fork: v chain on s1 (pack_wv -> v_gemm -> vT transpose)
    cudaEventRecord(evFork, 0);
    cudaStreamWaitEvent(s1, evFork, 0);
    pack_wv<<<512, 256, 0, s1>>>(Wv, wvbf);
    v_gemm_bf16<<<dim3(NPIX / 64, BB), 512, VG_SMEM, s1>>>(x, wvbf, bv);
    cudaEventRecord(evV, s1);
    transpose_wh_bf16<<<dim3(2, 2, BB * CC), dim3(32, 8), 0, s1>>>(vTbf, vbf);
    cudaEventRecord(evT, s1);

    // qk chain on stream 0
    qk_gemm_mma<<<dim3(NPIX / 128, BB), 256, QK_SMEM>>>(x, Wq, bq, Wk, bk);
    transpose_wh<<<dim3(4, 4, BB * C8), dim3(32, 8)>>>(qT, q);
    transpose_wh<<<dim3(4, 4, BB * C8), dim3(32, 8)>>>(kT, k);
    attn_logits_mma<<<dim3(S, BB), 256, LOGITS_SMEM>>>(qT, kT, att, stc, 1);
    attn_logits_mma<<<dim3(S, BB), 256, LOGITS_SMEM>>>(q,  k,  att, str, 0);
    softmax_combine<<<dim3(SS / 256, BB), 256>>>(stc, str, scol, srow);
    cudaEventRecord(evSoft, 0);

    // av-row on stream 0 (needs vbf); av-col on s1 (needs vTbf + att/scol)
    cudaStreamWaitEvent(0, evV, 0);
    attn_av_mma<<<dim3(2, S, BB), 512, BF_SMEM>>>(vbf, att, out, nullptr, gamma, x, srow, 0);
    cudaStreamWaitEvent(s1, evSoft, 0);
    attn_av_mma<<<dim3(2, S, BB), 512, BF_SMEM, s1>>>(vTbf, att, nullptr, ocolT, gamma, nullptr, scol, 1);
    cudaEventRecord(evCol, s1);

    // join: out += ocolT^T
    cudaStreamWaitEvent(0, evCol, 0);
    final_combine<<<dim3(2, 2, BB * CC), dim3(32, 8)>>>(ocolT, out);
}

// round 13
// speedup vs baseline: 1.6557x; 1.0663x over previous
#include <cuda_runtime.h>
#include <cuda_bf16.h>
#include <cstdint>

#define BB 8
#define CC 512
#define C8 64
#define S  128
#define SS (S*S)
#define NPIX (SS)
#define SSW (SS/2)
#define NEG_INF_F (-1000000000.0f)

// ---------------- scratch buffers (device globals; no allocation) ----------------
__device__ float    g_q    [BB * C8 * SS];
__device__ float    g_k    [BB * C8 * SS];
__device__ float    g_qT   [BB * C8 * SS];
__device__ float    g_kT   [BB * C8 * SS];
__device__ uint32_t g_wvbf [CC * CC / 2];
__device__ uint32_t g_vbf  [BB * CC * SSW];
__device__ uint32_t g_vTbf [BB * CC * SSW];
__device__ uint32_t g_att  [BB * SS * S];
__device__ uint32_t g_ocolTbf[BB * CC * SSW];
__device__ float2   g_stat_col[BB * SS];
__device__ float2   g_stat_row[BB * SS];
__device__ float    g_scale_col[BB * SS];
__device__ float    g_scale_row[BB * SS];

// ---------------- helpers --------------------------------------------------------
__device__ __forceinline__ uint32_t f2tf32(float f) {
    uint32_t u;
    asm("cvt.rn.tf32.f32 %0, %1;" : "=r"(u) : "f"(f));
    return u;
}
__device__ __forceinline__ uint4 tf32x4(float4 v) {
    return make_uint4(f2tf32(v.x), f2tf32(v.y), f2tf32(v.z), f2tf32(v.w));
}
__device__ __forceinline__ void mma_tf32(float c[4], const uint32_t a[4], const uint32_t b[2]) {
    asm volatile(
        "mma.sync.aligned.m16n8k8.row.col.f32.tf32.tf32.f32 "
        "{%0,%1,%2,%3}, {%4,%5,%6,%7}, {%8,%9}, {%0,%1,%2,%3};"
        : "+f"(c[0]), "+f"(c[1]), "+f"(c[2]), "+f"(c[3])
        : "r"(a[0]), "r"(a[1]), "r"(a[2]), "r"(a[3]), "r"(b[0]), "r"(b[1]));
}
__device__ __forceinline__ void mma_bf16(float c[4], const uint32_t a[4], const uint32_t b[2]) {
    asm volatile(
        "mma.sync.aligned.m16n8k16.row.col.f32.bf16.bf16.f32 "
        "{%0,%1,%2,%3}, {%4,%5,%6,%7}, {%8,%9}, {%0,%1,%2,%3};"
        : "+f"(c[0]), "+f"(c[1]), "+f"(c[2]), "+f"(c[3])
        : "r"(a[0]), "r"(a[1]), "r"(a[2]), "r"(a[3]), "r"(b[0]), "r"(b[1]));
}
__device__ __forceinline__ uint32_t fpack_bf2(float lo, float hi) {
    __nv_bfloat162 h = __floats2bfloat162_rn(lo, hi);
    return *reinterpret_cast<uint32_t*>(&h);
}
__device__ __forceinline__ void cp_async16(uint32_t saddr, const void* gptr) {
    asm volatile("cp.async.cg.shared.global [%0], [%1], 16;"
                 :: "r"(saddr), "l"(gptr) : "memory");
}
#define CP_COMMIT() asm volatile("cp.async.commit_group;" ::: "memory")
#define CP_WAIT0()  asm volatile("cp.async.wait_group 0;" ::: "memory")
#define CP_WAIT1()  asm volatile("cp.async.wait_group 1;" ::: "memory")

// SMEM geometry (32-bit words)
#define PA   36
#define PB   136
#define QK_A_W   (128 * PA)
#define QK_B_W   (32 * PB)
#define QK_BUF_W (QK_A_W + QK_B_W)
#define QK_SMEM  (3 * QK_BUF_W * 4)      // 107,520 B (3-stage)
#define LG_Q_W    (64 * PB)
#define LOGITS_SMEM (2 * LG_Q_W * 4)
#define RW        20
#define BF_A_W    (256 * RW)
#define BF_B_W    (128 * RW)
#define BF_BUF_W  (BF_A_W + BF_B_W)
#define BF_SMEM   (3 * BF_BUF_W * 4)     // 92,160 B (3-stage)
#define VG_A_W    (512 * RW)
#define VG_B_W    (64 * RW)
#define VG_BUF_W  (VG_A_W + VG_B_W)
#define VG_SMEM   (3 * VG_BUF_W * 4)     // 138,240 B (3-stage)

// ---------------- K0: pack Wv to bf16 k-pair words ------------------------------
__global__ void pack_wv(const float* __restrict__ Wv, uint32_t* __restrict__ wvbf) {
    int i = blockIdx.x * 256 + threadIdx.x;
    wvbf[i] = fpack_bf2(Wv[2 * i], Wv[2 * i + 1]);
}

// ---------------- K1a: q/k projection (tf32, 3-stage cp.async) ------------------
__global__ void __launch_bounds__(256, 2)
qk_gemm_mma(const float* __restrict__ x,
            const float* __restrict__ Wq, const float* __restrict__ bq,
            const float* __restrict__ Wk, const float* __restrict__ bk) {
    extern __shared__ uint32_t sm[];
    const uint32_t sb = (uint32_t)__cvta_generic_to_shared(sm);

    const int tid  = threadIdx.x;
    const int lane = tid & 31, wid = tid >> 5;
    const int grp  = lane >> 2, tig = lane & 3;
    const int wm   = (wid >> 1) * 32;
    const int wn   = (wid & 1) * 64;
    const int n0   = blockIdx.x * 128;
    const int b    = blockIdx.y;

    const float* xb = x + (size_t)b * CC * NPIX;

    float acc[2][8][4] = {};

    auto cp_tile = [&](int k0, int buf) {
        uint32_t A = sb + (buf * QK_BUF_W) * 4;
        uint32_t B = A + QK_A_W * 4;
        #pragma unroll
        for (int l = 0; l < 4; l++) {
            int idx = l * 256 + tid;
            int m = idx >> 3, kq = idx & 7;
            const float* src = (m < 64) ? Wq + (size_t)m * CC : Wk + (size_t)(m - 64) * CC;
            cp_async16(A + (m * PA + kq * 4) * 4, src + k0 + kq * 4);
        }
        #pragma unroll
        for (int l = 0; l < 4; l++) {
            int idx = l * 256 + tid;
            int kk = idx >> 5, nq = idx & 31;
            cp_async16(B + (kk * PB + nq * 4) * 4,
                       xb + (size_t)(k0 + kk) * NPIX + n0 + nq * 4);
        }
        CP_COMMIT();
    };

    cp_tile(0, 0);
    cp_tile(32, 1);

    for (int i = 0; i < 16; i++) {
        if (i < 15) CP_WAIT1(); else CP_WAIT0();
        __syncthreads();
        if (i < 14) cp_tile((i + 2) * 32, (i + 2) % 3);

        const uint32_t* A = sm + (i % 3) * QK_BUF_W;
        const uint32_t* B = A + QK_A_W;
        #pragma unroll
        for (int kk = 0; kk < 4; kk++) {
            const int kr = kk * 8 + tig;
            uint32_t a[2][4], bf[8][2];
            #pragma unroll
            for (int ii = 0; ii < 2; ii++) {
                a[ii][0] = A[(wm + ii * 16 + grp    ) * PA + kr];
                a[ii][1] = A[(wm + ii * 16 + grp + 8) * PA + kr];
                a[ii][2] = A[(wm + ii * 16 + grp    ) * PA + kr + 4];
                a[ii][3] = A[(wm + ii * 16 + grp + 8) * PA + kr + 4];
            }
            #pragma unroll
            for (int j = 0; j < 8; j++) {
                bf[j][0] = B[kr * PB       + wn + j * 8 + grp];
                bf[j][1] = B[(kr + 4) * PB + wn + j * 8 + grp];
            }
            #pragma unroll
            for (int ii = 0; ii < 2; ii++)
                #pragma unroll
                for (int j = 0; j < 8; j++)
                    mma_tf32(acc[ii][j], a[ii], bf[j]);
        }
    }

    #pragma unroll
    for (int i = 0; i < 2; i++) {
        #pragma unroll
        for (int r = 0; r < 2; r++) {
            int m = wm + i * 16 + grp + r * 8;
            float bias; float* dst;
            if (m < 64) { bias = bq[m];      dst = g_q + ((size_t)b * C8 + m) * SS; }
            else        { bias = bk[m - 64]; dst = g_k + ((size_t)b * C8 + m - 64) * SS; }
            float* row = dst + n0 + wn + tig * 2;
            #pragma unroll
            for (int j = 0; j < 8; j++) {
                float2 o;
                o.x = acc[i][j][r * 2 + 0] + bias;
                o.y = acc[i][j][r * 2 + 1] + bias;
                *reinterpret_cast<float2*>(row + j * 8) = o;
            }
        }
    }
}

// ---------------- K1b: v projection, M=512 x N=64, bf16, 3-stage ----------------
__global__ void __launch_bounds__(512, 1)
v_gemm_bf16(const float* __restrict__ x, const uint32_t* __restrict__ wvbf,
            const float* __restrict__ bv) {
    extern __shared__ uint32_t sm[];
    const uint32_t sb = (uint32_t)__cvta_generic_to_shared(sm);

    const int tid  = threadIdx.x;
    const int lane = tid & 31, wid = tid >> 5;
    const int grp  = lane >> 2, tig = lane & 3;
    const int wm   = wid * 32;
    const int n0   = blockIdx.x * 64;
    const int b    = blockIdx.y;
    const int bkp  = tid >> 4;
    const int bg   = tid & 15;

    const float* xb = x + (size_t)b * CC * NPIX;

    float acc[2][8][4] = {};
    float4 pxlo, pxhi;

    auto cpA_tile = [&](int k0, int buf) {
        uint32_t A = sb + (buf * VG_BUF_W) * 4;
        const int kw0 = k0 >> 1;
        #pragma unroll
        for (int l = 0; l < 4; l++) {
            int idx = l * 512 + tid;
            int m = idx >> 2, q = idx & 3;
            cp_async16(A + (m * RW + q * 4) * 4,
                       wvbf + (size_t)m * (CC / 2) + kw0 + q * 4);
        }
        CP_COMMIT();
    };
    auto ldgB = [&](int k0) {
        if (tid < 256) {
            const float* p0 = xb + (size_t)(k0 + 2 * bkp) * NPIX + n0 + bg * 4;
            pxlo = *reinterpret_cast<const float4*>(p0);
            pxhi = *reinterpret_cast<const float4*>(p0 + NPIX);
        }
    };
    auto stsB = [&](int buf) {
        uint32_t* B = sm + buf * VG_BUF_W + VG_A_W;
        if (tid < 256) {
            B[(bg * 4 + 0) * RW + bkp] = fpack_bf2(pxlo.x, pxhi.x);
            B[(bg * 4 + 1) * RW + bkp] = fpack_bf2(pxlo.y, pxhi.y);
            B[(bg * 4 + 2) * RW + bkp] = fpack_bf2(pxlo.z, pxhi.z);
            B[(bg * 4 + 3) * RW + bkp] = fpack_bf2(pxlo.w, pxhi.w);
        }
    };

    // prologue: tiles 0 and 1 (B via registers, A via cp.async)
    cpA_tile(0, 0);
    ldgB(0); stsB(0);
    cpA_tile(32, 1);
    ldgB(32); stsB(1);

    for (int i = 0; i < 16; i++) {
        if (i < 14) ldgB((i + 2) * 32);          // register load, no smem hazard
        if (i < 15) CP_WAIT1(); else CP_WAIT0();
        __syncthreads();
        if (i < 14) { stsB((i + 2) % 3); cpA_tile((i + 2) * 32, (i + 2) % 3); }

        const uint32_t* A = sm + (i % 3) * VG_BUF_W;
        const uint32_t* B = A + VG_A_W;
        #pragma unroll
        for (int s = 0; s < 2; s++) {
            uint32_t a[2][4], bf[8][2];
            #pragma unroll
            for (int ii = 0; ii < 2; ii++) {
                a[ii][0] = A[(wm + ii * 16 + grp    ) * RW + s * 8 + tig];
                a[ii][1] = A[(wm + ii * 16 + grp + 8) * RW + s * 8 + tig];
                a[ii][2] = A[(wm + ii * 16 + grp    ) * RW + s * 8 + tig + 4];
                a[ii][3] = A[(wm + ii * 16 + grp + 8) * RW + s * 8 + tig + 4];
            }
            #pragma unroll
            for (int j = 0; j < 8; j++) {
                bf[j][0] = B[(j * 8 + grp) * RW + s * 8 + tig];
                bf[j][1] = B[(j * 8 + grp) * RW + s * 8 + tig + 4];
            }
            #pragma unroll
            for (int ii = 0; ii < 2; ii++)
                #pragma unroll
                for (int j = 0; j < 8; j++)
                    mma_bf16(acc[ii][j], a[ii], bf[j]);
        }
        // note: stsB for i+2 happens after the sync at iteration i, and its
        // buffer (i+2)%3 was last read by MMA at iteration i-1 (all warps past
        // that point due to this iteration's sync) -> race-free.
        if (i < 14) { /* B store already done above, before MMA */ }
    }

    #pragma unroll
    for (int i = 0; i < 2; i++) {
        #pragma unroll
        for (int r = 0; r < 2; r++) {
            int m = wm + i * 16 + grp + r * 8;
            float bias = bv[m];
            uint32_t* row = g_vbf + ((size_t)b * CC + m) * SSW + (n0 >> 1) + tig;
            #pragma unroll
            for (int j = 0; j < 8; j++)
                row[j * 4] = fpack_bf2(acc[i][j][r * 2 + 0] + bias,
                                       acc[i][j][r * 2 + 1] + bias);
        }
    }
}

// ---------------- K2a: fp32 plane transpose (q, k) ------------------------------
__global__ void transpose_wh(float* __restrict__ dst, const float* __restrict__ src) {
    __shared__ float t[32][33];
    const size_t base = (size_t)blockIdx.z * SS;
    const int x0 = blockIdx.x * 32, y0 = blockIdx.y * 32;
    const int tx = threadIdx.x, ty = threadIdx.y;
    #pragma unroll
    for (int i = 0; i < 32; i += 8)
        t[ty + i][tx] = src[base + (size_t)(y0 + ty + i) * S + x0 + tx];
    __syncthreads();
    #pragma unroll
    for (int i = 0; i < 32; i += 8)
        dst[base + (size_t)(x0 + ty + i) * S + y0 + tx] = t[tx][ty + i];
}

// ---------------- K2b: bf16 plane transpose (v) ---------------------------------
__global__ void transpose_wh_bf16(uint32_t* __restrict__ dst, const uint32_t* __restrict__ src) {
    __shared__ unsigned short t[64][66];
    const size_t base = (size_t)blockIdx.z * SSW;
    const int w0 = blockIdx.x * 64, h0 = blockIdx.y * 64;
    const int tx = threadIdx.x, ty = threadIdx.y;
    #pragma unroll
    for (int i = 0; i < 64; i += 8) {
        int w = w0 + ty + i;
        uint32_t word = src[base + (size_t)w * 64 + (h0 >> 1) + tx];
        t[tx * 2 + 0][ty + i] = (unsigned short)(word & 0xffff);
        t[tx * 2 + 1][ty + i] = (unsigned short)(word >> 16);
    }
    __syncthreads();
    #pragma unroll
    for (int i = 0; i < 64; i += 8) {
        int h = h0 + ty + i;
        uint32_t word = *reinterpret_cast<const uint32_t*>(&t[ty + i][tx * 2]);
        dst[base + (size_t)h * 64 + (w0 >> 1) + tx] = word;
    }
}

// ---------------- K3: logits + unnormalized exp (bf16 out) + (m,s) stats -------
__global__ void __launch_bounds__(256, 2)
attn_logits_mma(const float* __restrict__ qsrc, const float* __restrict__ ksrc,
                uint32_t* __restrict__ attw, float2* __restrict__ stat, int is_col) {
    extern __shared__ uint32_t sm[];
    uint32_t* Qs = sm;
    uint32_t* Ks = sm + LG_Q_W;
    __shared__ float redm[128][2];
    __shared__ float reds[128][2];

    const int p = blockIdx.x;
    const int b = blockIdx.y;
    const int tid  = threadIdx.x;
    const int lane = tid & 31, wid = tid >> 5;
    const int grp  = lane >> 2, tig = lane & 3;
    const int wm   = (wid >> 1) * 32;
    const int wc   = wid & 1;
    const int wn   = wc * 64;

    const size_t qbase = (size_t)b * C8 * SS + (size_t)p * S;

    #pragma unroll
    for (int l = 0; l < 8; l++) {
        int idx = l * 256 + tid;
        int cc  = idx >> 5;
        int nq  = idx & 31;
        size_t g = qbase + (size_t)cc * SS + nq * 4;
        *reinterpret_cast<uint4*>(Qs + cc * PB + nq * 4) =
            tf32x4(*reinterpret_cast<const float4*>(qsrc + g));
        *reinterpret_cast<uint4*>(Ks + cc * PB + nq * 4) =
            tf32x4(*reinterpret_cast<const float4*>(ksrc + g));
    }
    __syncthreads();

    float acc[2][8][4] = {};
    #pragma unroll
    for (int kk = 0; kk < 8; kk++) {
        const int kr = kk * 8 + tig;
        uint32_t a[2][4], bf[8][2];
        #pragma unroll
        for (int i = 0; i < 2; i++) {
            a[i][0] = Qs[kr * PB       + wm + i * 16 + grp];
            a[i][1] = Qs[kr * PB       + wm + i * 16 + grp + 8];
            a[i][2] = Qs[(kr + 4) * PB + wm + i * 16 + grp];
            a[i][3] = Qs[(kr + 4) * PB + wm + i * 16 + grp + 8];
        }
        #pragma unroll
        for (int j = 0; j < 8; j++) {
            bf[j][0] = Ks[kr * PB       + wn + j * 8 + grp];
            bf[j][1] = Ks[(kr + 4) * PB + wn + j * 8 + grp];
        }
        #pragma unroll
        for (int i = 0; i < 2; i++)
            #pragma unroll
            for (int j = 0; j < 8; j++)
                mma_tf32(acc[i][j], a[i], bf[j]);
    }

    if (is_col) {
        #pragma unroll
        for (int i = 0; i < 2; i++)
            #pragma unroll
            for (int r = 0; r < 2; r++) {
                int rr = wm + i * 16 + grp + r * 8;
                #pragma unroll
                for (int j = 0; j < 8; j++) {
                    int u = wn + j * 8 + tig * 2;
                    if (rr == u)     acc[i][j][r * 2 + 0] = NEG_INF_F;
                    if (rr == u + 1) acc[i][j][r * 2 + 1] = NEG_INF_F;
                }
            }
    }

    float mloc[2][2];
    #pragma unroll
    for (int i = 0; i < 2; i++)
        #pragma unroll
        for (int r = 0; r < 2; r++) {
            float ml = -3.4e38f;
            #pragma unroll
            for (int j = 0; j < 8; j++) {
                ml = fmaxf(ml, acc[i][j][r * 2 + 0]);
                ml = fmaxf(ml, acc[i][j][r * 2 + 1]);
            }
            ml = fmaxf(ml, __shfl_xor_sync(0xffffffff, ml, 1));
            ml = fmaxf(ml, __shfl_xor_sync(0xffffffff, ml, 2));
            mloc[i][r] = ml;
        }
    if (tig == 0) {
        #pragma unroll
        for (int i = 0; i < 2; i++)
            #pragma unroll
            for (int r = 0; r < 2; r++)
                redm[wm + i * 16 + grp + r * 8][wc] = mloc[i][r];
    }
    __syncthreads();

    float mrow[2][2], sloc[2][2];
    #pragma unroll
    for (int i = 0; i < 2; i++)
        #pragma unroll
        for (int r = 0; r < 2; r++) {
            int rr = wm + i * 16 + grp + r * 8;
            float m = fmaxf(redm[rr][0], redm[rr][1]);
            mrow[i][r] = m;
            float sl = 0.f;
            #pragma unroll
            for (int j = 0; j < 8; j++) {
                float e0 = __expf(acc[i][j][r * 2 + 0] - m);
                float e1 = __expf(acc[i][j][r * 2 + 1] - m);
                acc[i][j][r * 2 + 0] = e0;
                acc[i][j][r * 2 + 1] = e1;
                sl += e0 + e1;
            }
            sl += __shfl_xor_sync(0xffffffff, sl, 1);
            sl += __shfl_xor_sync(0xffffffff, sl, 2);
            sloc[i][r] = sl;
        }
    if (tig == 0) {
        #pragma unroll
        for (int i = 0; i < 2; i++)
            #pragma unroll
            for (int r = 0; r < 2; r++)
                reds[wm + i * 16 + grp + r * 8][wc] = sloc[i][r];
    }
    __syncthreads();

    if (tig == 0 && wc == 0) {
        #pragma unroll
        for (int i = 0; i < 2; i++)
            #pragma unroll
            for (int r = 0; r < 2; r++) {
                int rr = wm + i * 16 + grp + r * 8;
                stat[(size_t)b * SS + (size_t)p * S + rr] =
                    make_float2(mrow[i][r], reds[rr][0] + reds[rr][1]);
            }
    }

    const size_t obase_w  = ((size_t)b * SS * 256 +
                            (is_col ? (size_t)p * 256 : (size_t)p * S * 256 + 128)) >> 1;
    const size_t rstride_w = (is_col ? (size_t)S * 256 : 256) >> 1;
    #pragma unroll
    for (int i = 0; i < 2; i++) {
        #pragma unroll
        for (int r = 0; r < 2; r++) {
            int rr = wm + i * 16 + grp + r * 8;
            uint32_t* row = attw + obase_w + (size_t)rr * rstride_w + ((wn >> 1) + tig);
            #pragma unroll
            for (int j = 0; j < 8; j++)
                row[j * 4] = fpack_bf2(acc[i][j][r * 2 + 0], acc[i][j][r * 2 + 1]);
        }
    }
}

// ---------------- K4: combine halves -> per-pixel normalization scales ---------
__global__ void softmax_combine(const float2* __restrict__ sc, const float2* __restrict__ sr,
                                float* __restrict__ scol, float* __restrict__ srow) {
    const int b = blockIdx.y;
    const int t = blockIdx.x * 256 + threadIdx.x;
    const int w = t & (S - 1), h = t >> 7;
    float2 c = sc[(size_t)b * SS + t];
    float2 r = sr[(size_t)b * SS + w * S + h];
    float m  = fmaxf(c.x, r.x);
    float ec = __expf(c.x - m), er = __expf(r.x - m);
    float inv = 1.f / (c.y * ec + r.y * er);
    scol[(size_t)b * SS + t]         = ec * inv;
    srow[(size_t)b * SS + w * S + h] = er * inv;
}

// ---------------- K5: attention @ V, bf16, M=256, 3-stage cp.async --------------
__global__ void __launch_bounds__(512, 1)
attn_av_mma(const uint32_t* __restrict__ vsrc, const uint32_t* __restrict__ attw,
            float* __restrict__ dstf, uint32_t* __restrict__ dstw,
            const float* __restrict__ gammap,
            const float* __restrict__ xres, const float* __restrict__ scale,
            int is_col) {
    extern __shared__ uint32_t sm[];
    const uint32_t sb = (uint32_t)__cvta_generic_to_shared(sm);

    const int ct = blockIdx.x;
    const int p  = blockIdx.y;
    const int b  = blockIdx.z;
    const int tid  = threadIdx.x;
    const int lane = tid & 31, wid = tid >> 5;
    const int grp  = lane >> 2, tig = lane & 3;
    const int wm   = (wid >> 1) * 32;
    const int wn   = (wid & 1) * 64;

    const size_t vbase_f = (size_t)(b * CC + ct * 256) * SS + (size_t)p * S;
    const size_t vbase_w = vbase_f >> 1;
    const size_t abase_w = ((size_t)b * SS * 256 +
                           (is_col ? (size_t)p * 256 : (size_t)p * S * 256 + 128)) >> 1;
    const size_t aq_w    = (is_col ? (size_t)S * 256 : 256) >> 1;

    const float gm = gammap[0];

    float acc[2][8][4] = {};

    auto cp_tile = [&](int u0, int buf) {
        uint32_t V = sb + (buf * BF_BUF_W) * 4;
        uint32_t T = V + BF_A_W * 4;
        #pragma unroll
        for (int l = 0; l < 2; l++) {
            int idx = l * 512 + tid;
            int cp = idx >> 2, u4 = idx & 3;
            cp_async16(V + (cp * RW + u4 * 4) * 4,
                       vsrc + vbase_w + (size_t)cp * SSW + (u0 >> 1) + u4 * 4);
        }
        {
            int qp = tid >> 2, u4 = tid & 3;
            cp_async16(T + (qp * RW + u4 * 4) * 4,
                       attw + abase_w + (size_t)qp * aq_w + (u0 >> 1) + u4 * 4);
        }
        CP_COMMIT();
    };

    cp_tile(0, 0);
    cp_tile(32, 1);

    for (int i = 0; i < 4; i++) {
        if (i < 3) CP_WAIT1(); else CP_WAIT0();
        __syncthreads();
        if (i < 2) cp_tile((i + 2) * 32, (i + 2) % 3);

        const uint32_t* V = sm + (i % 3) * BF_BUF_W;
        const uint32_t* T = V + BF_A_W;
        #pragma unroll
        for (int s = 0; s < 2; s++) {
            uint32_t a[2][4], bf[8][2];
            #pragma unroll
            for (int ii = 0; ii < 2; ii++) {
                a[ii][0] = V[(wm + ii * 16 + grp    ) * RW + s * 8 + tig];
                a[ii][1] = V[(wm + ii * 16 + grp + 8) * RW + s * 8 + tig];
                a[ii][2] = V[(wm + ii * 16 + grp    ) * RW + s * 8 + tig + 4];
                a[ii][3] = V[(wm + ii * 16 + grp + 8) * RW + s * 8 + tig + 4];
            }
            #pragma unroll
            for (int j = 0; j < 8; j++) {
                bf[j][0] = T[(wn + j * 8 + grp) * RW + s * 8 + tig];
                bf[j][1] = T[(wn + j * 8 + grp) * RW + s * 8 + tig + 4];
            }
            #pragma unroll
            for (int ii = 0; ii < 2; ii++)
                #pragma unroll
                for (int j = 0; j < 8; j++)
                    mma_bf16(acc[ii][j], a[ii], bf[j]);
        }
    }

    const float* scl = scale + (size_t)b * SS + (size_t)p * S;
    float2 scv[8];
    #pragma unroll
    for (int j = 0; j < 8; j++)
        scv[j] = *reinterpret_cast<const float2*>(scl + wn + j * 8 + tig * 2);

    #pragma unroll
    for (int i = 0; i < 2; i++) {
        #pragma unroll
        for (int r = 0; r < 2; r++) {
            int cl = wm + i * 16 + grp + r * 8;
            size_t off = vbase_f + (size_t)cl * SS + wn + tig * 2;
            if (is_col) {
                uint32_t* roww = dstw + (off >> 1);
                #pragma unroll
                for (int j = 0; j < 8; j++)
                    roww[j * 4] = fpack_bf2(gm * scv[j].x * acc[i][j][r * 2 + 0],
                                            gm * scv[j].y * acc[i][j][r * 2 + 1]);
            } else {
                float* row = dstf + off;
                const float* xrow = xres + off;
                #pragma unroll
                for (int j = 0; j < 8; j++) {
                    float2 xr = *reinterpret_cast<const float2*>(xrow + j * 8);
                    float2 o;
                    o.x = gm * scv[j].x * acc[i][j][r * 2 + 0] + xr.x;
                    o.y = gm * scv[j].y * acc[i][j][r * 2 + 1] + xr.y;
                    *reinterpret_cast<float2*>(row + j * 8) = o;
                }
            }
        }
    }
}

// ---------------- K6: out += transpose(ocolT bf16) -----------------------------
__global__ void final_combine(const uint32_t* __restrict__ ocolT, float* __restrict__ out) {
    __shared__ unsigned short t[64][66];
    const size_t base_w = (size_t)blockIdx.z * SSW;
    const size_t base_f = (size_t)blockIdx.z * SS;
    const int w0 = blockIdx.x * 64, h0 = blockIdx.y * 64;
    const int tx = threadIdx.x, ty = threadIdx.y;

    #pragma unroll
    for (int i = 0; i < 64; i += 8) {
        int h = h0 + ty + i;
        uint32_t word = ocolT[base_w + (size_t)h * 64 + (w0 >> 1) + tx];
        t[tx * 2 + 0][ty + i] = (unsigned short)(word & 0xffff);
        t[tx * 2 + 1][ty + i] = (unsigned short)(word >> 16);
    }
    __syncthreads();
    #pragma unroll
    for (int i = 0; i < 64; i += 8) {
        int w = w0 + ty + i;
        uint32_t word = *reinterpret_cast<const uint32_t*>(&t[ty + i][tx * 2]);
        __nv_bfloat162 bf = *reinterpret_cast<__nv_bfloat162*>(&word);
        float* o = out + base_f + (size_t)w * S + h0 + tx * 2;
        float2 cur = *reinterpret_cast<float2*>(o);
        cur.x += __bfloat162float(bf.x);
        cur.y += __bfloat162float(bf.y);
        *reinterpret_cast<float2*>(o) = cur;
    }
}

// ---------------- launch ------------------------------------------------------
extern "C" void kernel_launch(void* const* d_in, const int* in_sizes, int n_in,
                              void* d_out, int out_size) {
    const float* x     = (const float*)d_in[0];
    const float* Wq    = (const float*)d_in[1];
    const float* bq    = (const float*)d_in[2];
    const float* Wk    = (const float*)d_in[3];
    const float* bk    = (const float*)d_in[4];
    const float* Wv    = (const float*)d_in[5];
    const float* bv    = (const float*)d_in[6];
    const float* gamma = (const float*)d_in[7];
    float* out = (float*)d_out;

    float *q, *k, *qT, *kT, *scol, *srow;
    uint32_t *wvbf, *vbf, *vTbf, *att, *ocolT;
    float2 *stc, *str;
    cudaGetSymbolAddress((void**)&q,     g_q);
    cudaGetSymbolAddress((void**)&k,     g_k);
    cudaGetSymbolAddress((void**)&qT,    g_qT);
    cudaGetSymbolAddress((void**)&kT,    g_kT);
    cudaGetSymbolAddress((void**)&wvbf,  g_wvbf);
    cudaGetSymbolAddress((void**)&vbf,   g_vbf);
    cudaGetSymbolAddress((void**)&vTbf,  g_vTbf);
    cudaGetSymbolAddress((void**)&att,   g_att);
    cudaGetSymbolAddress((void**)&ocolT, g_ocolTbf);
    cudaGetSymbolAddress((void**)&stc,   g_stat_col);
    cudaGetSymbolAddress((void**)&str,   g_stat_row);
    cudaGetSymbolAddress((void**)&scol,  g_scale_col);
    cudaGetSymbolAddress((void**)&srow,  g_scale_row);

    static cudaStream_t s1 = nullptr;
    static cudaEvent_t evFork = nullptr, evV = nullptr, evT = nullptr,
                       evSoft = nullptr, evCol = nullptr;
    static bool init_done = false;
    if (!init_done) {
        cudaStreamCreateWithFlags(&s1, cudaStreamNonBlocking);
        cudaEventCreateWithFlags(&evFork, cudaEventDisableTiming);
        cudaEventCreateWithFlags(&evV,    cudaEventDisableTiming);
        cudaEventCreateWithFlags(&evT,    cudaEventDisableTiming);
        cudaEventCreateWithFlags(&evSoft, cudaEventDisableTiming);
        cudaEventCreateWithFlags(&evCol,  cudaEventDisableTiming);
        cudaFuncSetAttribute(qk_gemm_mma,     cudaFuncAttributeMaxDynamicSharedMemorySize, QK_SMEM);
        cudaFuncSetAttribute(v_gemm_bf16,     cudaFuncAttributeMaxDynamicSharedMemorySize, VG_SMEM);
        cudaFuncSetAttribute(attn_logits_mma, cudaFuncAttributeMaxDynamicSharedMemorySize, LOGITS_SMEM);
        cudaFuncSetAttribute(attn_av_mma,     cudaFuncAttributeMaxDynamicSharedMemorySize, BF_SMEM);
        init_done = true;
    }

    // fork: v chain on s1 (pack_wv -> v_gemm -> vT transpose)
    cudaEventRecord(evFork, 0);
    cudaStreamWaitEvent(s1, evFork, 0);
    pack_wv<<<512, 256, 0, s1>>>(Wv, wvbf);
    v_gemm_bf16<<<dim3(NPIX / 64, BB), 512, VG_SMEM, s1>>>(x, wvbf, bv);
    cudaEventRecord(evV, s1);
    transpose_wh_bf16<<<dim3(2, 2, BB * CC), dim3(32, 8), 0, s1>>>(vTbf, vbf);
    cudaEventRecord(evT, s1);

    // qk chain on stream 0
    qk_gemm_mma<<<dim3(NPIX / 128, BB), 256, QK_SMEM>>>(x, Wq, bq, Wk, bk);
    transpose_wh<<<dim3(4, 4, BB * C8), dim3(32, 8)>>>(qT, q);
    transpose_wh<<<dim3(4, 4, BB * C8), dim3(32, 8)>>>(kT, k);
    attn_logits_mma<<<dim3(S, BB), 256, LOGITS_SMEM>>>(qT, kT, att, stc, 1);
    attn_logits_mma<<<dim3(S, BB), 256, LOGITS_SMEM>>>(q,  k,  att, str, 0);
    softmax_combine<<<dim3(SS / 256, BB), 256>>>(stc, str, scol, srow);
    cudaEventRecord(evSoft, 0);

    // av-row on stream 0 (needs vbf); av-col on s1 (needs vTbf + att/scol)
    cudaStreamWaitEvent(0, evV, 0);
    attn_av_mma<<<dim3(2, S, BB), 512, BF_SMEM>>>(vbf, att, out, nullptr, gamma, x, srow, 0);
    cudaStreamWaitEvent(s1, evSoft, 0);
    attn_av_mma<<<dim3(2, S, BB), 512, BF_SMEM, s1>>>(vTbf, att, nullptr, ocolT, gamma, nullptr, scol, 1);
    cudaEventRecord(evCol, s1);

    // join: out += ocolT^T
    cudaStreamWaitEvent(0, evCol, 0);
    final_combine<<<dim3(2, 2, BB * CC), dim3(32, 8)>>>(ocolT, out);
}

// round 14
// speedup vs baseline: 1.7298x; 1.0448x over previous
#include <cuda_runtime.h>
#include <cuda_bf16.h>
#include <cstdint>

#define BB 8
#define CC 512
#define C8 64
#define S  128
#define SS (S*S)
#define NPIX (SS)
#define SSW (SS/2)
#define NEG_INF_F (-1000000000.0f)

// ---------------- scratch buffers (device globals; no allocation) ----------------
__device__ float    g_q    [BB * C8 * SS];
__device__ float    g_k    [BB * C8 * SS];
__device__ float    g_qT   [BB * C8 * SS];
__device__ float    g_kT   [BB * C8 * SS];
__device__ uint32_t g_wvbf [CC * CC / 2];
__device__ uint32_t g_vbf  [BB * CC * SSW];
__device__ uint32_t g_vTbf [BB * CC * SSW];
__device__ uint32_t g_att  [BB * SS * S];
__device__ uint32_t g_ocolTbf[BB * CC * SSW];   // o_col^T bf16 [c][h][w]
__device__ uint32_t g_orowbf [BB * CC * SSW];   // o_row   bf16 [c][w][h]
__device__ float2   g_stat_col[BB * SS];
__device__ float2   g_stat_row[BB * SS];
__device__ float    g_scale_col[BB * SS];
__device__ float    g_scale_row[BB * SS];

// ---------------- helpers --------------------------------------------------------
__device__ __forceinline__ uint32_t f2tf32(float f) {
    uint32_t u;
    asm("cvt.rn.tf32.f32 %0, %1;" : "=r"(u) : "f"(f));
    return u;
}
__device__ __forceinline__ uint4 tf32x4(float4 v) {
    return make_uint4(f2tf32(v.x), f2tf32(v.y), f2tf32(v.z), f2tf32(v.w));
}
__device__ __forceinline__ void mma_tf32(float c[4], const uint32_t a[4], const uint32_t b[2]) {
    asm volatile(
        "mma.sync.aligned.m16n8k8.row.col.f32.tf32.tf32.f32 "
        "{%0,%1,%2,%3}, {%4,%5,%6,%7}, {%8,%9}, {%0,%1,%2,%3};"
        : "+f"(c[0]), "+f"(c[1]), "+f"(c[2]), "+f"(c[3])
        : "r"(a[0]), "r"(a[1]), "r"(a[2]), "r"(a[3]), "r"(b[0]), "r"(b[1]));
}
__device__ __forceinline__ void mma_bf16(float c[4], const uint32_t a[4], const uint32_t b[2]) {
    asm volatile(
        "mma.sync.aligned.m16n8k16.row.col.f32.bf16.bf16.f32 "
        "{%0,%1,%2,%3}, {%4,%5,%6,%7}, {%8,%9}, {%0,%1,%2,%3};"
        : "+f"(c[0]), "+f"(c[1]), "+f"(c[2]), "+f"(c[3])
        : "r"(a[0]), "r"(a[1]), "r"(a[2]), "r"(a[3]), "r"(b[0]), "r"(b[1]));
}
__device__ __forceinline__ uint32_t fpack_bf2(float lo, float hi) {
    __nv_bfloat162 h = __floats2bfloat162_rn(lo, hi);
    return *reinterpret_cast<uint32_t*>(&h);
}
__device__ __forceinline__ void cp_async16(uint32_t saddr, const void* gptr) {
    asm volatile("cp.async.cg.shared.global [%0], [%1], 16;"
                 :: "r"(saddr), "l"(gptr) : "memory");
}
#define CP_COMMIT() asm volatile("cp.async.commit_group;" ::: "memory")
#define CP_WAIT0()  asm volatile("cp.async.wait_group 0;" ::: "memory")
#define CP_WAIT1()  asm volatile("cp.async.wait_group 1;" ::: "memory")

// SMEM geometry (32-bit words)
#define PA   36
#define PB   136
#define QK_A_W   (128 * PA)
#define QK_B_W   (32 * PB)
#define QK_BUF_W (QK_A_W + QK_B_W)
#define QK_SMEM  (3 * QK_BUF_W * 4)
#define LG_Q_W    (64 * PB)
#define LOGITS_SMEM (2 * LG_Q_W * 4)
#define RW        20
#define BF_A_W    (256 * RW)
#define BF_B_W    (128 * RW)
#define BF_BUF_W  (BF_A_W + BF_B_W)
#define BF_SMEM   (3 * BF_BUF_W * 4)
#define VG_A_W    (512 * RW)
#define VG_B_W    (64 * RW)
#define VG_BUF_W  (VG_A_W + VG_B_W)
#define VG_SMEM   (3 * VG_BUF_W * 4)

// ---------------- K0: pack Wv to bf16 k-pair words ------------------------------
__global__ void pack_wv(const float* __restrict__ Wv, uint32_t* __restrict__ wvbf) {
    int i = blockIdx.x * 256 + threadIdx.x;
    wvbf[i] = fpack_bf2(Wv[2 * i], Wv[2 * i + 1]);
}

// ---------------- K1a: q/k projection (tf32, 3-stage cp.async) ------------------
__global__ void __launch_bounds__(256, 2)
qk_gemm_mma(const float* __restrict__ x,
            const float* __restrict__ Wq, const float* __restrict__ bq,
            const float* __restrict__ Wk, const float* __restrict__ bk) {
    extern __shared__ uint32_t sm[];
    const uint32_t sb = (uint32_t)__cvta_generic_to_shared(sm);

    const int tid  = threadIdx.x;
    const int lane = tid & 31, wid = tid >> 5;
    const int grp  = lane >> 2, tig = lane & 3;
    const int wm   = (wid >> 1) * 32;
    const int wn   = (wid & 1) * 64;
    const int n0   = blockIdx.x * 128;
    const int b    = blockIdx.y;

    const float* xb = x + (size_t)b * CC * NPIX;

    float acc[2][8][4] = {};

    auto cp_tile = [&](int k0, int buf) {
        uint32_t A = sb + (buf * QK_BUF_W) * 4;
        uint32_t B = A + QK_A_W * 4;
        #pragma unroll
        for (int l = 0; l < 4; l++) {
            int idx = l * 256 + tid;
            int m = idx >> 3, kq = idx & 7;
            const float* src = (m < 64) ? Wq + (size_t)m * CC : Wk + (size_t)(m - 64) * CC;
            cp_async16(A + (m * PA + kq * 4) * 4, src + k0 + kq * 4);
        }
        #pragma unroll
        for (int l = 0; l < 4; l++) {
            int idx = l * 256 + tid;
            int kk = idx >> 5, nq = idx & 31;
            cp_async16(B + (kk * PB + nq * 4) * 4,
                       xb + (size_t)(k0 + kk) * NPIX + n0 + nq * 4);
        }
        CP_COMMIT();
    };

    cp_tile(0, 0);
    cp_tile(32, 1);

    for (int i = 0; i < 16; i++) {
        if (i < 15) CP_WAIT1(); else CP_WAIT0();
        __syncthreads();
        if (i < 14) cp_tile((i + 2) * 32, (i + 2) % 3);

        const uint32_t* A = sm + (i % 3) * QK_BUF_W;
        const uint32_t* B = A + QK_A_W;
        #pragma unroll
        for (int kk = 0; kk < 4; kk++) {
            const int kr = kk * 8 + tig;
            uint32_t a[2][4], bf[8][2];
            #pragma unroll
            for (int ii = 0; ii < 2; ii++) {
                a[ii][0] = A[(wm + ii * 16 + grp    ) * PA + kr];
                a[ii][1] = A[(wm + ii * 16 + grp + 8) * PA + kr];
                a[ii][2] = A[(wm + ii * 16 + grp    ) * PA + kr + 4];
                a[ii][3] = A[(wm + ii * 16 + grp + 8) * PA + kr + 4];
            }
            #pragma unroll
            for (int j = 0; j < 8; j++) {
                bf[j][0] = B[kr * PB       + wn + j * 8 + grp];
                bf[j][1] = B[(kr + 4) * PB + wn + j * 8 + grp];
            }
            #pragma unroll
            for (int ii = 0; ii < 2; ii++)
                #pragma unroll
                for (int j = 0; j < 8; j++)
                    mma_tf32(acc[ii][j], a[ii], bf[j]);
        }
    }

    #pragma unroll
    for (int i = 0; i < 2; i++) {
        #pragma unroll
        for (int r = 0; r < 2; r++) {
            int m = wm + i * 16 + grp + r * 8;
            float bias; float* dst;
            if (m < 64) { bias = bq[m];      dst = g_q + ((size_t)b * C8 + m) * SS; }
            else        { bias = bk[m - 64]; dst = g_k + ((size_t)b * C8 + m - 64) * SS; }
            float* row = dst + n0 + wn + tig * 2;
            #pragma unroll
            for (int j = 0; j < 8; j++) {
                float2 o;
                o.x = acc[i][j][r * 2 + 0] + bias;
                o.y = acc[i][j][r * 2 + 1] + bias;
                *reinterpret_cast<float2*>(row + j * 8) = o;
            }
        }
    }
}

// ---------------- K1b: v projection, M=512 x N=64, bf16, 3-stage ----------------
__global__ void __launch_bounds__(512, 1)
v_gemm_bf16(const float* __restrict__ x, const uint32_t* __restrict__ wvbf,
            const float* __restrict__ bv) {
    extern __shared__ uint32_t sm[];
    const uint32_t sb = (uint32_t)__cvta_generic_to_shared(sm);

    const int tid  = threadIdx.x;
    const int lane = tid & 31, wid = tid >> 5;
    const int grp  = lane >> 2, tig = lane & 3;
    const int wm   = wid * 32;
    const int n0   = blockIdx.x * 64;
    const int b    = blockIdx.y;
    const int bkp  = tid >> 4;
    const int bg   = tid & 15;

    const float* xb = x + (size_t)b * CC * NPIX;

    float acc[2][8][4] = {};
    float4 pxlo, pxhi;

    auto cpA_tile = [&](int k0, int buf) {
        uint32_t A = sb + (buf * VG_BUF_W) * 4;
        const int kw0 = k0 >> 1;
        #pragma unroll
        for (int l = 0; l < 4; l++) {
            int idx = l * 512 + tid;
            int m = idx >> 2, q = idx & 3;
            cp_async16(A + (m * RW + q * 4) * 4,
                       wvbf + (size_t)m * (CC / 2) + kw0 + q * 4);
        }
        CP_COMMIT();
    };
    auto ldgB = [&](int k0) {
        if (tid < 256) {
            const float* p0 = xb + (size_t)(k0 + 2 * bkp) * NPIX + n0 + bg * 4;
            pxlo = *reinterpret_cast<const float4*>(p0);
            pxhi = *reinterpret_cast<const float4*>(p0 + NPIX);
        }
    };
    auto stsB = [&](int buf) {
        uint32_t* B = sm + buf * VG_BUF_W + VG_A_W;
        if (tid < 256) {
            B[(bg * 4 + 0) * RW + bkp] = fpack_bf2(pxlo.x, pxhi.x);
            B[(bg * 4 + 1) * RW + bkp] = fpack_bf2(pxlo.y, pxhi.y);
            B[(bg * 4 + 2) * RW + bkp] = fpack_bf2(pxlo.z, pxhi.z);
            B[(bg * 4 + 3) * RW + bkp] = fpack_bf2(pxlo.w, pxhi.w);
        }
    };

    cpA_tile(0, 0);
    ldgB(0); stsB(0);
    cpA_tile(32, 1);
    ldgB(32); stsB(1);

    for (int i = 0; i < 16; i++) {
        if (i < 14) ldgB((i + 2) * 32);
        if (i < 15) CP_WAIT1(); else CP_WAIT0();
        __syncthreads();
        if (i < 14) { stsB((i + 2) % 3); cpA_tile((i + 2) * 32, (i + 2) % 3); }

        const uint32_t* A = sm + (i % 3) * VG_BUF_W;
        const uint32_t* B = A + VG_A_W;
        #pragma unroll
        for (int s = 0; s < 2; s++) {
            uint32_t a[2][4], bf[8][2];
            #pragma unroll
            for (int ii = 0; ii < 2; ii++) {
                a[ii][0] = A[(wm + ii * 16 + grp    ) * RW + s * 8 + tig];
                a[ii][1] = A[(wm + ii * 16 + grp + 8) * RW + s * 8 + tig];
                a[ii][2] = A[(wm + ii * 16 + grp    ) * RW + s * 8 + tig + 4];
                a[ii][3] = A[(wm + ii * 16 + grp + 8) * RW + s * 8 + tig + 4];
            }
            #pragma unroll
            for (int j = 0; j < 8; j++) {
                bf[j][0] = B[(j * 8 + grp) * RW + s * 8 + tig];
                bf[j][1] = B[(j * 8 + grp) * RW + s * 8 + tig + 4];
            }
            #pragma unroll
            for (int ii = 0; ii < 2; ii++)
                #pragma unroll
                for (int j = 0; j < 8; j++)
                    mma_bf16(acc[ii][j], a[ii], bf[j]);
        }
    }

    #pragma unroll
    for (int i = 0; i < 2; i++) {
        #pragma unroll
        for (int r = 0; r < 2; r++) {
            int m = wm + i * 16 + grp + r * 8;
            float bias = bv[m];
            uint32_t* row = g_vbf + ((size_t)b * CC + m) * SSW + (n0 >> 1) + tig;
            #pragma unroll
            for (int j = 0; j < 8; j++)
                row[j * 4] = fpack_bf2(acc[i][j][r * 2 + 0] + bias,
                                       acc[i][j][r * 2 + 1] + bias);
        }
    }
}

// ---------------- K2a: fp32 plane transpose (q AND k in one launch) -------------
__global__ void transpose_qk(const float* __restrict__ q, float* __restrict__ qT,
                             const float* __restrict__ k, float* __restrict__ kT) {
    __shared__ float t[32][33];
    const int npl = BB * C8;
    const int z = blockIdx.z;
    const float* src = (z < npl) ? q : k;
    float* dst       = (z < npl) ? qT : kT;
    const size_t base = (size_t)(z < npl ? z : z - npl) * SS;
    const int x0 = blockIdx.x * 32, y0 = blockIdx.y * 32;
    const int tx = threadIdx.x, ty = threadIdx.y;
    #pragma unroll
    for (int i = 0; i < 32; i += 8)
        t[ty + i][tx] = src[base + (size_t)(y0 + ty + i) * S + x0 + tx];
    __syncthreads();
    #pragma unroll
    for (int i = 0; i < 32; i += 8)
        dst[base + (size_t)(x0 + ty + i) * S + y0 + tx] = t[tx][ty + i];
}

// ---------------- K2b: bf16 plane transpose (v) ---------------------------------
__global__ void transpose_wh_bf16(uint32_t* __restrict__ dst, const uint32_t* __restrict__ src) {
    __shared__ unsigned short t[64][66];
    const size_t base = (size_t)blockIdx.z * SSW;
    const int w0 = blockIdx.x * 64, h0 = blockIdx.y * 64;
    const int tx = threadIdx.x, ty = threadIdx.y;
    #pragma unroll
    for (int i = 0; i < 64; i += 8) {
        int w = w0 + ty + i;
        uint32_t word = src[base + (size_t)w * 64 + (h0 >> 1) + tx];
        t[tx * 2 + 0][ty + i] = (unsigned short)(word & 0xffff);
        t[tx * 2 + 1][ty + i] = (unsigned short)(word >> 16);
    }
    __syncthreads();
    #pragma unroll
    for (int i = 0; i < 64; i += 8) {
        int h = h0 + ty + i;
        uint32_t word = *reinterpret_cast<const uint32_t*>(&t[ty + i][tx * 2]);
        dst[base + (size_t)h * 64 + (w0 >> 1) + tx] = word;
    }
}

// ---------------- K3: logits + unnormalized exp (bf16 out) + (m,s) stats -------
__global__ void __launch_bounds__(256, 2)
attn_logits_mma(const float* __restrict__ qsrc, const float* __restrict__ ksrc,
                uint32_t* __restrict__ attw, float2* __restrict__ stat, int is_col) {
    extern __shared__ uint32_t sm[];
    uint32_t* Qs = sm;
    uint32_t* Ks = sm + LG_Q_W;
    __shared__ float redm[128][2];
    __shared__ float reds[128][2];

    const int p = blockIdx.x;
    const int b = blockIdx.y;
    const int tid  = threadIdx.x;
    const int lane = tid & 31, wid = tid >> 5;
    const int grp  = lane >> 2, tig = lane & 3;
    const int wm   = (wid >> 1) * 32;
    const int wc   = wid & 1;
    const int wn   = wc * 64;

    const size_t qbase = (size_t)b * C8 * SS + (size_t)p * S;

    #pragma unroll
    for (int l = 0; l < 8; l++) {
        int idx = l * 256 + tid;
        int cc  = idx >> 5;
        int nq  = idx & 31;
        size_t g = qbase + (size_t)cc * SS + nq * 4;
        *reinterpret_cast<uint4*>(Qs + cc * PB + nq * 4) =
            tf32x4(*reinterpret_cast<const float4*>(qsrc + g));
        *reinterpret_cast<uint4*>(Ks + cc * PB + nq * 4) =
            tf32x4(*reinterpret_cast<const float4*>(ksrc + g));
    }
    __syncthreads();

    float acc[2][8][4] = {};
    #pragma unroll
    for (int kk = 0; kk < 8; kk++) {
        const int kr = kk * 8 + tig;
        uint32_t a[2][4], bf[8][2];
        #pragma unroll
        for (int i = 0; i < 2; i++) {
            a[i][0] = Qs[kr * PB       + wm + i * 16 + grp];
            a[i][1] = Qs[kr * PB       + wm + i * 16 + grp + 8];
            a[i][2] = Qs[(kr + 4) * PB + wm + i * 16 + grp];
            a[i][3] = Qs[(kr + 4) * PB + wm + i * 16 + grp + 8];
        }
        #pragma unroll
        for (int j = 0; j < 8; j++) {
            bf[j][0] = Ks[kr * PB       + wn + j * 8 + grp];
            bf[j][1] = Ks[(kr + 4) * PB + wn + j * 8 + grp];
        }
        #pragma unroll
        for (int i = 0; i < 2; i++)
            #pragma unroll
            for (int j = 0; j < 8; j++)
                mma_tf32(acc[i][j], a[i], bf[j]);
    }

    if (is_col) {
        #pragma unroll
        for (int i = 0; i < 2; i++)
            #pragma unroll
            for (int r = 0; r < 2; r++) {
                int rr = wm + i * 16 + grp + r * 8;
                #pragma unroll
                for (int j = 0; j < 8; j++) {
                    int u = wn + j * 8 + tig * 2;
                    if (rr == u)     acc[i][j][r * 2 + 0] = NEG_INF_F;
                    if (rr == u + 1) acc[i][j][r * 2 + 1] = NEG_INF_F;
                }
            }
    }

    float mloc[2][2];
    #pragma unroll
    for (int i = 0; i < 2; i++)
        #pragma unroll
        for (int r = 0; r < 2; r++) {
            float ml = -3.4e38f;
            #pragma unroll
            for (int j = 0; j < 8; j++) {
                ml = fmaxf(ml, acc[i][j][r * 2 + 0]);
                ml = fmaxf(ml, acc[i][j][r * 2 + 1]);
            }
            ml = fmaxf(ml, __shfl_xor_sync(0xffffffff, ml, 1));
            ml = fmaxf(ml, __shfl_xor_sync(0xffffffff, ml, 2));
            mloc[i][r] = ml;
        }
    if (tig == 0) {
        #pragma unroll
        for (int i = 0; i < 2; i++)
            #pragma unroll
            for (int r = 0; r < 2; r++)
                redm[wm + i * 16 + grp + r * 8][wc] = mloc[i][r];
    }
    __syncthreads();

    float mrow[2][2], sloc[2][2];
    #pragma unroll
    for (int i = 0; i < 2; i++)
        #pragma unroll
        for (int r = 0; r < 2; r++) {
            int rr = wm + i * 16 + grp + r * 8;
            float m = fmaxf(redm[rr][0], redm[rr][1]);
            mrow[i][r] = m;
            float sl = 0.f;
            #pragma unroll
            for (int j = 0; j < 8; j++) {
                float e0 = __expf(acc[i][j][r * 2 + 0] - m);
                float e1 = __expf(acc[i][j][r * 2 + 1] - m);
                acc[i][j][r * 2 + 0] = e0;
                acc[i][j][r * 2 + 1] = e1;
                sl += e0 + e1;
            }
            sl += __shfl_xor_sync(0xffffffff, sl, 1);
            sl += __shfl_xor_sync(0xffffffff, sl, 2);
            sloc[i][r] = sl;
        }
    if (tig == 0) {
        #pragma unroll
        for (int i = 0; i < 2; i++)
            #pragma unroll
            for (int r = 0; r < 2; r++)
                reds[wm + i * 16 + grp + r * 8][wc] = sloc[i][r];
    }
    __syncthreads();

    if (tig == 0 && wc == 0) {
        #pragma unroll
        for (int i = 0; i < 2; i++)
            #pragma unroll
            for (int r = 0; r < 2; r++) {
                int rr = wm + i * 16 + grp + r * 8;
                stat[(size_t)b * SS + (size_t)p * S + rr] =
                    make_float2(mrow[i][r], reds[rr][0] + reds[rr][1]);
            }
    }

    const size_t obase_w  = ((size_t)b * SS * 256 +
                            (is_col ? (size_t)p * 256 : (size_t)p * S * 256 + 128)) >> 1;
    const size_t rstride_w = (is_col ? (size_t)S * 256 : 256) >> 1;
    #pragma unroll
    for (int i = 0; i < 2; i++) {
        #pragma unroll
        for (int r = 0; r < 2; r++) {
            int rr = wm + i * 16 + grp + r * 8;
            uint32_t* row = attw + obase_w + (size_t)rr * rstride_w + ((wn >> 1) + tig);
            #pragma unroll
            for (int j = 0; j < 8; j++)
                row[j * 4] = fpack_bf2(acc[i][j][r * 2 + 0], acc[i][j][r * 2 + 1]);
        }
    }
}

// ---------------- K4: combine halves -> per-pixel normalization scales ---------
__global__ void softmax_combine(const float2* __restrict__ sc, const float2* __restrict__ sr,
                                float* __restrict__ scol, float* __restrict__ srow) {
    const int b = blockIdx.y;
    const int t = blockIdx.x * 256 + threadIdx.x;
    const int w = t & (S - 1), h = t >> 7;
    float2 c = sc[(size_t)b * SS + t];
    float2 r = sr[(size_t)b * SS + w * S + h];
    float m  = fmaxf(c.x, r.x);
    float ec = __expf(c.x - m), er = __expf(r.x - m);
    float inv = 1.f / (c.y * ec + r.y * er);
    scol[(size_t)b * SS + t]         = ec * inv;
    srow[(size_t)b * SS + w * S + h] = er * inv;
}

// ---------------- K5: attention @ V, bf16, M=256, 3-stage; bf16 output ---------
__global__ void __launch_bounds__(512, 1)
attn_av_mma(const uint32_t* __restrict__ vsrc, const uint32_t* __restrict__ attw,
            uint32_t* __restrict__ dstw, const float* __restrict__ gammap,
            const float* __restrict__ scale, int is_col) {
    extern __shared__ uint32_t sm[];
    const uint32_t sb = (uint32_t)__cvta_generic_to_shared(sm);

    const int ct = blockIdx.x;
    const int p  = blockIdx.y;
    const int b  = blockIdx.z;
    const int tid  = threadIdx.x;
    const int lane = tid & 31, wid = tid >> 5;
    const int grp  = lane >> 2, tig = lane & 3;
    const int wm   = (wid >> 1) * 32;
    const int wn   = (wid & 1) * 64;

    const size_t vbase_f = (size_t)(b * CC + ct * 256) * SS + (size_t)p * S;
    const size_t vbase_w = vbase_f >> 1;
    const size_t abase_w = ((size_t)b * SS * 256 +
                           (is_col ? (size_t)p * 256 : (size_t)p * S * 256 + 128)) >> 1;
    const size_t aq_w    = (is_col ? (size_t)S * 256 : 256) >> 1;

    const float gm = gammap[0];

    float acc[2][8][4] = {};

    auto cp_tile = [&](int u0, int buf) {
        uint32_t V = sb + (buf * BF_BUF_W) * 4;
        uint32_t T = V + BF_A_W * 4;
        #pragma unroll
        for (int l = 0; l < 2; l++) {
            int idx = l * 512 + tid;
            int cp = idx >> 2, u4 = idx & 3;
            cp_async16(V + (cp * RW + u4 * 4) * 4,
                       vsrc + vbase_w + (size_t)cp * SSW + (u0 >> 1) + u4 * 4);
        }
        {
            int qp = tid >> 2, u4 = tid & 3;
            cp_async16(T + (qp * RW + u4 * 4) * 4,
                       attw + abase_w + (size_t)qp * aq_w + (u0 >> 1) + u4 * 4);
        }
        CP_COMMIT();
    };

    cp_tile(0, 0);
    cp_tile(32, 1);

    for (int i = 0; i < 4; i++) {
        if (i < 3) CP_WAIT1(); else CP_WAIT0();
        __syncthreads();
        if (i < 2) cp_tile((i + 2) * 32, (i + 2) % 3);

        const uint32_t* V = sm + (i % 3) * BF_BUF_W;
        const uint32_t* T = V + BF_A_W;
        #pragma unroll
        for (int s = 0; s < 2; s++) {
            uint32_t a[2][4], bf[8][2];
            #pragma unroll
            for (int ii = 0; ii < 2; ii++) {
                a[ii][0] = V[(wm + ii * 16 + grp    ) * RW + s * 8 + tig];
                a[ii][1] = V[(wm + ii * 16 + grp + 8) * RW + s * 8 + tig];
                a[ii][2] = V[(wm + ii * 16 + grp    ) * RW + s * 8 + tig + 4];
                a[ii][3] = V[(wm + ii * 16 + grp + 8) * RW + s * 8 + tig + 4];
            }
            #pragma unroll
            for (int j = 0; j < 8; j++) {
                bf[j][0] = T[(wn + j * 8 + grp) * RW + s * 8 + tig];
                bf[j][1] = T[(wn + j * 8 + grp) * RW + s * 8 + tig + 4];
            }
            #pragma unroll
            for (int ii = 0; ii < 2; ii++)
                #pragma unroll
                for (int j = 0; j < 8; j++)
                    mma_bf16(acc[ii][j], a[ii], bf[j]);
        }
    }

    const float* scl = scale + (size_t)b * SS + (size_t)p * S;
    float2 scv[8];
    #pragma unroll
    for (int j = 0; j < 8; j++)
        scv[j] = *reinterpret_cast<const float2*>(scl + wn + j * 8 + tig * 2);

    #pragma unroll
    for (int i = 0; i < 2; i++) {
        #pragma unroll
        for (int r = 0; r < 2; r++) {
            int cl = wm + i * 16 + grp + r * 8;
            size_t off = vbase_f + (size_t)cl * SS + wn + tig * 2;
            uint32_t* roww = dstw + (off >> 1);
            #pragma unroll
            for (int j = 0; j < 8; j++)
                roww[j * 4] = fpack_bf2(gm * scv[j].x * acc[i][j][r * 2 + 0],
                                        gm * scv[j].y * acc[i][j][r * 2 + 1]);
        }
    }
}

// ---------------- K6: out = orow + ocolT^T + x ----------------------------------
__global__ void final_combine(const uint32_t* __restrict__ orow,
                              const uint32_t* __restrict__ ocolT,
                              const float* __restrict__ x, float* __restrict__ out) {
    __shared__ unsigned short t[64][66];
    const size_t base_w = (size_t)blockIdx.z * SSW;
    const size_t base_f = (size_t)blockIdx.z * SS;
    const int w0 = blockIdx.x * 64, h0 = blockIdx.y * 64;
    const int tx = threadIdx.x, ty = threadIdx.y;

    // load ocolT plane [h][w pairs] -> t[w_local][h_local]
    #pragma unroll
    for (int i = 0; i < 64; i += 8) {
        int h = h0 + ty + i;
        uint32_t word = ocolT[base_w + (size_t)h * 64 + (w0 >> 1) + tx];
        t[tx * 2 + 0][ty + i] = (unsigned short)(word & 0xffff);
        t[tx * 2 + 1][ty + i] = (unsigned short)(word >> 16);
    }
    __syncthreads();
    #pragma unroll
    for (int i = 0; i < 64; i += 8) {
        int w = w0 + ty + i;
        size_t off_w = base_w + (size_t)w * 64 + (h0 >> 1) + tx;
        size_t off_f = base_f + (size_t)w * S + h0 + tx * 2;

        uint32_t cw = *reinterpret_cast<const uint32_t*>(&t[ty + i][tx * 2]);
        __nv_bfloat162 cb = *reinterpret_cast<__nv_bfloat162*>(&cw);
        uint32_t rw = orow[off_w];
        __nv_bfloat162 rb = *reinterpret_cast<__nv_bfloat162*>(&rw);
        float2 xr = *reinterpret_cast<const float2*>(x + off_f);
        float2 o;
        o.x = __bfloat162float(rb.x) + __bfloat162float(cb.x) + xr.x;
        o.y = __bfloat162float(rb.y) + __bfloat162float(cb.y) + xr.y;
        *reinterpret_cast<float2*>(out + off_f) = o;
    }
}

// ---------------- launch ------------------------------------------------------
extern "C" void kernel_launch(void* const* d_in, const int* in_sizes, int n_in,
                              void* d_out, int out_size) {
    const float* x     = (const float*)d_in[0];
    const float* Wq    = (const float*)d_in[1];
    const float* bq    = (const float*)d_in[2];
    const float* Wk    = (const float*)d_in[3];
    const float* bk    = (const float*)d_in[4];
    const float* Wv    = (const float*)d_in[5];
    const float* bv    = (const float*)d_in[6];
    const float* gamma = (const float*)d_in[7];
    float* out = (float*)d_out;

    float *q, *k, *qT, *kT, *scol, *srow;
    uint32_t *wvbf, *vbf, *vTbf, *att, *ocolT, *orow;
    float2 *stc, *str;
    cudaGetSymbolAddress((void**)&q,     g_q);
    cudaGetSymbolAddress((void**)&k,     g_k);
    cudaGetSymbolAddress((void**)&qT,    g_qT);
    cudaGetSymbolAddress((void**)&kT,    g_kT);
    cudaGetSymbolAddress((void**)&wvbf,  g_wvbf);
    cudaGetSymbolAddress((void**)&vbf,   g_vbf);
    cudaGetSymbolAddress((void**)&vTbf,  g_vTbf);
    cudaGetSymbolAddress((void**)&att,   g_att);
    cudaGetSymbolAddress((void**)&ocolT, g_ocolTbf);
    cudaGetSymbolAddress((void**)&orow,  g_orowbf);
    cudaGetSymbolAddress((void**)&stc,   g_stat_col);
    cudaGetSymbolAddress((void**)&str,   g_stat_row);
    cudaGetSymbolAddress((void**)&scol,  g_scale_col);
    cudaGetSymbolAddress((void**)&srow,  g_scale_row);

    static cudaStream_t s1 = nullptr;
    static cudaEvent_t evFork = nullptr, evV = nullptr, evT = nullptr,
                       evSoft = nullptr, evCol = nullptr;
    static bool init_done = false;
    if (!init_done) {
        cudaStreamCreateWithFlags(&s1, cudaStreamNonBlocking);
        cudaEventCreateWithFlags(&evFork, cudaEventDisableTiming);
        cudaEventCreateWithFlags(&evV,    cudaEventDisableTiming);
        cudaEventCreateWithFlags(&evT,    cudaEventDisableTiming);
        cudaEventCreateWithFlags(&evSoft, cudaEventDisableTiming);
        cudaEventCreateWithFlags(&evCol,  cudaEventDisableTiming);
        cudaFuncSetAttribute(qk_gemm_mma,     cudaFuncAttributeMaxDynamicSharedMemorySize, QK_SMEM);
        cudaFuncSetAttribute(v_gemm_bf16,     cudaFuncAttributeMaxDynamicSharedMemorySize, VG_SMEM);
        cudaFuncSetAttribute(attn_logits_mma, cudaFuncAttributeMaxDynamicSharedMemorySize, LOGITS_SMEM);
        cudaFuncSetAttribute(attn_av_mma,     cudaFuncAttributeMaxDynamicSharedMemorySize, BF_SMEM);
        init_done = true;
    }

    // fork: v chain on s1 (pack_wv -> v_gemm -> vT transpose)
    cudaEventRecord(evFork, 0);
    cudaStreamWaitEvent(s1, evFork, 0);
    pack_wv<<<512, 256, 0, s1>>>(Wv, wvbf);
    v_gemm_bf16<<<dim3(NPIX / 64, BB), 512, VG_SMEM, s1>>>(x, wvbf, bv);
    cudaEventRecord(evV, s1);
    transpose_wh_bf16<<<dim3(2, 2, BB * CC), dim3(32, 8), 0, s1>>>(vTbf, vbf);
    cudaEventRecord(evT, s1);

    // qk chain on stream 0
    qk_gemm_mma<<<dim3(NPIX / 128, BB), 256, QK_SMEM>>>(x, Wq, bq, Wk, bk);
    transpose_qk<<<dim3(4, 4, 2 * BB * C8), dim3(32, 8)>>>(q, qT, k, kT);
    attn_logits_mma<<<dim3(S, BB), 256, LOGITS_SMEM>>>(qT, kT, att, stc, 1);
    attn_logits_mma<<<dim3(S, BB), 256, LOGITS_SMEM>>>(q,  k,  att, str, 0);
    softmax_combine<<<dim3(SS / 256, BB), 256>>>(stc, str, scol, srow);
    cudaEventRecord(evSoft, 0);

    // av-row on stream 0 (needs vbf); av-col on s1 (needs vTbf + att/scol)
    cudaStreamWaitEvent(0, evV, 0);
    attn_av_mma<<<dim3(2, S, BB), 512, BF_SMEM>>>(vbf, att, orow, gamma, srow, 0);
    cudaStreamWaitEvent(s1, evSoft, 0);
    attn_av_mma<<<dim3(2, S, BB), 512, BF_SMEM, s1>>>(vTbf, att, ocolT, gamma, scol, 1);
    cudaEventRecord(evCol, s1);

    // join: out = orow + ocolT^T + x
    cudaStreamWaitEvent(0, evCol, 0);
    final_combine<<<dim3(2, 2, BB * CC), dim3(32, 8)>>>(orow, ocolT, x, out);
}